// round 7
// baseline (speedup 1.0000x reference)
#include <cuda_runtime.h>
#include <math.h>
#include <stdint.h>

#define NN 30000
#define NE 480000
#define FDIM 192
#define DX 64
#define LV 256
#define LT 100

// ---------------- scratch arenas ----------------
__device__ float g_farena[44000000];
__device__ int   g_iarena[1600000];

// ---------------- graph build ----------------
__global__ void k_detect(const void* ei, int* is64) {
    const int* p = (const int*)ei;
    int zeros = 0;
    for (int i = 1; i < 256; i += 2) if (p[i] == 0) zeros++;
    *is64 = (zeros >= 120) ? 1 : 0;
}

__global__ void k_zero_i(int* a, int n) {
    int i = blockIdx.x * blockDim.x + threadIdx.x;
    if (i < n) a[i] = 0;
}

__global__ void k_convert_hist(const void* ei, int* src, int* dst,
                               int* cnt, int* degs, const int* is64) {
    int e = blockIdx.x * blockDim.x + threadIdx.x;
    if (e >= NE) return;
    int s, d;
    if (*is64) {
        const long long* p = (const long long*)ei;
        s = (int)p[e];
        d = (int)p[NE + e];
    } else {
        const int* p = (const int*)ei;
        s = p[e];
        d = p[NE + e];
    }
    src[e] = s;
    dst[e] = d;
    atomicAdd(&cnt[d], 1);
    atomicAdd(&degs[s], 1);
}

__global__ void __launch_bounds__(1024)
k_scan(const int* __restrict__ cnt, int* __restrict__ off, int* __restrict__ cur,
       const int* __restrict__ degs, float* __restrict__ dinv) {
    const int CH = 30;
    int t = threadIdx.x;
    int base = t * CH;
    int s = 0;
#pragma unroll 5
    for (int i = 0; i < CH; i++) {
        int idx = base + i;
        if (idx < NN) s += cnt[idx];
    }
    int lane = t & 31, wid = t >> 5;
    int v = s;
#pragma unroll
    for (int o = 1; o < 32; o <<= 1) {
        int u = __shfl_up_sync(~0u, v, o);
        if (lane >= o) v += u;
    }
    __shared__ int wt[32];
    if (lane == 31) wt[wid] = v;
    __syncthreads();
    if (wid == 0) {
        int w = wt[lane];
#pragma unroll
        for (int o = 1; o < 32; o <<= 1) {
            int u = __shfl_up_sync(~0u, w, o);
            if (lane >= o) w += u;
        }
        wt[lane] = w;
    }
    __syncthreads();
    int pre = v - s + (wid ? wt[wid - 1] : 0);
    int run = pre;
#pragma unroll 5
    for (int i = 0; i < CH; i++) {
        int idx = base + i;
        if (idx < NN) {
            off[idx] = run;
            cur[idx] = run;
            int dg = degs[idx];
            dinv[idx] = (dg > 0) ? rsqrtf((float)dg) : 0.f;
            run += cnt[idx];
        }
    }
    if (t == 1023) off[NN] = run;
}

// scatter src VALUES per dst segment (atomic order irrelevant: multiset sorted after)
__global__ void k_fill(const int* src, const int* dst, int* cur, int* esrc) {
    int e = blockIdx.x * blockDim.x + threadIdx.x;
    if (e >= NE) return;
    int p = atomicAdd(&cur[dst[e]], 1);
    esrc[p] = src[e];
}

__global__ void k_sortseg(const int* __restrict__ off, int* __restrict__ esrc) {
    int n = blockIdx.x * blockDim.x + threadIdx.x;
    if (n >= NN) return;
    int b = off[n], e = off[n + 1];
    for (int i = b + 1; i < e; i++) {
        int v = esrc[i];
        int j = i - 1;
        while (j >= b && esrc[j] > v) { esrc[j + 1] = esrc[j]; j--; }
        esrc[j + 1] = v;
    }
}

// ---------------- GEMM params ----------------
struct GP {
    const float* A;
    const float* B;
    float* C;
    const float* tl;
    const float* lb;
    const float* gb;
    int lda, ldb, ldc, K, M;
};
struct GP2 { GP g[2]; };

// ========== big GEMM: BM=128, BN=128, BK=16, 256 thr, 8x8/thread ==========
__global__ void __launch_bounds__(256, 2)
k_gemmBig(GP2 p) {
    GP g = p.g[blockIdx.z];
    int bcol = blockIdx.x * 128;
    if (bcol >= g.M) return;
    __shared__ float sA[2][16][128];
    __shared__ float sB[2][16][128];
    int tid = threadIdx.x;
    int tx = tid & 15, ty = tid >> 4;
    int brow = blockIdx.y * 128;
    const int K = g.K, M = g.M;

    // A: 128 rows x 16 k; thread -> row tid>>1, k-quad (tid&1)*8 (2 float4)
    const int ar = tid >> 1, ak = (tid & 1) * 8;
    // B: 16 k x 128 cols; thread -> k-row tid>>4, col (tid&15)*8 (2 float4)
    const int bkr = tid >> 4, bcq = (tid & 15) * 8;

    float4 pA0, pA1, pB0, pB1;

#define LOAD_TILE(k0)                                                          \
    do {                                                                       \
        pA0 = make_float4(0.f, 0.f, 0.f, 0.f);                                 \
        pA1 = make_float4(0.f, 0.f, 0.f, 0.f);                                 \
        pB0 = make_float4(0.f, 0.f, 0.f, 0.f);                                 \
        pB1 = make_float4(0.f, 0.f, 0.f, 0.f);                                 \
        if (brow + ar < NN) {                                                  \
            const float* ap = g.A + (size_t)(brow + ar) * g.lda + (k0) + ak;   \
            if ((k0) + ak + 7 < K) {                                           \
                pA0 = *(const float4*)ap;                                      \
                pA1 = *(const float4*)(ap + 4);                                \
            } else {                                                           \
                float t[8];                                                    \
                for (int q = 0; q < 8; q++)                                    \
                    t[q] = ((k0) + ak + q < K) ? ap[q] : 0.f;                  \
                pA0 = make_float4(t[0], t[1], t[2], t[3]);                     \
                pA1 = make_float4(t[4], t[5], t[6], t[7]);                     \
            }                                                                  \
        }                                                                      \
        if ((k0) + bkr < K) {                                                  \
            const float* bp = g.B + (size_t)((k0) + bkr) * g.ldb + bcol + bcq; \
            if (bcol + bcq + 7 < M) {                                          \
                pB0 = *(const float4*)bp;                                      \
                pB1 = *(const float4*)(bp + 4);                                \
            } else {                                                           \
                float t[8];                                                    \
                for (int q = 0; q < 8; q++)                                    \
                    t[q] = (bcol + bcq + q < M) ? bp[q] : 0.f;                 \
                pB0 = make_float4(t[0], t[1], t[2], t[3]);                     \
                pB1 = make_float4(t[4], t[5], t[6], t[7]);                     \
            }                                                                  \
        }                                                                      \
    } while (0)

#define STORE_TILE(buf)                                                        \
    do {                                                                       \
        sA[buf][ak + 0][ar] = pA0.x;                                           \
        sA[buf][ak + 1][ar] = pA0.y;                                           \
        sA[buf][ak + 2][ar] = pA0.z;                                           \
        sA[buf][ak + 3][ar] = pA0.w;                                           \
        sA[buf][ak + 4][ar] = pA1.x;                                           \
        sA[buf][ak + 5][ar] = pA1.y;                                           \
        sA[buf][ak + 6][ar] = pA1.z;                                           \
        sA[buf][ak + 7][ar] = pA1.w;                                           \
        *(float4*)&sB[buf][bkr][bcq]     = pB0;                                \
        *(float4*)&sB[buf][bkr][bcq + 4] = pB1;                                \
    } while (0)

    float acc[8][8] = {};
    LOAD_TILE(0);
    STORE_TILE(0);
    __syncthreads();
    int buf = 0;

    for (int k0 = 0; k0 < K; k0 += 16) {
        int nk = k0 + 16;
        if (nk < K) LOAD_TILE(nk);
#pragma unroll
        for (int kk = 0; kk < 16; kk++) {
            float4 a0 = *(const float4*)&sA[buf][kk][ty * 8];
            float4 a1 = *(const float4*)&sA[buf][kk][ty * 8 + 4];
            float4 b0 = *(const float4*)&sB[buf][kk][tx * 8];
            float4 b1 = *(const float4*)&sB[buf][kk][tx * 8 + 4];
            float a[8] = {a0.x, a0.y, a0.z, a0.w, a1.x, a1.y, a1.z, a1.w};
            float b[8] = {b0.x, b0.y, b0.z, b0.w, b1.x, b1.y, b1.z, b1.w};
#pragma unroll
            for (int i = 0; i < 8; i++)
#pragma unroll
                for (int j = 0; j < 8; j++)
                    acc[i][j] += a[i] * b[j];
        }
        if (nk < K) {
            STORE_TILE(buf ^ 1);
            __syncthreads();
            buf ^= 1;
        }
    }
#undef LOAD_TILE
#undef STORE_TILE

#pragma unroll
    for (int i = 0; i < 8; i++) {
        int r = brow + ty * 8 + i;
        if (r >= NN) continue;
        float* crow = g.C + (size_t)r * g.ldc + bcol + tx * 8;
#pragma unroll
        for (int j = 0; j < 8; j++) {
            int c = bcol + tx * 8 + j;
            if (c < M) crow[j] = acc[i][j];
        }
    }
}

// ========== small GEMM: BM=128, BN=64, BK=16, 8x4/thread ==========
// EPI==1: C := lrelu( acc + gb[c] + lrelu(tl+lb) + id )  (M<=64, ldc=64)
template <int EPI>
__global__ void __launch_bounds__(256)
k_gemm(GP2 p, const float* __restrict__ id) {
    GP g = p.g[blockIdx.z];
    int bcol = blockIdx.x * 64;
    if (bcol >= g.M) return;
    __shared__ float sA[2][16][128];
    __shared__ float sB[2][16][64];
    int tid = threadIdx.x;
    int tx = tid & 15, ty = tid >> 4;
    int brow = blockIdx.y * 128;
    const int K = g.K, M = g.M;

    const int ar0 = tid >> 2, akq = (tid & 3) * 4;
    const int ar1 = (tid + 256) >> 2;
    const int bkr = tid >> 4, bcq = (tid & 15) * 4;

    float4 pA0, pA1, pB;

#define LOAD_TILE(k0)                                                          \
    do {                                                                       \
        pA0 = make_float4(0.f, 0.f, 0.f, 0.f);                                 \
        pA1 = make_float4(0.f, 0.f, 0.f, 0.f);                                 \
        pB  = make_float4(0.f, 0.f, 0.f, 0.f);                                 \
        if (brow + ar0 < NN) {                                                 \
            const float* ap = g.A + (size_t)(brow + ar0) * g.lda + (k0) + akq; \
            if ((k0) + akq + 3 < K) pA0 = *(const float4*)ap;                  \
            else {                                                             \
                if ((k0) + akq + 0 < K) pA0.x = ap[0];                         \
                if ((k0) + akq + 1 < K) pA0.y = ap[1];                         \
                if ((k0) + akq + 2 < K) pA0.z = ap[2];                         \
                if ((k0) + akq + 3 < K) pA0.w = ap[3];                         \
            }                                                                  \
        }                                                                      \
        if (brow + ar1 < NN) {                                                 \
            const float* ap = g.A + (size_t)(brow + ar1) * g.lda + (k0) + akq; \
            if ((k0) + akq + 3 < K) pA1 = *(const float4*)ap;                  \
            else {                                                             \
                if ((k0) + akq + 0 < K) pA1.x = ap[0];                         \
                if ((k0) + akq + 1 < K) pA1.y = ap[1];                         \
                if ((k0) + akq + 2 < K) pA1.z = ap[2];                         \
                if ((k0) + akq + 3 < K) pA1.w = ap[3];                         \
            }                                                                  \
        }                                                                      \
        if ((k0) + bkr < K) {                                                  \
            const float* bp = g.B + (size_t)((k0) + bkr) * g.ldb + bcol + bcq; \
            if (bcol + bcq + 3 < M) pB = *(const float4*)bp;                   \
            else {                                                             \
                if (bcol + bcq + 0 < M) pB.x = bp[0];                          \
                if (bcol + bcq + 1 < M) pB.y = bp[1];                          \
                if (bcol + bcq + 2 < M) pB.z = bp[2];                          \
                if (bcol + bcq + 3 < M) pB.w = bp[3];                          \
            }                                                                  \
        }                                                                      \
    } while (0)

#define STORE_TILE(buf)                                                        \
    do {                                                                       \
        sA[buf][akq + 0][ar0] = pA0.x;                                         \
        sA[buf][akq + 1][ar0] = pA0.y;                                         \
        sA[buf][akq + 2][ar0] = pA0.z;                                         \
        sA[buf][akq + 3][ar0] = pA0.w;                                         \
        sA[buf][akq + 0][ar1] = pA1.x;                                         \
        sA[buf][akq + 1][ar1] = pA1.y;                                         \
        sA[buf][akq + 2][ar1] = pA1.z;                                         \
        sA[buf][akq + 3][ar1] = pA1.w;                                         \
        *(float4*)&sB[buf][bkr][bcq] = pB;                                     \
    } while (0)

    float acc[8][4] = {};
    LOAD_TILE(0);
    STORE_TILE(0);
    __syncthreads();
    int buf = 0;

    for (int k0 = 0; k0 < K; k0 += 16) {
        int nk = k0 + 16;
        if (nk < K) LOAD_TILE(nk);
#pragma unroll
        for (int kk = 0; kk < 16; kk++) {
            float4 a0 = *(const float4*)&sA[buf][kk][ty * 8];
            float4 a1 = *(const float4*)&sA[buf][kk][ty * 8 + 4];
            float4 b  = *(const float4*)&sB[buf][kk][tx * 4];
            float a[8] = {a0.x, a0.y, a0.z, a0.w, a1.x, a1.y, a1.z, a1.w};
            float bb[4] = {b.x, b.y, b.z, b.w};
#pragma unroll
            for (int i = 0; i < 8; i++)
#pragma unroll
                for (int j = 0; j < 4; j++)
                    acc[i][j] += a[i] * bb[j];
        }
        if (nk < K) {
            STORE_TILE(buf ^ 1);
            __syncthreads();
            buf ^= 1;
        }
    }
#undef LOAD_TILE
#undef STORE_TILE

#pragma unroll
    for (int i = 0; i < 8; i++) {
        int r = brow + ty * 8 + i;
        if (r >= NN) continue;
#pragma unroll
        for (int j = 0; j < 4; j++) {
            int c = bcol + tx * 4 + j;
            if (c >= M) continue;
            if (EPI == 0) {
                g.C[(size_t)r * g.ldc + c] = acc[i][j];
            } else {
                size_t lin = (size_t)r * 64 + c;
                float xh = g.tl[lin] + g.lb[c];
                xh = (xh > 0.f) ? xh : 0.01f * xh;
                xh += id[lin];
                float v = acc[i][j] + g.gb[c] + xh;
                g.C[lin] = (v > 0.f) ? v : 0.01f * v;
            }
        }
    }
}

// ---------------- tanh + l2norm ----------------
__global__ void __launch_bounds__(256)
k_tanh2(float* __restrict__ xv, const float* __restrict__ bv,
        float* __restrict__ xt, const float* __restrict__ bt) {
    int w = (blockIdx.x * blockDim.x + threadIdx.x) >> 5;
    int lane = threadIdx.x & 31;
    if (w >= 2 * NN) return;
    float* row;
    const float* b;
    int dim;
    if (w < NN) { row = xv + (size_t)w * LV; b = bv; dim = LV; }
    else        { row = xt + (size_t)(w - NN) * LT; b = bt; dim = LT; }
    float v[8];
    float ss = 0.f;
#pragma unroll
    for (int j = 0; j < 8; j++) {
        v[j] = 0.f;
        int c = lane + 32 * j;
        if (c < dim) {
            float t = tanhf(row[c] + b[c]);
            v[j] = t;
            ss += t * t;
        }
    }
#pragma unroll
    for (int o = 16; o; o >>= 1) ss += __shfl_xor_sync(~0u, ss, o);
    float sc = 1.f / fmaxf(sqrtf(ss), 1e-12f);
#pragma unroll
    for (int j = 0; j < 8; j++) {
        int c = lane + 32 * j;
        if (c < dim) row[c] = v[j] * sc;
    }
}

// ---------------- vector helpers ----------------
template <int VEC>
__device__ __forceinline__ void ldrow(const float* __restrict__ p, float* v) {
    if (VEC == 8) {
        float4 a = *(const float4*)p;
        float4 b = *(const float4*)(p + 4);
        v[0] = a.x; v[1] = a.y; v[2] = a.z; v[3] = a.w;
        v[4] = b.x; v[5] = b.y; v[6] = b.z; v[7] = b.w;
    } else if (VEC == 4) {
        float4 a = *(const float4*)p;
        v[0] = a.x; v[1] = a.y; v[2] = a.z; v[3] = a.w;
    } else {
        float2 a = *(const float2*)p;
        v[0] = a.x; v[1] = a.y;
    }
}

template <int VEC>
__device__ __forceinline__ void strow(float* __restrict__ p, const float* v) {
    if (VEC == 8) {
        *(float4*)p       = make_float4(v[0], v[1], v[2], v[3]);
        *(float4*)(p + 4) = make_float4(v[4], v[5], v[6], v[7]);
    } else if (VEC == 4) {
        *(float4*)p = make_float4(v[0], v[1], v[2], v[3]);
    } else {
        *(float2*)p = make_float2(v[0], v[1]);
    }
}

// ---------------- GAT (single-pass online softmax) ----------------
template <int VEC>
__device__ __forceinline__ void gat_update(const float* v, float di,
                                           const float (&hd)[VEC], float (&acc)[VEC],
                                           float& m, float& denom) {
    float d = 0.f;
#pragma unroll
    for (int j = 0; j < VEC; j++) {
        float lr = (v[j] > 0.f) ? v[j] : 0.01f * v[j];
        d += hd[j] * lr;
    }
#pragma unroll
    for (int o = 16; o; o >>= 1) d += __shfl_xor_sync(~0u, d, o);
    float t = d * di;
    float gate = 1.f / (1.f + __expf(-t));
    float lg = d * gate;
    if (lg > m) {
        float sc = __expf(m - lg);
        denom *= sc;
#pragma unroll
        for (int j = 0; j < VEC; j++) acc[j] *= sc;
        m = lg;
    }
    float w = __expf(lg - m);
    denom += w;
#pragma unroll
    for (int j = 0; j < VEC; j++) acc[j] += w * v[j];
}

template <int VEC>
__device__ __forceinline__ void gat_node(const float* __restrict__ hc, int dim,
                                         const int* __restrict__ esrc, int b0, int b1,
                                         const float* __restrict__ dinv,
                                         const float* __restrict__ bias,
                                         float* __restrict__ out, int n, int lane) {
    int c0 = lane * VEC;
    bool valid = c0 < dim;
    float hd[VEC];
#pragma unroll
    for (int j = 0; j < VEC; j++) hd[j] = 0.f;
    if (valid) ldrow<VEC>(hc + (size_t)n * dim + c0, hd);

    float m = -1e30f, denom = 0.f;
    float acc[VEC];
#pragma unroll
    for (int j = 0; j < VEC; j++) acc[j] = 0.f;

    int p = b0;
    for (; p + 3 < b1; p += 4) {
        int s[4];
        float di[4];
        float v[4][VEC];
#pragma unroll
        for (int q = 0; q < 4; q++) s[q] = esrc[p + q];
#pragma unroll
        for (int q = 0; q < 4; q++) di[q] = dinv[s[q]];
#pragma unroll
        for (int q = 0; q < 4; q++) {
#pragma unroll
            for (int j = 0; j < VEC; j++) v[q][j] = 0.f;
            if (valid) ldrow<VEC>(hc + (size_t)s[q] * dim + c0, v[q]);
        }
#pragma unroll
        for (int q = 0; q < 4; q++)
            gat_update<VEC>(v[q], di[q], hd, acc, m, denom);
    }
    for (; p < b1; p++) {
        int s = esrc[p];
        float di = dinv[s];
        float v[VEC];
#pragma unroll
        for (int j = 0; j < VEC; j++) v[j] = 0.f;
        if (valid) ldrow<VEC>(hc + (size_t)s * dim + c0, v);
        gat_update<VEC>(v, di, hd, acc, m, denom);
    }

    float inv = 1.f / (denom + 1e-16f);
    float val[VEC];
    float ss = 0.f;
#pragma unroll
    for (int j = 0; j < VEC; j++) {
        val[j] = 0.f;
        if (valid) {
            float v = acc[j] * inv + bias[c0 + j];
            val[j] = v;
            ss += v * v;
        }
    }
#pragma unroll
    for (int o = 16; o; o >>= 1) ss += __shfl_xor_sync(~0u, ss, o);
    float sc = 1.f / fmaxf(sqrtf(ss), 1e-12f);
    if (valid) {
        float res[VEC];
#pragma unroll
        for (int j = 0; j < VEC; j++) {
            float v = val[j] * sc;
            res[j] = (v > 0.f) ? v : 0.01f * v;
        }
        strow<VEC>(out + (size_t)n * dim + c0, res);
    }
}

__global__ void __launch_bounds__(128)
k_gat1(const float* __restrict__ hcv, const float* __restrict__ hct,
       const int* __restrict__ esrc, const int* __restrict__ off,
       const float* __restrict__ dinv,
       const float* __restrict__ bv, const float* __restrict__ bt,
       float* __restrict__ ov, float* __restrict__ ot) {
    int w = (blockIdx.x * blockDim.x + threadIdx.x) >> 5;
    int lane = threadIdx.x & 31;
    if (w >= 2 * NN) return;
    if (w < NN) {
        gat_node<8>(hcv, LV, esrc, off[w], off[w + 1], dinv, bv, ov, w, lane);
    } else {
        int n = w - NN;
        gat_node<4>(hct, LT, esrc, off[n], off[n + 1], dinv, bt, ot, n, lane);
    }
}

__global__ void __launch_bounds__(128)
k_gat2(const float* __restrict__ hcv, const float* __restrict__ hct,
       const int* __restrict__ esrc, const int* __restrict__ off,
       const float* __restrict__ dinv,
       const float* __restrict__ bv, const float* __restrict__ bt,
       float* __restrict__ ov, float* __restrict__ ot) {
    int w = (blockIdx.x * blockDim.x + threadIdx.x) >> 5;
    int lane = threadIdx.x & 31;
    if (w >= 2 * NN) return;
    if (w < NN) {
        gat_node<2>(hcv, DX, esrc, off[w], off[w + 1], dinv, bv, ov, w, lane);
    } else {
        int n = w - NN;
        gat_node<2>(hct, DX, esrc, off[n], off[n + 1], dinv, bt, ot, n, lane);
    }
}

// output: [representation | v_rep | t_rep]
__global__ void __launch_bounds__(256)
k_final(const float* __restrict__ vx1, const float* __restrict__ vx2,
        const float* __restrict__ tx1, const float* __restrict__ tx2,
        float* __restrict__ out, int out_size) {
    int i = blockIdx.x * blockDim.x + threadIdx.x;
    if (i >= NN * DX) return;
    int n = i >> 6, c = i & 63;
    float a1 = vx1[i], a2 = vx2[i], b1 = tx1[i], b2 = tx2[i];
    size_t base = (size_t)n * 128;
    out[base + c]      = (a1 + b1) * 0.5f;
    out[base + 64 + c] = (a2 + b2) * 0.5f;
    if (out_size >= 2 * NN * 128) {
        out[(size_t)NN * 128 + base + c]      = a1;
        out[(size_t)NN * 128 + base + 64 + c] = a2;
    }
    if (out_size >= 3 * NN * 128) {
        out[(size_t)2 * NN * 128 + base + c]      = b1;
        out[(size_t)2 * NN * 128 + base + 64 + c] = b2;
    }
}

// ---------------- host side ----------------
extern "C" void kernel_launch(void* const* d_in, const int* in_sizes, int n_in,
                              void* d_out, int out_size) {
    static float* F = nullptr;
    static int*   I = nullptr;
    if (!F) {
        cudaGetSymbolAddress((void**)&F, g_farena);
        cudaGetSymbolAddress((void**)&I, g_iarena);
    }

    float* x_v  = F;
    float* hc_v = F + 7680000;
    float* h_v  = F + 15360000;
    float* x_t  = F + 23040000;
    float* hc_t = F + 26040000;
    float* h_t  = F + 29040000;
    float* tl_v = F + 32040000;
    float* tl_t = F + 33960000;
    float* vx1  = F + 35880000;
    float* vx2  = F + 37800000;
    float* tx1  = F + 39720000;
    float* tx2  = F + 41640000;
    float* dinv = F + 43560000;

    int* src  = I;
    int* dst  = I + NE;
    int* esrc = I + 2 * NE;
    int* cnt  = I + 3 * NE;
    int* degs = cnt + (NN + 1);
    int* off  = degs + NN;
    int* cur  = off + (NN + 1);
    int* is64 = cur + NN;

    const float* feat  = (const float*)d_in[0];
    const void*  ei    = d_in[1];
    const float* idemb = (const float*)d_in[2];
    void* const* PV = d_in + 3;
    void* const* PT = d_in + 17;

#define PW(P, i) ((const float*)P[i])

    dim3 blk(256);
    int gy = (NN + 127) / 128;
    int warp2_grid = (2 * NN * 32 + 255) / 256;
    int gat_grid = (2 * NN * 32 + 127) / 128;

    k_zero_i<<<(2 * NN + 256) / 256, 256>>>(cnt, 2 * NN + 1);
    k_detect<<<1, 1>>>(ei, is64);
    k_convert_hist<<<(NE + 255) / 256, 256>>>(ei, src, dst, cnt, degs, is64);

    // S1: mlp GEMM (big tile; v M=256 needs x=0,1; t M=100 only x=0)
    {
        GP2 p = {{
            {feat, PW(PV, 0), x_v, nullptr, nullptr, nullptr, FDIM, LV, LV, 128, LV},
            {feat + 128, PW(PT, 0), x_t, nullptr, nullptr, nullptr, FDIM, LT, LT, 64, LT}}};
        k_gemmBig<<<dim3(2, gy, 2), blk>>>(p);
    }
    // S2: tanh + l2norm
    k_tanh2<<<warp2_grid, 256>>>(x_v, PW(PV, 1), x_t, PW(PT, 1));
    // S3: c1 GEMM (big tile)
    {
        GP2 p = {{
            {x_v, PW(PV, 2), hc_v, nullptr, nullptr, nullptr, LV, LV, LV, LV, LV},
            {x_t, PW(PT, 2), hc_t, nullptr, nullptr, nullptr, LT, LT, LT, LT, LT}}};
        k_gemmBig<<<dim3(2, gy, 2), blk>>>(p);
    }

    // graph build tail
    k_scan<<<1, 1024>>>(cnt, off, cur, degs, dinv);
    k_fill<<<(NE + 255) / 256, 256>>>(src, dst, cur, esrc);
    k_sortseg<<<(NN + 255) / 256, 256>>>(off, esrc);

    // S4: GAT layer 1
    k_gat1<<<gat_grid, 128>>>(hc_v, hc_t, esrc, off, dinv, PW(PV, 3), PW(PT, 3), h_v, h_t);

    // S5: l1 GEMM
    {
        GP2 p = {{
            {x_v, PW(PV, 4), tl_v, nullptr, nullptr, nullptr, LV, DX, DX, LV, DX},
            {x_t, PW(PT, 4), tl_t, nullptr, nullptr, nullptr, LT, DX, DX, LT, DX}}};
        k_gemm<0><<<dim3(1, gy, 2), blk>>>(p, nullptr);
    }
    // S6: g1 GEMM + combine -> x1
    {
        GP2 p = {{
            {h_v, PW(PV, 6), vx1, tl_v, PW(PV, 5), PW(PV, 7), LV, DX, DX, LV, DX},
            {h_t, PW(PT, 6), tx1, tl_t, PW(PT, 5), PW(PT, 7), LT, DX, DX, LT, DX}}};
        k_gemm<1><<<dim3(1, gy, 2), blk>>>(p, idemb);
    }
    // S7: c2 GEMM
    {
        GP2 p = {{
            {vx1, PW(PV, 8), hc_v, nullptr, nullptr, nullptr, DX, DX, DX, DX, DX},
            {tx1, PW(PT, 8), hc_t, nullptr, nullptr, nullptr, DX, DX, DX, DX, DX}}};
        k_gemm<0><<<dim3(1, gy, 2), blk>>>(p, nullptr);
    }
    // S8: GAT layer 2
    k_gat2<<<gat_grid, 128>>>(hc_v, hc_t, esrc, off, dinv, PW(PV, 9), PW(PT, 9), h_v, h_t);

    // S9: l2 GEMM
    {
        GP2 p = {{
            {vx1, PW(PV, 10), tl_v, nullptr, nullptr, nullptr, DX, DX, DX, DX, DX},
            {tx1, PW(PT, 10), tl_t, nullptr, nullptr, nullptr, DX, DX, DX, DX, DX}}};
        k_gemm<0><<<dim3(1, gy, 2), blk>>>(p, nullptr);
    }
    // S10: g2 GEMM + combine -> x2
    {
        GP2 p = {{
            {h_v, PW(PV, 12), vx2, tl_v, PW(PV, 11), PW(PV, 13), DX, DX, DX, DX, DX},
            {h_t, PW(PT, 12), tx2, tl_t, PW(PT, 11), PW(PT, 13), DX, DX, DX, DX, DX}}};
        k_gemm<1><<<dim3(1, gy, 2), blk>>>(p, idemb);
    }

    k_final<<<(NN * DX + 255) / 256, 256>>>(vx1, vx2, tx1, tx2, (float*)d_out, out_size);
#undef PW
}

// round 9
// speedup vs baseline: 1.2804x; 1.2804x over previous
#include <cuda_runtime.h>
#include <math.h>
#include <stdint.h>

#define NN 30000
#define NE 480000
#define FDIM 192
#define DX 64
#define LV 256
#define LT 100

// ---------------- scratch arenas ----------------
__device__ float g_farena[44000000];
__device__ int   g_iarena[1600000];

// ---------------- graph build ----------------
__global__ void k_detect(const void* ei, int* is64) {
    const int* p = (const int*)ei;
    int zeros = 0;
    for (int i = 1; i < 256; i += 2) if (p[i] == 0) zeros++;
    *is64 = (zeros >= 120) ? 1 : 0;
}

__global__ void k_zero_i(int* a, int n) {
    int i = blockIdx.x * blockDim.x + threadIdx.x;
    if (i < n) a[i] = 0;
}

__global__ void k_convert_hist(const void* ei, int* src, int* dst,
                               int* cnt, int* degs, const int* is64) {
    int e = blockIdx.x * blockDim.x + threadIdx.x;
    if (e >= NE) return;
    int s, d;
    if (*is64) {
        const long long* p = (const long long*)ei;
        s = (int)p[e];
        d = (int)p[NE + e];
    } else {
        const int* p = (const int*)ei;
        s = p[e];
        d = p[NE + e];
    }
    src[e] = s;
    dst[e] = d;
    atomicAdd(&cnt[d], 1);
    atomicAdd(&degs[s], 1);
}

__global__ void __launch_bounds__(1024)
k_scan(const int* __restrict__ cnt, int* __restrict__ off, int* __restrict__ cur,
       const int* __restrict__ degs, float* __restrict__ dinv) {
    const int CH = 30;
    int t = threadIdx.x;
    int base = t * CH;
    int s = 0;
#pragma unroll 5
    for (int i = 0; i < CH; i++) {
        int idx = base + i;
        if (idx < NN) s += cnt[idx];
    }
    int lane = t & 31, wid = t >> 5;
    int v = s;
#pragma unroll
    for (int o = 1; o < 32; o <<= 1) {
        int u = __shfl_up_sync(~0u, v, o);
        if (lane >= o) v += u;
    }
    __shared__ int wt[32];
    if (lane == 31) wt[wid] = v;
    __syncthreads();
    if (wid == 0) {
        int w = wt[lane];
#pragma unroll
        for (int o = 1; o < 32; o <<= 1) {
            int u = __shfl_up_sync(~0u, w, o);
            if (lane >= o) w += u;
        }
        wt[lane] = w;
    }
    __syncthreads();
    int pre = v - s + (wid ? wt[wid - 1] : 0);
    int run = pre;
#pragma unroll 5
    for (int i = 0; i < CH; i++) {
        int idx = base + i;
        if (idx < NN) {
            off[idx] = run;
            cur[idx] = run;
            int dg = degs[idx];
            dinv[idx] = (dg > 0) ? rsqrtf((float)dg) : 0.f;
            run += cnt[idx];
        }
    }
    if (t == 1023) off[NN] = run;
}

__global__ void k_fill(const int* src, const int* dst, int* cur, int* esrc) {
    int e = blockIdx.x * blockDim.x + threadIdx.x;
    if (e >= NE) return;
    int p = atomicAdd(&cur[dst[e]], 1);
    esrc[p] = src[e];
}

__global__ void k_sortseg(const int* __restrict__ off, int* __restrict__ esrc) {
    int n = blockIdx.x * blockDim.x + threadIdx.x;
    if (n >= NN) return;
    int b = off[n], e = off[n + 1];
    for (int i = b + 1; i < e; i++) {
        int v = esrc[i];
        int j = i - 1;
        while (j >= b && esrc[j] > v) { esrc[j + 1] = esrc[j]; j--; }
        esrc[j + 1] = v;
    }
}

// ---------------- TF32 tensor-core GEMM ----------------
struct GP {
    const float* A;
    const float* B;
    float* C;
    const float* tl;
    const float* lb;
    const float* gb;
    int lda, ldb, ldc, K, M;
};
struct GP2 { GP g[2]; };

__device__ __forceinline__ float f2tf(float x) {
    uint32_t u;
    asm("cvt.rna.tf32.f32 %0, %1;" : "=r"(u) : "f"(x));
    return __uint_as_float(u);
}

__device__ __forceinline__ void mma_tf32(float* c,
                                         uint32_t a0, uint32_t a1, uint32_t a2, uint32_t a3,
                                         uint32_t b0, uint32_t b1) {
    asm volatile(
        "mma.sync.aligned.m16n8k8.row.col.f32.tf32.tf32.f32 "
        "{%0,%1,%2,%3}, {%4,%5,%6,%7}, {%8,%9}, {%0,%1,%2,%3};\n"
        : "+f"(c[0]), "+f"(c[1]), "+f"(c[2]), "+f"(c[3])
        : "r"(a0), "r"(a1), "r"(a2), "r"(a3), "r"(b0), "r"(b1));
}

#define SAS 136  // sA row stride (conflict-free frag loads: 136%32==8)
#define SBS 72   // sB row stride (72%32==8)

// BM=128, BN=64, BK=16, 256 threads = 8 warps (4 m x 2 n), warp tile 32x32.
// EPI==1: C := lrelu( acc + gb[c] + lrelu(tl+lb) + id )  (M<=64, ldc=64)
template <int EPI>
__global__ void __launch_bounds__(256)
k_gemm(GP2 p, const float* __restrict__ id) {
    GP g = p.g[blockIdx.z];
    const int bcol = blockIdx.x * 64;
    if (bcol >= g.M) return;
    __shared__ float sA[2][16][SAS];
    __shared__ float sB[2][16][SBS];
    const int tid = threadIdx.x;
    const int brow = blockIdx.y * 128;
    const int K = g.K, M = g.M;

    const int lane = tid & 31;
    const int wid  = tid >> 5;
    const int wm = (wid & 3) * 32;   // warp row base within tile
    const int wn = (wid >> 2) * 32;  // warp col base within tile
    const int grp = lane >> 2, thr = lane & 3;

    // global load coords
    const int ar0 = tid >> 2, akq = (tid & 3) * 4;   // A: rows ar0, ar0+64
    const int ar1 = ar0 + 64;
    const int bkr = tid >> 4, bcq = (tid & 15) * 4;  // B: k-row, col-quad

    float4 pA0, pA1, pB;

#define LOAD_TILE(k0)                                                          \
    do {                                                                       \
        pA0 = make_float4(0.f, 0.f, 0.f, 0.f);                                 \
        pA1 = make_float4(0.f, 0.f, 0.f, 0.f);                                 \
        pB  = make_float4(0.f, 0.f, 0.f, 0.f);                                 \
        if (brow + ar0 < NN) {                                                 \
            const float* ap = g.A + (size_t)(brow + ar0) * g.lda + (k0) + akq; \
            if ((k0) + akq + 3 < K) pA0 = *(const float4*)ap;                  \
            else {                                                             \
                if ((k0) + akq + 0 < K) pA0.x = ap[0];                         \
                if ((k0) + akq + 1 < K) pA0.y = ap[1];                         \
                if ((k0) + akq + 2 < K) pA0.z = ap[2];                         \
                if ((k0) + akq + 3 < K) pA0.w = ap[3];                         \
            }                                                                  \
        }                                                                      \
        if (brow + ar1 < NN) {                                                 \
            const float* ap = g.A + (size_t)(brow + ar1) * g.lda + (k0) + akq; \
            if ((k0) + akq + 3 < K) pA1 = *(const float4*)ap;                  \
            else {                                                             \
                if ((k0) + akq + 0 < K) pA1.x = ap[0];                         \
                if ((k0) + akq + 1 < K) pA1.y = ap[1];                         \
                if ((k0) + akq + 2 < K) pA1.z = ap[2];                         \
                if ((k0) + akq + 3 < K) pA1.w = ap[3];                         \
            }                                                                  \
        }                                                                      \
        if ((k0) + bkr < K) {                                                  \
            const float* bp = g.B + (size_t)((k0) + bkr) * g.ldb + bcol + bcq; \
            if (bcol + bcq + 3 < M) pB = *(const float4*)bp;                   \
            else {                                                             \
                if (bcol + bcq + 0 < M) pB.x = bp[0];                          \
                if (bcol + bcq + 1 < M) pB.y = bp[1];                          \
                if (bcol + bcq + 2 < M) pB.z = bp[2];                          \
                if (bcol + bcq + 3 < M) pB.w = bp[3];                          \
            }                                                                  \
        }                                                                      \
    } while (0)

#define STORE_TILE(buf)                                                        \
    do {                                                                       \
        sA[buf][akq + 0][ar0] = f2tf(pA0.x);                                   \
        sA[buf][akq + 1][ar0] = f2tf(pA0.y);                                   \
        sA[buf][akq + 2][ar0] = f2tf(pA0.z);                                   \
        sA[buf][akq + 3][ar0] = f2tf(pA0.w);                                   \
        sA[buf][akq + 0][ar1] = f2tf(pA1.x);                                   \
        sA[buf][akq + 1][ar1] = f2tf(pA1.y);                                   \
        sA[buf][akq + 2][ar1] = f2tf(pA1.z);                                   \
        sA[buf][akq + 3][ar1] = f2tf(pA1.w);                                   \
        sB[buf][bkr][bcq + 0] = f2tf(pB.x);                                    \
        sB[buf][bkr][bcq + 1] = f2tf(pB.y);                                    \
        sB[buf][bkr][bcq + 2] = f2tf(pB.z);                                    \
        sB[buf][bkr][bcq + 3] = f2tf(pB.w);                                    \
    } while (0)

    float acc[2][4][4] = {};
    LOAD_TILE(0);
    STORE_TILE(0);
    __syncthreads();
    int buf = 0;

    for (int k0 = 0; k0 < K; k0 += 16) {
        int nk = k0 + 16;
        if (nk < K) LOAD_TILE(nk);
#pragma unroll
        for (int ks = 0; ks < 2; ks++) {
            int kb = ks * 8;
            uint32_t af[2][4], bf[4][2];
#pragma unroll
            for (int mt = 0; mt < 2; mt++) {
                int r = wm + mt * 16 + grp;
                af[mt][0] = __float_as_uint(sA[buf][kb + thr][r]);
                af[mt][1] = __float_as_uint(sA[buf][kb + thr][r + 8]);
                af[mt][2] = __float_as_uint(sA[buf][kb + 4 + thr][r]);
                af[mt][3] = __float_as_uint(sA[buf][kb + 4 + thr][r + 8]);
            }
#pragma unroll
            for (int nt = 0; nt < 4; nt++) {
                int c = wn + nt * 8 + grp;
                bf[nt][0] = __float_as_uint(sB[buf][kb + thr][c]);
                bf[nt][1] = __float_as_uint(sB[buf][kb + 4 + thr][c]);
            }
#pragma unroll
            for (int mt = 0; mt < 2; mt++)
#pragma unroll
                for (int nt = 0; nt < 4; nt++)
                    mma_tf32(acc[mt][nt], af[mt][0], af[mt][1], af[mt][2], af[mt][3],
                             bf[nt][0], bf[nt][1]);
        }
        if (nk < K) {
            STORE_TILE(buf ^ 1);
            __syncthreads();
            buf ^= 1;
        }
    }
#undef LOAD_TILE
#undef STORE_TILE

    // epilogue: lane holds (r0,c0),(r0,c0+1),(r1,c0),(r1,c0+1) per (mt,nt)
#pragma unroll
    for (int mt = 0; mt < 2; mt++) {
#pragma unroll
        for (int nt = 0; nt < 4; nt++) {
#pragma unroll
            for (int e = 0; e < 4; e++) {
                int r = brow + wm + mt * 16 + grp + (e >= 2 ? 8 : 0);
                int c = bcol + wn + nt * 8 + 2 * thr + (e & 1);
                if (r >= NN || c >= M) continue;
                float v = acc[mt][nt][e];
                if (EPI == 0) {
                    g.C[(size_t)r * g.ldc + c] = v;
                } else {
                    size_t lin = (size_t)r * 64 + c;
                    float xh = g.tl[lin] + g.lb[c];
                    xh = (xh > 0.f) ? xh : 0.01f * xh;
                    xh += id[lin];
                    float o = v + g.gb[c] + xh;
                    g.C[lin] = (o > 0.f) ? o : 0.01f * o;
                }
            }
        }
    }
}

// ---------------- tanh + l2norm ----------------
__global__ void __launch_bounds__(256)
k_tanh2(float* __restrict__ xv, const float* __restrict__ bv,
        float* __restrict__ xt, const float* __restrict__ bt) {
    int w = (blockIdx.x * blockDim.x + threadIdx.x) >> 5;
    int lane = threadIdx.x & 31;
    if (w >= 2 * NN) return;
    float* row;
    const float* b;
    int dim;
    if (w < NN) { row = xv + (size_t)w * LV; b = bv; dim = LV; }
    else        { row = xt + (size_t)(w - NN) * LT; b = bt; dim = LT; }
    float v[8];
    float ss = 0.f;
#pragma unroll
    for (int j = 0; j < 8; j++) {
        v[j] = 0.f;
        int c = lane + 32 * j;
        if (c < dim) {
            float t = tanhf(row[c] + b[c]);
            v[j] = t;
            ss += t * t;
        }
    }
#pragma unroll
    for (int o = 16; o; o >>= 1) ss += __shfl_xor_sync(~0u, ss, o);
    float sc = 1.f / fmaxf(sqrtf(ss), 1e-12f);
#pragma unroll
    for (int j = 0; j < 8; j++) {
        int c = lane + 32 * j;
        if (c < dim) row[c] = v[j] * sc;
    }
}

// ---------------- vector helpers ----------------
template <int VEC>
__device__ __forceinline__ void ldrow(const float* __restrict__ p, float* v) {
    if (VEC == 8) {
        float4 a = *(const float4*)p;
        float4 b = *(const float4*)(p + 4);
        v[0] = a.x; v[1] = a.y; v[2] = a.z; v[3] = a.w;
        v[4] = b.x; v[5] = b.y; v[6] = b.z; v[7] = b.w;
    } else if (VEC == 4) {
        float4 a = *(const float4*)p;
        v[0] = a.x; v[1] = a.y; v[2] = a.z; v[3] = a.w;
    } else {
        float2 a = *(const float2*)p;
        v[0] = a.x; v[1] = a.y;
    }
}

template <int VEC>
__device__ __forceinline__ void strow(float* __restrict__ p, const float* v) {
    if (VEC == 8) {
        *(float4*)p       = make_float4(v[0], v[1], v[2], v[3]);
        *(float4*)(p + 4) = make_float4(v[4], v[5], v[6], v[7]);
    } else if (VEC == 4) {
        *(float4*)p = make_float4(v[0], v[1], v[2], v[3]);
    } else {
        *(float2*)p = make_float2(v[0], v[1]);
    }
}

// ---------------- GAT (single-pass online softmax) ----------------
template <int VEC>
__device__ __forceinline__ void gat_update(const float* v, float di,
                                           const float (&hd)[VEC], float (&acc)[VEC],
                                           float& m, float& denom) {
    float d = 0.f;
#pragma unroll
    for (int j = 0; j < VEC; j++) {
        float lr = (v[j] > 0.f) ? v[j] : 0.01f * v[j];
        d += hd[j] * lr;
    }
#pragma unroll
    for (int o = 16; o; o >>= 1) d += __shfl_xor_sync(~0u, d, o);
    float t = d * di;
    float gate = 1.f / (1.f + __expf(-t));
    float lg = d * gate;
    if (lg > m) {
        float sc = __expf(m - lg);
        denom *= sc;
#pragma unroll
        for (int j = 0; j < VEC; j++) acc[j] *= sc;
        m = lg;
    }
    float w = __expf(lg - m);
    denom += w;
#pragma unroll
    for (int j = 0; j < VEC; j++) acc[j] += w * v[j];
}

template <int VEC>
__device__ __forceinline__ void gat_node(const float* __restrict__ hc, int dim,
                                         const int* __restrict__ esrc, int b0, int b1,
                                         const float* __restrict__ dinv,
                                         const float* __restrict__ bias,
                                         float* __restrict__ out, int n, int lane) {
    int c0 = lane * VEC;
    bool valid = c0 < dim;
    float hd[VEC];
#pragma unroll
    for (int j = 0; j < VEC; j++) hd[j] = 0.f;
    if (valid) ldrow<VEC>(hc + (size_t)n * dim + c0, hd);

    float m = -1e30f, denom = 0.f;
    float acc[VEC];
#pragma unroll
    for (int j = 0; j < VEC; j++) acc[j] = 0.f;

    int p = b0;
    for (; p + 3 < b1; p += 4) {
        int s[4];
        float di[4];
        float v[4][VEC];
#pragma unroll
        for (int q = 0; q < 4; q++) s[q] = esrc[p + q];
#pragma unroll
        for (int q = 0; q < 4; q++) di[q] = dinv[s[q]];
#pragma unroll
        for (int q = 0; q < 4; q++) {
#pragma unroll
            for (int j = 0; j < VEC; j++) v[q][j] = 0.f;
            if (valid) ldrow<VEC>(hc + (size_t)s[q] * dim + c0, v[q]);
        }
#pragma unroll
        for (int q = 0; q < 4; q++)
            gat_update<VEC>(v[q], di[q], hd, acc, m, denom);
    }
    for (; p < b1; p++) {
        int s = esrc[p];
        float di = dinv[s];
        float v[VEC];
#pragma unroll
        for (int j = 0; j < VEC; j++) v[j] = 0.f;
        if (valid) ldrow<VEC>(hc + (size_t)s * dim + c0, v);
        gat_update<VEC>(v, di, hd, acc, m, denom);
    }

    float inv = 1.f / (denom + 1e-16f);
    float val[VEC];
    float ss = 0.f;
#pragma unroll
    for (int j = 0; j < VEC; j++) {
        val[j] = 0.f;
        if (valid) {
            float v = acc[j] * inv + bias[c0 + j];
            val[j] = v;
            ss += v * v;
        }
    }
#pragma unroll
    for (int o = 16; o; o >>= 1) ss += __shfl_xor_sync(~0u, ss, o);
    float sc = 1.f / fmaxf(sqrtf(ss), 1e-12f);
    if (valid) {
        float res[VEC];
#pragma unroll
        for (int j = 0; j < VEC; j++) {
            float v = val[j] * sc;
            res[j] = (v > 0.f) ? v : 0.01f * v;
        }
        strow<VEC>(out + (size_t)n * dim + c0, res);
    }
}

__global__ void __launch_bounds__(128)
k_gat1(const float* __restrict__ hcv, const float* __restrict__ hct,
       const int* __restrict__ esrc, const int* __restrict__ off,
       const float* __restrict__ dinv,
       const float* __restrict__ bv, const float* __restrict__ bt,
       float* __restrict__ ov, float* __restrict__ ot) {
    int w = (blockIdx.x * blockDim.x + threadIdx.x) >> 5;
    int lane = threadIdx.x & 31;
    if (w >= 2 * NN) return;
    if (w < NN) {
        gat_node<8>(hcv, LV, esrc, off[w], off[w + 1], dinv, bv, ov, w, lane);
    } else {
        int n = w - NN;
        gat_node<4>(hct, LT, esrc, off[n], off[n + 1], dinv, bt, ot, n, lane);
    }
}

__global__ void __launch_bounds__(128)
k_gat2(const float* __restrict__ hcv, const float* __restrict__ hct,
       const int* __restrict__ esrc, const int* __restrict__ off,
       const float* __restrict__ dinv,
       const float* __restrict__ bv, const float* __restrict__ bt,
       float* __restrict__ ov, float* __restrict__ ot) {
    int w = (blockIdx.x * blockDim.x + threadIdx.x) >> 5;
    int lane = threadIdx.x & 31;
    if (w >= 2 * NN) return;
    if (w < NN) {
        gat_node<2>(hcv, DX, esrc, off[w], off[w + 1], dinv, bv, ov, w, lane);
    } else {
        int n = w - NN;
        gat_node<2>(hct, DX, esrc, off[n], off[n + 1], dinv, bt, ot, n, lane);
    }
}

// output: [representation | v_rep | t_rep]
__global__ void __launch_bounds__(256)
k_final(const float* __restrict__ vx1, const float* __restrict__ vx2,
        const float* __restrict__ tx1, const float* __restrict__ tx2,
        float* __restrict__ out, int out_size) {
    int i = blockIdx.x * blockDim.x + threadIdx.x;
    if (i >= NN * DX) return;
    int n = i >> 6, c = i & 63;
    float a1 = vx1[i], a2 = vx2[i], b1 = tx1[i], b2 = tx2[i];
    size_t base = (size_t)n * 128;
    out[base + c]      = (a1 + b1) * 0.5f;
    out[base + 64 + c] = (a2 + b2) * 0.5f;
    if (out_size >= 2 * NN * 128) {
        out[(size_t)NN * 128 + base + c]      = a1;
        out[(size_t)NN * 128 + base + 64 + c] = a2;
    }
    if (out_size >= 3 * NN * 128) {
        out[(size_t)2 * NN * 128 + base + c]      = b1;
        out[(size_t)2 * NN * 128 + base + 64 + c] = b2;
    }
}

// ---------------- host side ----------------
extern "C" void kernel_launch(void* const* d_in, const int* in_sizes, int n_in,
                              void* d_out, int out_size) {
    (void)in_sizes;
    (void)n_in;
    static float* F = nullptr;
    static int*   I = nullptr;
    if (!F) {
        cudaGetSymbolAddress((void**)&F, g_farena);
        cudaGetSymbolAddress((void**)&I, g_iarena);
    }

    float* x_v  = F;
    float* hc_v = F + 7680000;
    float* h_v  = F + 15360000;
    float* x_t  = F + 23040000;
    float* hc_t = F + 26040000;
    float* h_t  = F + 29040000;
    float* tl_v = F + 32040000;
    float* tl_t = F + 33960000;
    float* vx1  = F + 35880000;
    float* vx2  = F + 37800000;
    float* tx1  = F + 39720000;
    float* tx2  = F + 41640000;
    float* dinv = F + 43560000;

    int* src  = I;
    int* dst  = I + NE;
    int* esrc = I + 2 * NE;
    int* cnt  = I + 3 * NE;
    int* degs = cnt + (NN + 1);
    int* off  = degs + NN;
    int* cur  = off + (NN + 1);
    int* is64 = cur + NN;

    const float* feat  = (const float*)d_in[0];
    const void*  ei    = d_in[1];
    const float* idemb = (const float*)d_in[2];
    void* const* PV = d_in + 3;
    void* const* PT = d_in + 17;

#define PW(P, i) ((const float*)P[i])

    dim3 blk(256);
    int gy = (NN + 127) / 128;
    int warp2_grid = (2 * NN * 32 + 255) / 256;
    int gat_grid = (2 * NN * 32 + 127) / 128;

    k_zero_i<<<(2 * NN + 256) / 256, 256>>>(cnt, 2 * NN + 1);
    k_detect<<<1, 1>>>(ei, is64);
    k_convert_hist<<<(NE + 255) / 256, 256>>>(ei, src, dst, cnt, degs, is64);

    // S1: mlp GEMM (v M=256 -> x=0..3; t M=100 -> x=0,1, rest early-exit)
    {
        GP2 p = {{
            {feat, PW(PV, 0), x_v, nullptr, nullptr, nullptr, FDIM, LV, LV, 128, LV},
            {feat + 128, PW(PT, 0), x_t, nullptr, nullptr, nullptr, FDIM, LT, LT, 64, LT}}};
        k_gemm<0><<<dim3(4, gy, 2), blk>>>(p, nullptr);
    }
    // S2: tanh + l2norm
    k_tanh2<<<warp2_grid, 256>>>(x_v, PW(PV, 1), x_t, PW(PT, 1));
    // S3: c1 GEMM
    {
        GP2 p = {{
            {x_v, PW(PV, 2), hc_v, nullptr, nullptr, nullptr, LV, LV, LV, LV, LV},
            {x_t, PW(PT, 2), hc_t, nullptr, nullptr, nullptr, LT, LT, LT, LT, LT}}};
        k_gemm<0><<<dim3(4, gy, 2), blk>>>(p, nullptr);
    }

    // graph build tail
    k_scan<<<1, 1024>>>(cnt, off, cur, degs, dinv);
    k_fill<<<(NE + 255) / 256, 256>>>(src, dst, cur, esrc);
    k_sortseg<<<(NN + 255) / 256, 256>>>(off, esrc);

    // S4: GAT layer 1
    k_gat1<<<gat_grid, 128>>>(hc_v, hc_t, esrc, off, dinv, PW(PV, 3), PW(PT, 3), h_v, h_t);

    // S5: l1 GEMM
    {
        GP2 p = {{
            {x_v, PW(PV, 4), tl_v, nullptr, nullptr, nullptr, LV, DX, DX, LV, DX},
            {x_t, PW(PT, 4), tl_t, nullptr, nullptr, nullptr, LT, DX, DX, LT, DX}}};
        k_gemm<0><<<dim3(1, gy, 2), blk>>>(p, nullptr);
    }
    // S6: g1 GEMM + combine -> x1
    {
        GP2 p = {{
            {h_v, PW(PV, 6), vx1, tl_v, PW(PV, 5), PW(PV, 7), LV, DX, DX, LV, DX},
            {h_t, PW(PT, 6), tx1, tl_t, PW(PT, 5), PW(PT, 7), LT, DX, DX, LT, DX}}};
        k_gemm<1><<<dim3(1, gy, 2), blk>>>(p, idemb);
    }
    // S7: c2 GEMM
    {
        GP2 p = {{
            {vx1, PW(PV, 8), hc_v, nullptr, nullptr, nullptr, DX, DX, DX, DX, DX},
            {tx1, PW(PT, 8), hc_t, nullptr, nullptr, nullptr, DX, DX, DX, DX, DX}}};
        k_gemm<0><<<dim3(1, gy, 2), blk>>>(p, nullptr);
    }
    // S8: GAT layer 2
    k_gat2<<<gat_grid, 128>>>(hc_v, hc_t, esrc, off, dinv, PW(PV, 9), PW(PT, 9), h_v, h_t);

    // S9: l2 GEMM
    {
        GP2 p = {{
            {vx1, PW(PV, 10), tl_v, nullptr, nullptr, nullptr, DX, DX, DX, DX, DX},
            {tx1, PW(PT, 10), tl_t, nullptr, nullptr, nullptr, DX, DX, DX, DX, DX}}};
        k_gemm<0><<<dim3(1, gy, 2), blk>>>(p, nullptr);
    }
    // S10: g2 GEMM + combine -> x2
    {
        GP2 p = {{
            {h_v, PW(PV, 12), vx2, tl_v, PW(PV, 11), PW(PV, 13), DX, DX, DX, DX, DX},
            {h_t, PW(PT, 12), tx2, tl_t, PW(PT, 11), PW(PT, 13), DX, DX, DX, DX, DX}}};
        k_gemm<1><<<dim3(1, gy, 2), blk>>>(p, idemb);
    }

    k_final<<<(NN * DX + 255) / 256, 256>>>(vx1, vx2, tx1, tx2, (float*)d_out, out_size);
#undef PW
}

// round 10
// speedup vs baseline: 1.3012x; 1.0163x over previous
#include <cuda_runtime.h>
#include <math.h>
#include <stdint.h>

#define NN 30000
#define NE 480000
#define FDIM 192
#define DX 64
#define LV 256
#define LT 100

// ---------------- scratch arenas ----------------
__device__ float g_farena[44000000];
__device__ int   g_iarena[2700000];

// ---------------- graph build ----------------
__global__ void k_detect(const void* ei, int* is64) {
    const int* p = (const int*)ei;
    int zeros = 0;
    for (int i = 1; i < 256; i += 2) if (p[i] == 0) zeros++;
    *is64 = (zeros >= 120) ? 1 : 0;
}

__global__ void k_zero_i(int* a, int n) {
    int i = blockIdx.x * blockDim.x + threadIdx.x;
    if (i < n) a[i] = 0;
}

__global__ void k_convert_hist(const void* ei, int* src, int* dst,
                               int* cnt, int* degs, const int* is64) {
    int e = blockIdx.x * blockDim.x + threadIdx.x;
    if (e >= NE) return;
    int s, d;
    if (*is64) {
        const long long* p = (const long long*)ei;
        s = (int)p[e];
        d = (int)p[NE + e];
    } else {
        const int* p = (const int*)ei;
        s = p[e];
        d = p[NE + e];
    }
    src[e] = s;
    dst[e] = d;
    atomicAdd(&cnt[d], 1);
    atomicAdd(&degs[s], 1);
}

__global__ void __launch_bounds__(1024)
k_scan(const int* __restrict__ cnt, int* __restrict__ off, int* __restrict__ cur,
       const int* __restrict__ degs, float* __restrict__ dinv) {
    const int CH = 30;
    int t = threadIdx.x;
    int base = t * CH;
    int s = 0;
#pragma unroll 5
    for (int i = 0; i < CH; i++) {
        int idx = base + i;
        if (idx < NN) s += cnt[idx];
    }
    int lane = t & 31, wid = t >> 5;
    int v = s;
#pragma unroll
    for (int o = 1; o < 32; o <<= 1) {
        int u = __shfl_up_sync(~0u, v, o);
        if (lane >= o) v += u;
    }
    __shared__ int wt[32];
    if (lane == 31) wt[wid] = v;
    __syncthreads();
    if (wid == 0) {
        int w = wt[lane];
#pragma unroll
        for (int o = 1; o < 32; o <<= 1) {
            int u = __shfl_up_sync(~0u, w, o);
            if (lane >= o) w += u;
        }
        wt[lane] = w;
    }
    __syncthreads();
    int pre = v - s + (wid ? wt[wid - 1] : 0);
    int run = pre;
#pragma unroll 5
    for (int i = 0; i < CH; i++) {
        int idx = base + i;
        if (idx < NN) {
            off[idx] = run;
            cur[idx] = run;
            int dg = degs[idx];
            dinv[idx] = (dg > 0) ? rsqrtf((float)dg) : 0.f;
            run += cnt[idx];
        }
    }
    if (t == 1023) off[NN] = run;
}

__global__ void k_fill(const int* src, const int* dst, int* cur, int* esrc) {
    int e = blockIdx.x * blockDim.x + threadIdx.x;
    if (e >= NE) return;
    int p = atomicAdd(&cur[dst[e]], 1);
    esrc[p] = src[e];
}

// sort values within each segment (deterministic multiset) + emit (s, dinv[s])
__global__ void k_sortseg(const int* __restrict__ off, int* __restrict__ esrc,
                          const float* __restrict__ dinv, int2* __restrict__ esd) {
    int n = blockIdx.x * blockDim.x + threadIdx.x;
    if (n >= NN) return;
    int b = off[n], e = off[n + 1];
    for (int i = b + 1; i < e; i++) {
        int v = esrc[i];
        int j = i - 1;
        while (j >= b && esrc[j] > v) { esrc[j + 1] = esrc[j]; j--; }
        esrc[j + 1] = v;
    }
    for (int p = b; p < e; p++) {
        int s = esrc[p];
        esd[p] = make_int2(s, __float_as_int(dinv[s]));
    }
}

// ---------------- TF32 tensor-core GEMM ----------------
struct GP {
    const float* A;
    const float* B;
    float* C;
    const float* tl;
    const float* lb;
    const float* gb;
    int lda, ldb, ldc, K, M;
};
struct GP2 { GP g[2]; };

__device__ __forceinline__ float f2tf(float x) {
    uint32_t u;
    asm("cvt.rna.tf32.f32 %0, %1;" : "=r"(u) : "f"(x));
    return __uint_as_float(u);
}

__device__ __forceinline__ void mma_tf32(float* c,
                                         uint32_t a0, uint32_t a1, uint32_t a2, uint32_t a3,
                                         uint32_t b0, uint32_t b1) {
    asm volatile(
        "mma.sync.aligned.m16n8k8.row.col.f32.tf32.tf32.f32 "
        "{%0,%1,%2,%3}, {%4,%5,%6,%7}, {%8,%9}, {%0,%1,%2,%3};\n"
        : "+f"(c[0]), "+f"(c[1]), "+f"(c[2]), "+f"(c[3])
        : "r"(a0), "r"(a1), "r"(a2), "r"(a3), "r"(b0), "r"(b1));
}

#define SAS 136  // sA row stride (136%32==8 -> conflict-free frag loads)
#define SBS 72   // sB row stride (narrow kernel)
#define SWS 136  // sB row stride (wide kernel, 128 cols + pad)

// ===== wide GEMM: BM=128, BN=128, 256 thr = 4m x 2n warps, warp 32x64 =====
__global__ void __launch_bounds__(256)
k_gemmW(GP2 p) {
    GP g = p.g[blockIdx.z];
    const int bcol = blockIdx.x * 128;
    if (bcol >= g.M) return;
    __shared__ float sA[2][16][SAS];
    __shared__ float sB[2][16][SWS];
    const int tid = threadIdx.x;
    const int brow = blockIdx.y * 128;
    const int K = g.K, M = g.M;

    const int lane = tid & 31;
    const int wid  = tid >> 5;
    const int wm = (wid & 3) * 32;
    const int wn = (wid >> 2) * 64;
    const int grp = lane >> 2, thr = lane & 3;

    // A loads: 128 rows x 16 k = 512 float4; thread -> rows ar0, ar0+64
    const int ar0 = tid >> 2, akq = (tid & 3) * 4;
    const int ar1 = ar0 + 64;
    // B loads: 16 rows x 128 cols = 512 float4; thread -> rows br0, br0+8
    const int br0 = tid >> 5, bc4 = (tid & 31) * 4;
    const int br1 = br0 + 8;

    float4 pA0, pA1, pB0, pB1;

#define LD_A(dst, row, k0)                                                     \
    do {                                                                       \
        dst = make_float4(0.f, 0.f, 0.f, 0.f);                                 \
        if (brow + (row) < NN) {                                               \
            const float* ap = g.A + (size_t)(brow + (row)) * g.lda + (k0) + akq;\
            if ((k0) + akq + 3 < K) dst = *(const float4*)ap;                  \
            else {                                                             \
                if ((k0) + akq + 0 < K) dst.x = ap[0];                         \
                if ((k0) + akq + 1 < K) dst.y = ap[1];                         \
                if ((k0) + akq + 2 < K) dst.z = ap[2];                         \
                if ((k0) + akq + 3 < K) dst.w = ap[3];                         \
            }                                                                  \
        }                                                                      \
    } while (0)

#define LD_B(dst, row, k0)                                                     \
    do {                                                                       \
        dst = make_float4(0.f, 0.f, 0.f, 0.f);                                 \
        if ((k0) + (row) < K) {                                                \
            const float* bp = g.B + (size_t)((k0) + (row)) * g.ldb + bcol + bc4;\
            if (bcol + bc4 + 3 < M) dst = *(const float4*)bp;                  \
            else {                                                             \
                if (bcol + bc4 + 0 < M) dst.x = bp[0];                         \
                if (bcol + bc4 + 1 < M) dst.y = bp[1];                         \
                if (bcol + bc4 + 2 < M) dst.z = bp[2];                         \
                if (bcol + bc4 + 3 < M) dst.w = bp[3];                         \
            }                                                                  \
        }                                                                      \
    } while (0)

#define LOAD_TILE(k0) do { LD_A(pA0, ar0, k0); LD_A(pA1, ar1, k0);             \
                           LD_B(pB0, br0, k0); LD_B(pB1, br1, k0); } while (0)

#define STORE_TILE(buf)                                                        \
    do {                                                                       \
        sA[buf][akq + 0][ar0] = f2tf(pA0.x);                                   \
        sA[buf][akq + 1][ar0] = f2tf(pA0.y);                                   \
        sA[buf][akq + 2][ar0] = f2tf(pA0.z);                                   \
        sA[buf][akq + 3][ar0] = f2tf(pA0.w);                                   \
        sA[buf][akq + 0][ar1] = f2tf(pA1.x);                                   \
        sA[buf][akq + 1][ar1] = f2tf(pA1.y);                                   \
        sA[buf][akq + 2][ar1] = f2tf(pA1.z);                                   \
        sA[buf][akq + 3][ar1] = f2tf(pA1.w);                                   \
        sB[buf][br0][bc4 + 0] = f2tf(pB0.x);                                   \
        sB[buf][br0][bc4 + 1] = f2tf(pB0.y);                                   \
        sB[buf][br0][bc4 + 2] = f2tf(pB0.z);                                   \
        sB[buf][br0][bc4 + 3] = f2tf(pB0.w);                                   \
        sB[buf][br1][bc4 + 0] = f2tf(pB1.x);                                   \
        sB[buf][br1][bc4 + 1] = f2tf(pB1.y);                                   \
        sB[buf][br1][bc4 + 2] = f2tf(pB1.z);                                   \
        sB[buf][br1][bc4 + 3] = f2tf(pB1.w);                                   \
    } while (0)

    float acc[2][8][4] = {};
    LOAD_TILE(0);
    STORE_TILE(0);
    __syncthreads();
    int buf = 0;

    for (int k0 = 0; k0 < K; k0 += 16) {
        int nk = k0 + 16;
        if (nk < K) LOAD_TILE(nk);
#pragma unroll
        for (int ks = 0; ks < 2; ks++) {
            int kb = ks * 8;
            uint32_t af[2][4], bf[8][2];
#pragma unroll
            for (int mt = 0; mt < 2; mt++) {
                int r = wm + mt * 16 + grp;
                af[mt][0] = __float_as_uint(sA[buf][kb + thr][r]);
                af[mt][1] = __float_as_uint(sA[buf][kb + thr][r + 8]);
                af[mt][2] = __float_as_uint(sA[buf][kb + 4 + thr][r]);
                af[mt][3] = __float_as_uint(sA[buf][kb + 4 + thr][r + 8]);
            }
#pragma unroll
            for (int nt = 0; nt < 8; nt++) {
                int c = wn + nt * 8 + grp;
                bf[nt][0] = __float_as_uint(sB[buf][kb + thr][c]);
                bf[nt][1] = __float_as_uint(sB[buf][kb + 4 + thr][c]);
            }
#pragma unroll
            for (int mt = 0; mt < 2; mt++)
#pragma unroll
                for (int nt = 0; nt < 8; nt++)
                    mma_tf32(acc[mt][nt], af[mt][0], af[mt][1], af[mt][2], af[mt][3],
                             bf[nt][0], bf[nt][1]);
        }
        if (nk < K) {
            STORE_TILE(buf ^ 1);
            __syncthreads();
            buf ^= 1;
        }
    }
#undef LOAD_TILE
#undef STORE_TILE
#undef LD_A
#undef LD_B

#pragma unroll
    for (int mt = 0; mt < 2; mt++) {
#pragma unroll
        for (int nt = 0; nt < 8; nt++) {
#pragma unroll
            for (int e = 0; e < 4; e++) {
                int r = brow + wm + mt * 16 + grp + (e >= 2 ? 8 : 0);
                int c = bcol + wn + nt * 8 + 2 * thr + (e & 1);
                if (r < NN && c < M)
                    g.C[(size_t)r * g.ldc + c] = acc[mt][nt][e];
            }
        }
    }
}

// ===== narrow GEMM: BM=128, BN=64, 8 warps (4m x 2n), warp 32x32 =====
// EPI==1: C := lrelu( acc + gb[c] + lrelu(tl+lb) + id )  (M<=64, ldc=64)
template <int EPI>
__global__ void __launch_bounds__(256)
k_gemm(GP2 p, const float* __restrict__ id) {
    GP g = p.g[blockIdx.z];
    const int bcol = blockIdx.x * 64;
    if (bcol >= g.M) return;
    __shared__ float sA[2][16][SAS];
    __shared__ float sB[2][16][SBS];
    const int tid = threadIdx.x;
    const int brow = blockIdx.y * 128;
    const int K = g.K, M = g.M;

    const int lane = tid & 31;
    const int wid  = tid >> 5;
    const int wm = (wid & 3) * 32;
    const int wn = (wid >> 2) * 32;
    const int grp = lane >> 2, thr = lane & 3;

    const int ar0 = tid >> 2, akq = (tid & 3) * 4;
    const int ar1 = ar0 + 64;
    const int bkr = tid >> 4, bcq = (tid & 15) * 4;

    float4 pA0, pA1, pB;

#define LOAD_TILE(k0)                                                          \
    do {                                                                       \
        pA0 = make_float4(0.f, 0.f, 0.f, 0.f);                                 \
        pA1 = make_float4(0.f, 0.f, 0.f, 0.f);                                 \
        pB  = make_float4(0.f, 0.f, 0.f, 0.f);                                 \
        if (brow + ar0 < NN) {                                                 \
            const float* ap = g.A + (size_t)(brow + ar0) * g.lda + (k0) + akq; \
            if ((k0) + akq + 3 < K) pA0 = *(const float4*)ap;                  \
            else {                                                             \
                if ((k0) + akq + 0 < K) pA0.x = ap[0];                         \
                if ((k0) + akq + 1 < K) pA0.y = ap[1];                         \
                if ((k0) + akq + 2 < K) pA0.z = ap[2];                         \
                if ((k0) + akq + 3 < K) pA0.w = ap[3];                         \
            }                                                                  \
        }                                                                      \
        if (brow + ar1 < NN) {                                                 \
            const float* ap = g.A + (size_t)(brow + ar1) * g.lda + (k0) + akq; \
            if ((k0) + akq + 3 < K) pA1 = *(const float4*)ap;                  \
            else {                                                             \
                if ((k0) + akq + 0 < K) pA1.x = ap[0];                         \
                if ((k0) + akq + 1 < K) pA1.y = ap[1];                         \
                if ((k0) + akq + 2 < K) pA1.z = ap[2];                         \
                if ((k0) + akq + 3 < K) pA1.w = ap[3];                         \
            }                                                                  \
        }                                                                      \
        if ((k0) + bkr < K) {                                                  \
            const float* bp = g.B + (size_t)((k0) + bkr) * g.ldb + bcol + bcq; \
            if (bcol + bcq + 3 < M) pB = *(const float4*)bp;                   \
            else {                                                             \
                if (bcol + bcq + 0 < M) pB.x = bp[0];                          \
                if (bcol + bcq + 1 < M) pB.y = bp[1];                          \
                if (bcol + bcq + 2 < M) pB.z = bp[2];                          \
                if (bcol + bcq + 3 < M) pB.w = bp[3];                          \
            }                                                                  \
        }                                                                      \
    } while (0)

#define STORE_TILE(buf)                                                        \
    do {                                                                       \
        sA[buf][akq + 0][ar0] = f2tf(pA0.x);                                   \
        sA[buf][akq + 1][ar0] = f2tf(pA0.y);                                   \
        sA[buf][akq + 2][ar0] = f2tf(pA0.z);                                   \
        sA[buf][akq + 3][ar0] = f2tf(pA0.w);                                   \
        sA[buf][akq + 0][ar1] = f2tf(pA1.x);                                   \
        sA[buf][akq + 1][ar1] = f2tf(pA1.y);                                   \
        sA[buf][akq + 2][ar1] = f2tf(pA1.z);                                   \
        sA[buf][akq + 3][ar1] = f2tf(pA1.w);                                   \
        sB[buf][bkr][bcq + 0] = f2tf(pB.x);                                    \
        sB[buf][bkr][bcq + 1] = f2tf(pB.y);                                    \
        sB[buf][bkr][bcq + 2] = f2tf(pB.z);                                    \
        sB[buf][bkr][bcq + 3] = f2tf(pB.w);                                    \
    } while (0)

    float acc[2][4][4] = {};
    LOAD_TILE(0);
    STORE_TILE(0);
    __syncthreads();
    int buf = 0;

    for (int k0 = 0; k0 < K; k0 += 16) {
        int nk = k0 + 16;
        if (nk < K) LOAD_TILE(nk);
#pragma unroll
        for (int ks = 0; ks < 2; ks++) {
            int kb = ks * 8;
            uint32_t af[2][4], bf[4][2];
#pragma unroll
            for (int mt = 0; mt < 2; mt++) {
                int r = wm + mt * 16 + grp;
                af[mt][0] = __float_as_uint(sA[buf][kb + thr][r]);
                af[mt][1] = __float_as_uint(sA[buf][kb + thr][r + 8]);
                af[mt][2] = __float_as_uint(sA[buf][kb + 4 + thr][r]);
                af[mt][3] = __float_as_uint(sA[buf][kb + 4 + thr][r + 8]);
            }
#pragma unroll
            for (int nt = 0; nt < 4; nt++) {
                int c = wn + nt * 8 + grp;
                bf[nt][0] = __float_as_uint(sB[buf][kb + thr][c]);
                bf[nt][1] = __float_as_uint(sB[buf][kb + 4 + thr][c]);
            }
#pragma unroll
            for (int mt = 0; mt < 2; mt++)
#pragma unroll
                for (int nt = 0; nt < 4; nt++)
                    mma_tf32(acc[mt][nt], af[mt][0], af[mt][1], af[mt][2], af[mt][3],
                             bf[nt][0], bf[nt][1]);
        }
        if (nk < K) {
            STORE_TILE(buf ^ 1);
            __syncthreads();
            buf ^= 1;
        }
    }
#undef LOAD_TILE
#undef STORE_TILE

#pragma unroll
    for (int mt = 0; mt < 2; mt++) {
#pragma unroll
        for (int nt = 0; nt < 4; nt++) {
#pragma unroll
            for (int e = 0; e < 4; e++) {
                int r = brow + wm + mt * 16 + grp + (e >= 2 ? 8 : 0);
                int c = bcol + wn + nt * 8 + 2 * thr + (e & 1);
                if (r >= NN || c >= M) continue;
                float v = acc[mt][nt][e];
                if (EPI == 0) {
                    g.C[(size_t)r * g.ldc + c] = v;
                } else {
                    size_t lin = (size_t)r * 64 + c;
                    float xh = g.tl[lin] + g.lb[c];
                    xh = (xh > 0.f) ? xh : 0.01f * xh;
                    xh += id[lin];
                    float o = v + g.gb[c] + xh;
                    g.C[lin] = (o > 0.f) ? o : 0.01f * o;
                }
            }
        }
    }
}

// ---------------- tanh + l2norm ----------------
__global__ void __launch_bounds__(256)
k_tanh2(float* __restrict__ xv, const float* __restrict__ bv,
        float* __restrict__ xt, const float* __restrict__ bt) {
    int w = (blockIdx.x * blockDim.x + threadIdx.x) >> 5;
    int lane = threadIdx.x & 31;
    if (w >= 2 * NN) return;
    float* row;
    const float* b;
    int dim;
    if (w < NN) { row = xv + (size_t)w * LV; b = bv; dim = LV; }
    else        { row = xt + (size_t)(w - NN) * LT; b = bt; dim = LT; }
    float v[8];
    float ss = 0.f;
#pragma unroll
    for (int j = 0; j < 8; j++) {
        v[j] = 0.f;
        int c = lane + 32 * j;
        if (c < dim) {
            float t = tanhf(row[c] + b[c]);
            v[j] = t;
            ss += t * t;
        }
    }
#pragma unroll
    for (int o = 16; o; o >>= 1) ss += __shfl_xor_sync(~0u, ss, o);
    float sc = 1.f / fmaxf(sqrtf(ss), 1e-12f);
#pragma unroll
    for (int j = 0; j < 8; j++) {
        int c = lane + 32 * j;
        if (c < dim) row[c] = v[j] * sc;
    }
}

// ---------------- vector helpers ----------------
template <int VEC>
__device__ __forceinline__ void ldrow(const float* __restrict__ p, float* v) {
    if (VEC == 8) {
        float4 a = *(const float4*)p;
        float4 b = *(const float4*)(p + 4);
        v[0] = a.x; v[1] = a.y; v[2] = a.z; v[3] = a.w;
        v[4] = b.x; v[5] = b.y; v[6] = b.z; v[7] = b.w;
    } else if (VEC == 4) {
        float4 a = *(const float4*)p;
        v[0] = a.x; v[1] = a.y; v[2] = a.z; v[3] = a.w;
    } else {
        float2 a = *(const float2*)p;
        v[0] = a.x; v[1] = a.y;
    }
}

template <int VEC>
__device__ __forceinline__ void strow(float* __restrict__ p, const float* v) {
    if (VEC == 8) {
        *(float4*)p       = make_float4(v[0], v[1], v[2], v[3]);
        *(float4*)(p + 4) = make_float4(v[4], v[5], v[6], v[7]);
    } else if (VEC == 4) {
        *(float4*)p = make_float4(v[0], v[1], v[2], v[3]);
    } else {
        *(float2*)p = make_float2(v[0], v[1]);
    }
}

// ---------------- GAT (single-pass online softmax) ----------------
template <int VEC>
__device__ __forceinline__ void gat_update(const float* v, float di,
                                           const float (&hd)[VEC], float (&acc)[VEC],
                                           float& m, float& denom) {
    float d = 0.f;
#pragma unroll
    for (int j = 0; j < VEC; j++) {
        float lr = (v[j] > 0.f) ? v[j] : 0.01f * v[j];
        d += hd[j] * lr;
    }
#pragma unroll
    for (int o = 16; o; o >>= 1) d += __shfl_xor_sync(~0u, d, o);
    float t = d * di;
    float gate = 1.f / (1.f + __expf(-t));
    float lg = d * gate;
    if (lg > m) {
        float sc = __expf(m - lg);
        denom *= sc;
#pragma unroll
        for (int j = 0; j < VEC; j++) acc[j] *= sc;
        m = lg;
    }
    float w = __expf(lg - m);
    denom += w;
#pragma unroll
    for (int j = 0; j < VEC; j++) acc[j] += w * v[j];
}

template <int VEC>
__device__ __forceinline__ void gat_node(const float* __restrict__ hc, int dim,
                                         const int2* __restrict__ esd, int b0, int b1,
                                         const float* __restrict__ bias,
                                         float* __restrict__ out, int n, int lane) {
    int c0 = lane * VEC;
    bool valid = c0 < dim;
    float hd[VEC];
#pragma unroll
    for (int j = 0; j < VEC; j++) hd[j] = 0.f;
    if (valid) ldrow<VEC>(hc + (size_t)n * dim + c0, hd);

    float m = -1e30f, denom = 0.f;
    float acc[VEC];
#pragma unroll
    for (int j = 0; j < VEC; j++) acc[j] = 0.f;

    int p = b0;
    for (; p + 3 < b1; p += 4) {
        int2 e[4];
        float v[4][VEC];
#pragma unroll
        for (int q = 0; q < 4; q++) e[q] = esd[p + q];
#pragma unroll
        for (int q = 0; q < 4; q++) {
#pragma unroll
            for (int j = 0; j < VEC; j++) v[q][j] = 0.f;
            if (valid) ldrow<VEC>(hc + (size_t)e[q].x * dim + c0, v[q]);
        }
#pragma unroll
        for (int q = 0; q < 4; q++)
            gat_update<VEC>(v[q], __int_as_float(e[q].y), hd, acc, m, denom);
    }
    for (; p < b1; p++) {
        int2 e = esd[p];
        float v[VEC];
#pragma unroll
        for (int j = 0; j < VEC; j++) v[j] = 0.f;
        if (valid) ldrow<VEC>(hc + (size_t)e.x * dim + c0, v);
        gat_update<VEC>(v, __int_as_float(e.y), hd, acc, m, denom);
    }

    float inv = 1.f / (denom + 1e-16f);
    float val[VEC];
    float ss = 0.f;
#pragma unroll
    for (int j = 0; j < VEC; j++) {
        val[j] = 0.f;
        if (valid) {
            float v = acc[j] * inv + bias[c0 + j];
            val[j] = v;
            ss += v * v;
        }
    }
#pragma unroll
    for (int o = 16; o; o >>= 1) ss += __shfl_xor_sync(~0u, ss, o);
    float sc = 1.f / fmaxf(sqrtf(ss), 1e-12f);
    if (valid) {
        float res[VEC];
#pragma unroll
        for (int j = 0; j < VEC; j++) {
            float v = val[j] * sc;
            res[j] = (v > 0.f) ? v : 0.01f * v;
        }
        strow<VEC>(out + (size_t)n * dim + c0, res);
    }
}

__global__ void __launch_bounds__(128)
k_gat1(const float* __restrict__ hcv, const float* __restrict__ hct,
       const int2* __restrict__ esd, const int* __restrict__ off,
       const float* __restrict__ bv, const float* __restrict__ bt,
       float* __restrict__ ov, float* __restrict__ ot) {
    int w = (blockIdx.x * blockDim.x + threadIdx.x) >> 5;
    int lane = threadIdx.x & 31;
    if (w >= 2 * NN) return;
    if (w < NN) {
        gat_node<8>(hcv, LV, esd, off[w], off[w + 1], bv, ov, w, lane);
    } else {
        int n = w - NN;
        gat_node<4>(hct, LT, esd, off[n], off[n + 1], bt, ot, n, lane);
    }
}

__global__ void __launch_bounds__(128)
k_gat2(const float* __restrict__ hcv, const float* __restrict__ hct,
       const int2* __restrict__ esd, const int* __restrict__ off,
       const float* __restrict__ bv, const float* __restrict__ bt,
       float* __restrict__ ov, float* __restrict__ ot) {
    int w = (blockIdx.x * blockDim.x + threadIdx.x) >> 5;
    int lane = threadIdx.x & 31;
    if (w >= 2 * NN) return;
    if (w < NN) {
        gat_node<2>(hcv, DX, esd, off[w], off[w + 1], bv, ov, w, lane);
    } else {
        int n = w - NN;
        gat_node<2>(hct, DX, esd, off[n], off[n + 1], bt, ot, n, lane);
    }
}

// output: [representation | v_rep | t_rep]
__global__ void __launch_bounds__(256)
k_final(const float* __restrict__ vx1, const float* __restrict__ vx2,
        const float* __restrict__ tx1, const float* __restrict__ tx2,
        float* __restrict__ out, int out_size) {
    int i = blockIdx.x * blockDim.x + threadIdx.x;
    if (i >= NN * DX) return;
    int n = i >> 6, c = i & 63;
    float a1 = vx1[i], a2 = vx2[i], b1 = tx1[i], b2 = tx2[i];
    size_t base = (size_t)n * 128;
    out[base + c]      = (a1 + b1) * 0.5f;
    out[base + 64 + c] = (a2 + b2) * 0.5f;
    if (out_size >= 2 * NN * 128) {
        out[(size_t)NN * 128 + base + c]      = a1;
        out[(size_t)NN * 128 + base + 64 + c] = a2;
    }
    if (out_size >= 3 * NN * 128) {
        out[(size_t)2 * NN * 128 + base + c]      = b1;
        out[(size_t)2 * NN * 128 + base + 64 + c] = b2;
    }
}

// ---------------- host side ----------------
extern "C" void kernel_launch(void* const* d_in, const int* in_sizes, int n_in,
                              void* d_out, int out_size) {
    (void)in_sizes;
    (void)n_in;
    static float* F = nullptr;
    static int*   I = nullptr;
    if (!F) {
        cudaGetSymbolAddress((void**)&F, g_farena);
        cudaGetSymbolAddress((void**)&I, g_iarena);
    }

    float* x_v  = F;
    float* hc_v = F + 7680000;
    float* h_v  = F + 15360000;
    float* x_t  = F + 23040000;
    float* hc_t = F + 26040000;
    float* h_t  = F + 29040000;
    float* tl_v = F + 32040000;
    float* tl_t = F + 33960000;
    float* vx1  = F + 35880000;
    float* vx2  = F + 37800000;
    float* tx1  = F + 39720000;
    float* tx2  = F + 41640000;
    float* dinv = F + 43560000;

    int*  src  = I;
    int*  dst  = I + NE;
    int*  esrc = I + 2 * NE;
    int2* esd  = (int2*)(I + 3 * NE);      // 2*NE ints
    int*  cnt  = I + 5 * NE;               // NN+1
    int*  degs = cnt + (NN + 1);
    int*  off  = degs + NN;
    int*  cur  = off + (NN + 1);
    int*  is64 = cur + NN;

    const float* feat  = (const float*)d_in[0];
    const void*  ei    = d_in[1];
    const float* idemb = (const float*)d_in[2];
    void* const* PV = d_in + 3;
    void* const* PT = d_in + 17;

#define PW(P, i) ((const float*)P[i])

    dim3 blk(256);
    int gy = (NN + 127) / 128;
    int warp2_grid = (2 * NN * 32 + 255) / 256;
    int gat_grid = (2 * NN * 32 + 127) / 128;

    k_zero_i<<<(2 * NN + 256) / 256, 256>>>(cnt, 2 * NN + 1);
    k_detect<<<1, 1>>>(ei, is64);
    k_convert_hist<<<(NE + 255) / 256, 256>>>(ei, src, dst, cnt, degs, is64);

    // S1: mlp GEMM (wide; v M=256 -> x=0,1; t M=100 -> x=0)
    {
        GP2 p = {{
            {feat, PW(PV, 0), x_v, nullptr, nullptr, nullptr, FDIM, LV, LV, 128, LV},
            {feat + 128, PW(PT, 0), x_t, nullptr, nullptr, nullptr, FDIM, LT, LT, 64, LT}}};
        k_gemmW<<<dim3(2, gy, 2), blk>>>(p);
    }
    // S2: tanh + l2norm
    k_tanh2<<<warp2_grid, 256>>>(x_v, PW(PV, 1), x_t, PW(PT, 1));
    // S3: c1 GEMM (wide)
    {
        GP2 p = {{
            {x_v, PW(PV, 2), hc_v, nullptr, nullptr, nullptr, LV, LV, LV, LV, LV},
            {x_t, PW(PT, 2), hc_t, nullptr, nullptr, nullptr, LT, LT, LT, LT, LT}}};
        k_gemmW<<<dim3(2, gy, 2), blk>>>(p);
    }

    // graph build tail
    k_scan<<<1, 1024>>>(cnt, off, cur, degs, dinv);
    k_fill<<<(NE + 255) / 256, 256>>>(src, dst, cur, esrc);
    k_sortseg<<<(NN + 255) / 256, 256>>>(off, esrc, dinv, esd);

    // S4: GAT layer 1
    k_gat1<<<gat_grid, 128>>>(hc_v, hc_t, esd, off, PW(PV, 3), PW(PT, 3), h_v, h_t);

    // S5: l1 GEMM
    {
        GP2 p = {{
            {x_v, PW(PV, 4), tl_v, nullptr, nullptr, nullptr, LV, DX, DX, LV, DX},
            {x_t, PW(PT, 4), tl_t, nullptr, nullptr, nullptr, LT, DX, DX, LT, DX}}};
        k_gemm<0><<<dim3(1, gy, 2), blk>>>(p, nullptr);
    }
    // S6: g1 GEMM + combine -> x1
    {
        GP2 p = {{
            {h_v, PW(PV, 6), vx1, tl_v, PW(PV, 5), PW(PV, 7), LV, DX, DX, LV, DX},
            {h_t, PW(PT, 6), tx1, tl_t, PW(PT, 5), PW(PT, 7), LT, DX, DX, LT, DX}}};
        k_gemm<1><<<dim3(1, gy, 2), blk>>>(p, idemb);
    }
    // S7: c2 GEMM
    {
        GP2 p = {{
            {vx1, PW(PV, 8), hc_v, nullptr, nullptr, nullptr, DX, DX, DX, DX, DX},
            {tx1, PW(PT, 8), hc_t, nullptr, nullptr, nullptr, DX, DX, DX, DX, DX}}};
        k_gemm<0><<<dim3(1, gy, 2), blk>>>(p, nullptr);
    }
    // S8: GAT layer 2
    k_gat2<<<gat_grid, 128>>>(hc_v, hc_t, esd, off, PW(PV, 9), PW(PT, 9), h_v, h_t);

    // S9: l2 GEMM
    {
        GP2 p = {{
            {vx1, PW(PV, 10), tl_v, nullptr, nullptr, nullptr, DX, DX, DX, DX, DX},
            {tx1, PW(PT, 10), tl_t, nullptr, nullptr, nullptr, DX, DX, DX, DX, DX}}};
        k_gemm<0><<<dim3(1, gy, 2), blk>>>(p, nullptr);
    }
    // S10: g2 GEMM + combine -> x2
    {
        GP2 p = {{
            {h_v, PW(PV, 12), vx2, tl_v, PW(PV, 11), PW(PV, 13), DX, DX, DX, DX, DX},
            {h_t, PW(PT, 12), tx2, tl_t, PW(PT, 11), PW(PT, 13), DX, DX, DX, DX, DX}}};
        k_gemm<1><<<dim3(1, gy, 2), blk>>>(p, idemb);
    }

    k_final<<<(NN * DX + 255) / 256, 256>>>(vx1, vx2, tx1, tx2, (float*)d_out, out_size);
#undef PW
}

// round 11
// speedup vs baseline: 1.3062x; 1.0038x over previous
#include <cuda_runtime.h>
#include <math.h>
#include <stdint.h>

#define NN 30000
#define NE 480000
#define FDIM 192
#define DX 64
#define LV 256
#define LT 100

// ---------------- scratch arenas ----------------
__device__ float g_farena[44000000];
__device__ int   g_iarena[2700000];

// ---------------- graph build ----------------
__global__ void k_detect(const void* ei, int* is64) {
    const int* p = (const int*)ei;
    int zeros = 0;
    for (int i = 1; i < 256; i += 2) if (p[i] == 0) zeros++;
    *is64 = (zeros >= 120) ? 1 : 0;
}

__global__ void k_zero_i(int* a, int n) {
    int i = blockIdx.x * blockDim.x + threadIdx.x;
    if (i < n) a[i] = 0;
}

__global__ void k_convert_hist(const void* ei, int* src, int* dst,
                               int* cnt, int* degs, const int* is64) {
    int e = blockIdx.x * blockDim.x + threadIdx.x;
    if (e >= NE) return;
    int s, d;
    if (*is64) {
        const long long* p = (const long long*)ei;
        s = (int)p[e];
        d = (int)p[NE + e];
    } else {
        const int* p = (const int*)ei;
        s = p[e];
        d = p[NE + e];
    }
    src[e] = s;
    dst[e] = d;
    atomicAdd(&cnt[d], 1);
    atomicAdd(&degs[s], 1);
}

__global__ void __launch_bounds__(1024)
k_scan(const int* __restrict__ cnt, int* __restrict__ off, int* __restrict__ cur,
       const int* __restrict__ degs, float* __restrict__ dinv) {
    const int CH = 30;
    int t = threadIdx.x;
    int base = t * CH;
    int s = 0;
#pragma unroll 5
    for (int i = 0; i < CH; i++) {
        int idx = base + i;
        if (idx < NN) s += cnt[idx];
    }
    int lane = t & 31, wid = t >> 5;
    int v = s;
#pragma unroll
    for (int o = 1; o < 32; o <<= 1) {
        int u = __shfl_up_sync(~0u, v, o);
        if (lane >= o) v += u;
    }
    __shared__ int wt[32];
    if (lane == 31) wt[wid] = v;
    __syncthreads();
    if (wid == 0) {
        int w = wt[lane];
#pragma unroll
        for (int o = 1; o < 32; o <<= 1) {
            int u = __shfl_up_sync(~0u, w, o);
            if (lane >= o) w += u;
        }
        wt[lane] = w;
    }
    __syncthreads();
    int pre = v - s + (wid ? wt[wid - 1] : 0);
    int run = pre;
#pragma unroll 5
    for (int i = 0; i < CH; i++) {
        int idx = base + i;
        if (idx < NN) {
            off[idx] = run;
            cur[idx] = run;
            int dg = degs[idx];
            dinv[idx] = (dg > 0) ? rsqrtf((float)dg) : 0.f;
            run += cnt[idx];
        }
    }
    if (t == 1023) off[NN] = run;
}

__global__ void k_fill(const int* src, const int* dst, int* cur, int* esrc) {
    int e = blockIdx.x * blockDim.x + threadIdx.x;
    if (e >= NE) return;
    int p = atomicAdd(&cur[dst[e]], 1);
    esrc[p] = src[e];
}

// sort values within each segment (deterministic multiset) + emit (s, dinv[s])
__global__ void k_sortseg(const int* __restrict__ off, int* __restrict__ esrc,
                          const float* __restrict__ dinv, int2* __restrict__ esd) {
    int n = blockIdx.x * blockDim.x + threadIdx.x;
    if (n >= NN) return;
    int b = off[n], e = off[n + 1];
    for (int i = b + 1; i < e; i++) {
        int v = esrc[i];
        int j = i - 1;
        while (j >= b && esrc[j] > v) { esrc[j + 1] = esrc[j]; j--; }
        esrc[j + 1] = v;
    }
    for (int p = b; p < e; p++) {
        int s = esrc[p];
        esd[p] = make_int2(s, __float_as_int(dinv[s]));
    }
}

// ---------------- TF32 tensor-core GEMM ----------------
struct GP {
    const float* A;
    const float* B;
    float* C;
    int lda, ldb, ldc, K, M;
};
struct GP2 { GP g[2]; };

// dual GEMM + combine params
struct GD {
    const float* x;   // A1 (row stride ldx)
    const float* l;   // B1 (K x 64)
    const float* h;   // A2 (row stride ldx)
    const float* g;   // B2 (K x 64)
    const float* lb;
    const float* gb;
    float* C;         // x-next (NN x 64)
    int ldx, K;
};
struct GD2 { GD d[2]; };

__device__ __forceinline__ float f2tf(float x) {
    uint32_t u;
    asm("cvt.rna.tf32.f32 %0, %1;" : "=r"(u) : "f"(x));
    return __uint_as_float(u);
}

__device__ __forceinline__ void mma_tf32(float* c,
                                         uint32_t a0, uint32_t a1, uint32_t a2, uint32_t a3,
                                         uint32_t b0, uint32_t b1) {
    asm volatile(
        "mma.sync.aligned.m16n8k8.row.col.f32.tf32.tf32.f32 "
        "{%0,%1,%2,%3}, {%4,%5,%6,%7}, {%8,%9}, {%0,%1,%2,%3};\n"
        : "+f"(c[0]), "+f"(c[1]), "+f"(c[2]), "+f"(c[3])
        : "r"(a0), "r"(a1), "r"(a2), "r"(a3), "r"(b0), "r"(b1));
}

#define SAS 136  // sA row stride (136%32==8 -> conflict-free frag loads)
#define SBS 72   // sB row stride (narrow/dual kernels)
#define SWS 136  // sB row stride (wide kernel)

// ===== wide GEMM: BM=128, BN=128, 256 thr = 4m x 2n warps, warp 32x64 =====
__global__ void __launch_bounds__(256)
k_gemmW(GP2 p) {
    GP g = p.g[blockIdx.z];
    const int bcol = blockIdx.x * 128;
    if (bcol >= g.M) return;
    __shared__ float sA[2][16][SAS];
    __shared__ float sB[2][16][SWS];
    const int tid = threadIdx.x;
    const int brow = blockIdx.y * 128;
    const int K = g.K, M = g.M;

    const int lane = tid & 31;
    const int wid  = tid >> 5;
    const int wm = (wid & 3) * 32;
    const int wn = (wid >> 2) * 64;
    const int grp = lane >> 2, thr = lane & 3;

    const int ar0 = tid >> 2, akq = (tid & 3) * 4;
    const int ar1 = ar0 + 64;
    const int br0 = tid >> 5, bc4 = (tid & 31) * 4;
    const int br1 = br0 + 8;

    float4 pA0, pA1, pB0, pB1;

#define LD_A(dst, row, k0)                                                     \
    do {                                                                       \
        dst = make_float4(0.f, 0.f, 0.f, 0.f);                                 \
        if (brow + (row) < NN) {                                               \
            const float* ap = g.A + (size_t)(brow + (row)) * g.lda + (k0) + akq;\
            if ((k0) + akq + 3 < K) dst = *(const float4*)ap;                  \
            else {                                                             \
                if ((k0) + akq + 0 < K) dst.x = ap[0];                         \
                if ((k0) + akq + 1 < K) dst.y = ap[1];                         \
                if ((k0) + akq + 2 < K) dst.z = ap[2];                         \
                if ((k0) + akq + 3 < K) dst.w = ap[3];                         \
            }                                                                  \
        }                                                                      \
    } while (0)

#define LD_B(dst, row, k0)                                                     \
    do {                                                                       \
        dst = make_float4(0.f, 0.f, 0.f, 0.f);                                 \
        if ((k0) + (row) < K) {                                                \
            const float* bp = g.B + (size_t)((k0) + (row)) * g.ldb + bcol + bc4;\
            if (bcol + bc4 + 3 < M) dst = *(const float4*)bp;                  \
            else {                                                             \
                if (bcol + bc4 + 0 < M) dst.x = bp[0];                         \
                if (bcol + bc4 + 1 < M) dst.y = bp[1];                         \
                if (bcol + bc4 + 2 < M) dst.z = bp[2];                         \
                if (bcol + bc4 + 3 < M) dst.w = bp[3];                         \
            }                                                                  \
        }                                                                      \
    } while (0)

#define LOAD_TILE(k0) do { LD_A(pA0, ar0, k0); LD_A(pA1, ar1, k0);             \
                           LD_B(pB0, br0, k0); LD_B(pB1, br1, k0); } while (0)

#define STORE_TILE(buf)                                                        \
    do {                                                                       \
        sA[buf][akq + 0][ar0] = f2tf(pA0.x);                                   \
        sA[buf][akq + 1][ar0] = f2tf(pA0.y);                                   \
        sA[buf][akq + 2][ar0] = f2tf(pA0.z);                                   \
        sA[buf][akq + 3][ar0] = f2tf(pA0.w);                                   \
        sA[buf][akq + 0][ar1] = f2tf(pA1.x);                                   \
        sA[buf][akq + 1][ar1] = f2tf(pA1.y);                                   \
        sA[buf][akq + 2][ar1] = f2tf(pA1.z);                                   \
        sA[buf][akq + 3][ar1] = f2tf(pA1.w);                                   \
        sB[buf][br0][bc4 + 0] = f2tf(pB0.x);                                   \
        sB[buf][br0][bc4 + 1] = f2tf(pB0.y);                                   \
        sB[buf][br0][bc4 + 2] = f2tf(pB0.z);                                   \
        sB[buf][br0][bc4 + 3] = f2tf(pB0.w);                                   \
        sB[buf][br1][bc4 + 0] = f2tf(pB1.x);                                   \
        sB[buf][br1][bc4 + 1] = f2tf(pB1.y);                                   \
        sB[buf][br1][bc4 + 2] = f2tf(pB1.z);                                   \
        sB[buf][br1][bc4 + 3] = f2tf(pB1.w);                                   \
    } while (0)

    float acc[2][8][4] = {};
    LOAD_TILE(0);
    STORE_TILE(0);
    __syncthreads();
    int buf = 0;

    for (int k0 = 0; k0 < K; k0 += 16) {
        int nk = k0 + 16;
        if (nk < K) LOAD_TILE(nk);
#pragma unroll
        for (int ks = 0; ks < 2; ks++) {
            int kb = ks * 8;
            uint32_t af[2][4], bf[8][2];
#pragma unroll
            for (int mt = 0; mt < 2; mt++) {
                int r = wm + mt * 16 + grp;
                af[mt][0] = __float_as_uint(sA[buf][kb + thr][r]);
                af[mt][1] = __float_as_uint(sA[buf][kb + thr][r + 8]);
                af[mt][2] = __float_as_uint(sA[buf][kb + 4 + thr][r]);
                af[mt][3] = __float_as_uint(sA[buf][kb + 4 + thr][r + 8]);
            }
#pragma unroll
            for (int nt = 0; nt < 8; nt++) {
                int c = wn + nt * 8 + grp;
                bf[nt][0] = __float_as_uint(sB[buf][kb + thr][c]);
                bf[nt][1] = __float_as_uint(sB[buf][kb + 4 + thr][c]);
            }
#pragma unroll
            for (int mt = 0; mt < 2; mt++)
#pragma unroll
                for (int nt = 0; nt < 8; nt++)
                    mma_tf32(acc[mt][nt], af[mt][0], af[mt][1], af[mt][2], af[mt][3],
                             bf[nt][0], bf[nt][1]);
        }
        if (nk < K) {
            STORE_TILE(buf ^ 1);
            __syncthreads();
            buf ^= 1;
        }
    }
#undef LOAD_TILE
#undef STORE_TILE
#undef LD_A
#undef LD_B

#pragma unroll
    for (int mt = 0; mt < 2; mt++) {
#pragma unroll
        for (int nt = 0; nt < 8; nt++) {
#pragma unroll
            for (int e = 0; e < 4; e++) {
                int r = brow + wm + mt * 16 + grp + (e >= 2 ? 8 : 0);
                int c = bcol + wn + nt * 8 + 2 * thr + (e & 1);
                if (r < NN && c < M)
                    g.C[(size_t)r * g.ldc + c] = acc[mt][nt][e];
            }
        }
    }
}

// ===== shared phase for narrow/dual kernels: BM=128, BN=64 (bcol=0 for dual) =====
// Runs one double-buffered K-loop accumulating into acc. Ends with a final
// __syncthreads so smem can be reused by the caller.
__device__ __forceinline__ void gemm_phase64(
    const float* __restrict__ A, int lda, const float* __restrict__ B, int ldb,
    int K, int brow, int bcol, int Mlim, int tid, float (&acc)[2][4][4],
    float (*sA)[16][SAS], float (*sB)[16][SBS]) {

    const int lane = tid & 31;
    const int wid  = tid >> 5;
    const int wm = (wid & 3) * 32;
    const int wn = (wid >> 2) * 32;
    const int grp = lane >> 2, thr = lane & 3;

    const int ar0 = tid >> 2, akq = (tid & 3) * 4;
    const int ar1 = ar0 + 64;
    const int bkr = tid >> 4, bcq = (tid & 15) * 4;

    float4 pA0, pA1, pB;

#define LOAD_TILE64(k0)                                                        \
    do {                                                                       \
        pA0 = make_float4(0.f, 0.f, 0.f, 0.f);                                 \
        pA1 = make_float4(0.f, 0.f, 0.f, 0.f);                                 \
        pB  = make_float4(0.f, 0.f, 0.f, 0.f);                                 \
        if (brow + ar0 < NN) {                                                 \
            const float* ap = A + (size_t)(brow + ar0) * lda + (k0) + akq;     \
            if ((k0) + akq + 3 < K) pA0 = *(const float4*)ap;                  \
            else {                                                             \
                if ((k0) + akq + 0 < K) pA0.x = ap[0];                         \
                if ((k0) + akq + 1 < K) pA0.y = ap[1];                         \
                if ((k0) + akq + 2 < K) pA0.z = ap[2];                         \
                if ((k0) + akq + 3 < K) pA0.w = ap[3];                         \
            }                                                                  \
        }                                                                      \
        if (brow + ar1 < NN) {                                                 \
            const float* ap = A + (size_t)(brow + ar1) * lda + (k0) + akq;     \
            if ((k0) + akq + 3 < K) pA1 = *(const float4*)ap;                  \
            else {                                                             \
                if ((k0) + akq + 0 < K) pA1.x = ap[0];                         \
                if ((k0) + akq + 1 < K) pA1.y = ap[1];                         \
                if ((k0) + akq + 2 < K) pA1.z = ap[2];                         \
                if ((k0) + akq + 3 < K) pA1.w = ap[3];                         \
            }                                                                  \
        }                                                                      \
        if ((k0) + bkr < K) {                                                  \
            const float* bp = B + (size_t)((k0) + bkr) * ldb + bcol + bcq;     \
            if (bcol + bcq + 3 < Mlim) pB = *(const float4*)bp;                \
            else {                                                             \
                if (bcol + bcq + 0 < Mlim) pB.x = bp[0];                       \
                if (bcol + bcq + 1 < Mlim) pB.y = bp[1];                       \
                if (bcol + bcq + 2 < Mlim) pB.z = bp[2];                       \
                if (bcol + bcq + 3 < Mlim) pB.w = bp[3];                       \
            }                                                                  \
        }                                                                      \
    } while (0)

#define STORE_TILE64(buf)                                                      \
    do {                                                                       \
        sA[buf][akq + 0][ar0] = f2tf(pA0.x);                                   \
        sA[buf][akq + 1][ar0] = f2tf(pA0.y);                                   \
        sA[buf][akq + 2][ar0] = f2tf(pA0.z);                                   \
        sA[buf][akq + 3][ar0] = f2tf(pA0.w);                                   \
        sA[buf][akq + 0][ar1] = f2tf(pA1.x);                                   \
        sA[buf][akq + 1][ar1] = f2tf(pA1.y);                                   \
        sA[buf][akq + 2][ar1] = f2tf(pA1.z);                                   \
        sA[buf][akq + 3][ar1] = f2tf(pA1.w);                                   \
        sB[buf][bkr][bcq + 0] = f2tf(pB.x);                                    \
        sB[buf][bkr][bcq + 1] = f2tf(pB.y);                                    \
        sB[buf][bkr][bcq + 2] = f2tf(pB.z);                                    \
        sB[buf][bkr][bcq + 3] = f2tf(pB.w);                                    \
    } while (0)

    LOAD_TILE64(0);
    STORE_TILE64(0);
    __syncthreads();
    int buf = 0;

    for (int k0 = 0; k0 < K; k0 += 16) {
        int nk = k0 + 16;
        if (nk < K) LOAD_TILE64(nk);
#pragma unroll
        for (int ks = 0; ks < 2; ks++) {
            int kb = ks * 8;
            uint32_t af[2][4], bf[4][2];
#pragma unroll
            for (int mt = 0; mt < 2; mt++) {
                int r = wm + mt * 16 + grp;
                af[mt][0] = __float_as_uint(sA[buf][kb + thr][r]);
                af[mt][1] = __float_as_uint(sA[buf][kb + thr][r + 8]);
                af[mt][2] = __float_as_uint(sA[buf][kb + 4 + thr][r]);
                af[mt][3] = __float_as_uint(sA[buf][kb + 4 + thr][r + 8]);
            }
#pragma unroll
            for (int nt = 0; nt < 4; nt++) {
                int c = wn + nt * 8 + grp;
                bf[nt][0] = __float_as_uint(sB[buf][kb + thr][c]);
                bf[nt][1] = __float_as_uint(sB[buf][kb + 4 + thr][c]);
            }
#pragma unroll
            for (int mt = 0; mt < 2; mt++)
#pragma unroll
                for (int nt = 0; nt < 4; nt++)
                    mma_tf32(acc[mt][nt], af[mt][0], af[mt][1], af[mt][2], af[mt][3],
                             bf[nt][0], bf[nt][1]);
        }
        if (nk < K) {
            STORE_TILE64(buf ^ 1);
            __syncthreads();
            buf ^= 1;
        }
    }
    __syncthreads();
#undef LOAD_TILE64
#undef STORE_TILE64
}

// ===== narrow GEMM (plain): C = A @ B =====
__global__ void __launch_bounds__(256)
k_gemm(GP2 p) {
    GP g = p.g[blockIdx.z];
    const int bcol = blockIdx.x * 64;
    if (bcol >= g.M) return;
    __shared__ float sA[2][16][SAS];
    __shared__ float sB[2][16][SBS];
    const int tid = threadIdx.x;
    const int brow = blockIdx.y * 128;

    float acc[2][4][4] = {};
    gemm_phase64(g.A, g.lda, g.B, g.ldb, g.K, brow, bcol, g.M, tid, acc, sA, sB);

    const int lane = tid & 31;
    const int wid  = tid >> 5;
    const int wm = (wid & 3) * 32;
    const int wn = (wid >> 2) * 32;
    const int grp = lane >> 2, thr = lane & 3;

#pragma unroll
    for (int mt = 0; mt < 2; mt++)
#pragma unroll
        for (int nt = 0; nt < 4; nt++)
#pragma unroll
            for (int e = 0; e < 4; e++) {
                int r = brow + wm + mt * 16 + grp + (e >= 2 ? 8 : 0);
                int c = bcol + wn + nt * 8 + 2 * thr + (e & 1);
                if (r < NN && c < g.M)
                    g.C[(size_t)r * g.ldc + c] = acc[mt][nt][e];
            }
}

// ===== dual GEMM + combine: x-next = lrelu( h@g + gb + lrelu(x@l + lb) + id ) =====
__global__ void __launch_bounds__(256)
k_gemmD(GD2 p, const float* __restrict__ id) {
    GD d = p.d[blockIdx.z];
    __shared__ float sA[2][16][SAS];
    __shared__ float sB[2][16][SBS];
    const int tid = threadIdx.x;
    const int brow = blockIdx.y * 128;

    float acc1[2][4][4] = {};
    float acc2[2][4][4] = {};
    gemm_phase64(d.x, d.ldx, d.l, DX, d.K, brow, 0, DX, tid, acc1, sA, sB);
    gemm_phase64(d.h, d.ldx, d.g, DX, d.K, brow, 0, DX, tid, acc2, sA, sB);

    const int lane = tid & 31;
    const int wid  = tid >> 5;
    const int wm = (wid & 3) * 32;
    const int wn = (wid >> 2) * 32;
    const int grp = lane >> 2, thr = lane & 3;

#pragma unroll
    for (int mt = 0; mt < 2; mt++)
#pragma unroll
        for (int nt = 0; nt < 4; nt++)
#pragma unroll
            for (int e = 0; e < 4; e++) {
                int r = brow + wm + mt * 16 + grp + (e >= 2 ? 8 : 0);
                int c = wn + nt * 8 + 2 * thr + (e & 1);
                if (r >= NN) continue;
                size_t lin = (size_t)r * 64 + c;
                float xh = acc1[mt][nt][e] + d.lb[c];
                xh = (xh > 0.f) ? xh : 0.01f * xh;
                xh += id[lin];
                float o = acc2[mt][nt][e] + d.gb[c] + xh;
                d.C[lin] = (o > 0.f) ? o : 0.01f * o;
            }
}

// ---------------- tanh + l2norm ----------------
__global__ void __launch_bounds__(256)
k_tanh2(float* __restrict__ xv, const float* __restrict__ bv,
        float* __restrict__ xt, const float* __restrict__ bt) {
    int w = (blockIdx.x * blockDim.x + threadIdx.x) >> 5;
    int lane = threadIdx.x & 31;
    if (w >= 2 * NN) return;
    float* row;
    const float* b;
    int dim;
    if (w < NN) { row = xv + (size_t)w * LV; b = bv; dim = LV; }
    else        { row = xt + (size_t)(w - NN) * LT; b = bt; dim = LT; }
    float v[8];
    float ss = 0.f;
#pragma unroll
    for (int j = 0; j < 8; j++) {
        v[j] = 0.f;
        int c = lane + 32 * j;
        if (c < dim) {
            float t = tanhf(row[c] + b[c]);
            v[j] = t;
            ss += t * t;
        }
    }
#pragma unroll
    for (int o = 16; o; o >>= 1) ss += __shfl_xor_sync(~0u, ss, o);
    float sc = 1.f / fmaxf(sqrtf(ss), 1e-12f);
#pragma unroll
    for (int j = 0; j < 8; j++) {
        int c = lane + 32 * j;
        if (c < dim) row[c] = v[j] * sc;
    }
}

// ---------------- vector helpers ----------------
template <int VEC>
__device__ __forceinline__ void ldrow(const float* __restrict__ p, float* v) {
    if (VEC == 8) {
        float4 a = *(const float4*)p;
        float4 b = *(const float4*)(p + 4);
        v[0] = a.x; v[1] = a.y; v[2] = a.z; v[3] = a.w;
        v[4] = b.x; v[5] = b.y; v[6] = b.z; v[7] = b.w;
    } else if (VEC == 4) {
        float4 a = *(const float4*)p;
        v[0] = a.x; v[1] = a.y; v[2] = a.z; v[3] = a.w;
    } else {
        float2 a = *(const float2*)p;
        v[0] = a.x; v[1] = a.y;
    }
}

template <int VEC>
__device__ __forceinline__ void strow(float* __restrict__ p, const float* v) {
    if (VEC == 8) {
        *(float4*)p       = make_float4(v[0], v[1], v[2], v[3]);
        *(float4*)(p + 4) = make_float4(v[4], v[5], v[6], v[7]);
    } else if (VEC == 4) {
        *(float4*)p = make_float4(v[0], v[1], v[2], v[3]);
    } else {
        *(float2*)p = make_float2(v[0], v[1]);
    }
}

// ---------------- GAT (single-pass online softmax) ----------------
template <int VEC>
__device__ __forceinline__ void gat_update(const float* v, float di,
                                           const float (&hd)[VEC], float (&acc)[VEC],
                                           float& m, float& denom) {
    float d = 0.f;
#pragma unroll
    for (int j = 0; j < VEC; j++) {
        float lr = (v[j] > 0.f) ? v[j] : 0.01f * v[j];
        d += hd[j] * lr;
    }
#pragma unroll
    for (int o = 16; o; o >>= 1) d += __shfl_xor_sync(~0u, d, o);
    float t = d * di;
    float gate = 1.f / (1.f + __expf(-t));
    float lg = d * gate;
    if (lg > m) {
        float sc = __expf(m - lg);
        denom *= sc;
#pragma unroll
        for (int j = 0; j < VEC; j++) acc[j] *= sc;
        m = lg;
    }
    float w = __expf(lg - m);
    denom += w;
#pragma unroll
    for (int j = 0; j < VEC; j++) acc[j] += w * v[j];
}

template <int VEC>
__device__ __forceinline__ void gat_node(const float* __restrict__ hc, int dim,
                                         const int2* __restrict__ esd, int b0, int b1,
                                         const float* __restrict__ bias,
                                         float* __restrict__ out, int n, int lane) {
    int c0 = lane * VEC;
    bool valid = c0 < dim;
    float hd[VEC];
#pragma unroll
    for (int j = 0; j < VEC; j++) hd[j] = 0.f;
    if (valid) ldrow<VEC>(hc + (size_t)n * dim + c0, hd);

    float m = -1e30f, denom = 0.f;
    float acc[VEC];
#pragma unroll
    for (int j = 0; j < VEC; j++) acc[j] = 0.f;

    int p = b0;
    for (; p + 3 < b1; p += 4) {
        int2 e[4];
        float v[4][VEC];
#pragma unroll
        for (int q = 0; q < 4; q++) e[q] = esd[p + q];
#pragma unroll
        for (int q = 0; q < 4; q++) {
#pragma unroll
            for (int j = 0; j < VEC; j++) v[q][j] = 0.f;
            if (valid) ldrow<VEC>(hc + (size_t)e[q].x * dim + c0, v[q]);
        }
#pragma unroll
        for (int q = 0; q < 4; q++)
            gat_update<VEC>(v[q], __int_as_float(e[q].y), hd, acc, m, denom);
    }
    for (; p < b1; p++) {
        int2 e = esd[p];
        float v[VEC];
#pragma unroll
        for (int j = 0; j < VEC; j++) v[j] = 0.f;
        if (valid) ldrow<VEC>(hc + (size_t)e.x * dim + c0, v);
        gat_update<VEC>(v, __int_as_float(e.y), hd, acc, m, denom);
    }

    float inv = 1.f / (denom + 1e-16f);
    float val[VEC];
    float ss = 0.f;
#pragma unroll
    for (int j = 0; j < VEC; j++) {
        val[j] = 0.f;
        if (valid) {
            float v = acc[j] * inv + bias[c0 + j];
            val[j] = v;
            ss += v * v;
        }
    }
#pragma unroll
    for (int o = 16; o; o >>= 1) ss += __shfl_xor_sync(~0u, ss, o);
    float sc = 1.f / fmaxf(sqrtf(ss), 1e-12f);
    if (valid) {
        float res[VEC];
#pragma unroll
        for (int j = 0; j < VEC; j++) {
            float v = val[j] * sc;
            res[j] = (v > 0.f) ? v : 0.01f * v;
        }
        strow<VEC>(out + (size_t)n * dim + c0, res);
    }
}

__global__ void __launch_bounds__(128)
k_gat1(const float* __restrict__ hcv, const float* __restrict__ hct,
       const int2* __restrict__ esd, const int* __restrict__ off,
       const float* __restrict__ bv, const float* __restrict__ bt,
       float* __restrict__ ov, float* __restrict__ ot) {
    int w = (blockIdx.x * blockDim.x + threadIdx.x) >> 5;
    int lane = threadIdx.x & 31;
    if (w >= 2 * NN) return;
    if (w < NN) {
        gat_node<8>(hcv, LV, esd, off[w], off[w + 1], bv, ov, w, lane);
    } else {
        int n = w - NN;
        gat_node<4>(hct, LT, esd, off[n], off[n + 1], bt, ot, n, lane);
    }
}

__global__ void __launch_bounds__(128)
k_gat2(const float* __restrict__ hcv, const float* __restrict__ hct,
       const int2* __restrict__ esd, const int* __restrict__ off,
       const float* __restrict__ bv, const float* __restrict__ bt,
       float* __restrict__ ov, float* __restrict__ ot) {
    int w = (blockIdx.x * blockDim.x + threadIdx.x) >> 5;
    int lane = threadIdx.x & 31;
    if (w >= 2 * NN) return;
    if (w < NN) {
        gat_node<2>(hcv, DX, esd, off[w], off[w + 1], bv, ov, w, lane);
    } else {
        int n = w - NN;
        gat_node<2>(hct, DX, esd, off[n], off[n + 1], bt, ot, n, lane);
    }
}

// output: [representation | v_rep | t_rep]
__global__ void __launch_bounds__(256)
k_final(const float* __restrict__ vx1, const float* __restrict__ vx2,
        const float* __restrict__ tx1, const float* __restrict__ tx2,
        float* __restrict__ out, int out_size) {
    int i = blockIdx.x * blockDim.x + threadIdx.x;
    if (i >= NN * DX) return;
    int n = i >> 6, c = i & 63;
    float a1 = vx1[i], a2 = vx2[i], b1 = tx1[i], b2 = tx2[i];
    size_t base = (size_t)n * 128;
    out[base + c]      = (a1 + b1) * 0.5f;
    out[base + 64 + c] = (a2 + b2) * 0.5f;
    if (out_size >= 2 * NN * 128) {
        out[(size_t)NN * 128 + base + c]      = a1;
        out[(size_t)NN * 128 + base + 64 + c] = a2;
    }
    if (out_size >= 3 * NN * 128) {
        out[(size_t)2 * NN * 128 + base + c]      = b1;
        out[(size_t)2 * NN * 128 + base + 64 + c] = b2;
    }
}

// ---------------- host side ----------------
extern "C" void kernel_launch(void* const* d_in, const int* in_sizes, int n_in,
                              void* d_out, int out_size) {
    (void)in_sizes;
    (void)n_in;
    static float* F = nullptr;
    static int*   I = nullptr;
    if (!F) {
        cudaGetSymbolAddress((void**)&F, g_farena);
        cudaGetSymbolAddress((void**)&I, g_iarena);
    }

    float* x_v  = F;
    float* hc_v = F + 7680000;
    float* h_v  = F + 15360000;
    float* x_t  = F + 23040000;
    float* hc_t = F + 26040000;
    float* h_t  = F + 29040000;
    float* vx1  = F + 35880000;
    float* vx2  = F + 37800000;
    float* tx1  = F + 39720000;
    float* tx2  = F + 41640000;
    float* dinv = F + 43560000;

    int*  src  = I;
    int*  dst  = I + NE;
    int*  esrc = I + 2 * NE;
    int2* esd  = (int2*)(I + 3 * NE);
    int*  cnt  = I + 5 * NE;
    int*  degs = cnt + (NN + 1);
    int*  off  = degs + NN;
    int*  cur  = off + (NN + 1);
    int*  is64 = cur + NN;

    const float* feat  = (const float*)d_in[0];
    const void*  ei    = d_in[1];
    const float* idemb = (const float*)d_in[2];
    void* const* PV = d_in + 3;
    void* const* PT = d_in + 17;

#define PW(P, i) ((const float*)P[i])

    dim3 blk(256);
    int gy = (NN + 127) / 128;
    int warp2_grid = (2 * NN * 32 + 255) / 256;
    int gat_grid = (2 * NN * 32 + 127) / 128;

    k_zero_i<<<(2 * NN + 256) / 256, 256>>>(cnt, 2 * NN + 1);
    k_detect<<<1, 1>>>(ei, is64);
    k_convert_hist<<<(NE + 255) / 256, 256>>>(ei, src, dst, cnt, degs, is64);

    // S1: mlp GEMM (wide)
    {
        GP2 p = {{
            {feat, PW(PV, 0), x_v, FDIM, LV, LV, 128, LV},
            {feat + 128, PW(PT, 0), x_t, FDIM, LT, LT, 64, LT}}};
        k_gemmW<<<dim3(2, gy, 2), blk>>>(p);
    }
    // S2: tanh + l2norm
    k_tanh2<<<warp2_grid, 256>>>(x_v, PW(PV, 1), x_t, PW(PT, 1));
    // S3: c1 GEMM (wide)
    {
        GP2 p = {{
            {x_v, PW(PV, 2), hc_v, LV, LV, LV, LV, LV},
            {x_t, PW(PT, 2), hc_t, LT, LT, LT, LT, LT}}};
        k_gemmW<<<dim3(2, gy, 2), blk>>>(p);
    }

    // graph build tail
    k_scan<<<1, 1024>>>(cnt, off, cur, degs, dinv);
    k_fill<<<(NE + 255) / 256, 256>>>(src, dst, cur, esrc);
    k_sortseg<<<(NN + 255) / 256, 256>>>(off, esrc, dinv, esd);

    // S4: GAT layer 1
    k_gat1<<<gat_grid, 128>>>(hc_v, hc_t, esd, off, PW(PV, 3), PW(PT, 3), h_v, h_t);

    // S5: fused l1+g1 GEMMs + combine -> x1
    {
        GD2 p = {{
            {x_v, PW(PV, 4), h_v, PW(PV, 6), PW(PV, 5), PW(PV, 7), vx1, LV, LV},
            {x_t, PW(PT, 4), h_t, PW(PT, 6), PW(PT, 5), PW(PT, 7), tx1, LT, LT}}};
        k_gemmD<<<dim3(1, gy, 2), blk>>>(p, idemb);
    }
    // S6: c2 GEMM
    {
        GP2 p = {{
            {vx1, PW(PV, 8), hc_v, DX, DX, DX, DX, DX},
            {tx1, PW(PT, 8), hc_t, DX, DX, DX, DX, DX}}};
        k_gemm<<<dim3(1, gy, 2), blk>>>(p);
    }
    // S7: GAT layer 2
    k_gat2<<<gat_grid, 128>>>(hc_v, hc_t, esd, off, PW(PV, 9), PW(PT, 9), h_v, h_t);

    // S8: fused l2+g2 GEMMs + combine -> x2
    {
        GD2 p = {{
            {vx1, PW(PV, 10), h_v, PW(PV, 12), PW(PV, 11), PW(PV, 13), vx2, DX, DX},
            {tx1, PW(PT, 10), h_t, PW(PT, 12), PW(PT, 11), PW(PT, 13), tx2, DX, DX}}};
        k_gemmD<<<dim3(1, gy, 2), blk>>>(p, idemb);
    }

    k_final<<<(NN * DX + 255) / 256, 256>>>(vx1, vx2, tx1, tx2, (float*)d_out, out_size);
#undef PW
}

// round 12
// speedup vs baseline: 1.3742x; 1.0520x over previous
#include <cuda_runtime.h>
#include <math.h>
#include <stdint.h>

#define NN 30000
#define NE 480000
#define FDIM 192
#define DX 64
#define LV 256
#define LT 100

// ---------------- scratch arenas ----------------
__device__ float g_farena[44000000];
__device__ int   g_iarena[2700000];

// ---------------- graph build ----------------
// zero cnt/degs arrays + thread (0,0) computes the int64-vs-int32 detection
__global__ void k_init(const void* ei, int* a, int n, int* is64) {
    int i = blockIdx.x * blockDim.x + threadIdx.x;
    if (i < n) a[i] = 0;
    if (blockIdx.x == 0 && threadIdx.x == 0) {
        const int* p = (const int*)ei;
        int zeros = 0;
#pragma unroll 8
        for (int j = 1; j < 256; j += 2) if (p[j] == 0) zeros++;
        *is64 = (zeros >= 120) ? 1 : 0;
    }
}

__global__ void k_convert_hist(const void* ei, int* src, int* dst,
                               int* cnt, int* degs, const int* is64) {
    int e = blockIdx.x * blockDim.x + threadIdx.x;
    if (e >= NE) return;
    int s, d;
    if (*is64) {
        const long long* p = (const long long*)ei;
        s = (int)p[e];
        d = (int)p[NE + e];
    } else {
        const int* p = (const int*)ei;
        s = p[e];
        d = p[NE + e];
    }
    src[e] = s;
    dst[e] = d;
    atomicAdd(&cnt[d], 1);
    atomicAdd(&degs[s], 1);
}

__global__ void __launch_bounds__(1024)
k_scan(const int* __restrict__ cnt, int* __restrict__ off, int* __restrict__ cur,
       const int* __restrict__ degs, float* __restrict__ dinv) {
    const int CH = 30;
    int t = threadIdx.x;
    int base = t * CH;
    int s = 0;
#pragma unroll 5
    for (int i = 0; i < CH; i++) {
        int idx = base + i;
        if (idx < NN) s += cnt[idx];
    }
    int lane = t & 31, wid = t >> 5;
    int v = s;
#pragma unroll
    for (int o = 1; o < 32; o <<= 1) {
        int u = __shfl_up_sync(~0u, v, o);
        if (lane >= o) v += u;
    }
    __shared__ int wt[32];
    if (lane == 31) wt[wid] = v;
    __syncthreads();
    if (wid == 0) {
        int w = wt[lane];
#pragma unroll
        for (int o = 1; o < 32; o <<= 1) {
            int u = __shfl_up_sync(~0u, w, o);
            if (lane >= o) w += u;
        }
        wt[lane] = w;
    }
    __syncthreads();
    int pre = v - s + (wid ? wt[wid - 1] : 0);
    int run = pre;
#pragma unroll 5
    for (int i = 0; i < CH; i++) {
        int idx = base + i;
        if (idx < NN) {
            off[idx] = run;
            cur[idx] = run;
            int dg = degs[idx];
            dinv[idx] = (dg > 0) ? rsqrtf((float)dg) : 0.f;
            run += cnt[idx];
        }
    }
    if (t == 1023) off[NN] = run;
}

__global__ void k_fill(const int* src, const int* dst, int* cur, int* esrc) {
    int e = blockIdx.x * blockDim.x + threadIdx.x;
    if (e >= NE) return;
    int p = atomicAdd(&cur[dst[e]], 1);
    esrc[p] = src[e];
}

// sort values within each segment (deterministic multiset) + emit (s, dinv[s])
__global__ void k_sortseg(const int* __restrict__ off, int* __restrict__ esrc,
                          const float* __restrict__ dinv, int2* __restrict__ esd) {
    int n = blockIdx.x * blockDim.x + threadIdx.x;
    if (n >= NN) return;
    int b = off[n], e = off[n + 1];
    for (int i = b + 1; i < e; i++) {
        int v = esrc[i];
        int j = i - 1;
        while (j >= b && esrc[j] > v) { esrc[j + 1] = esrc[j]; j--; }
        esrc[j + 1] = v;
    }
    for (int p = b; p < e; p++) {
        int s = esrc[p];
        esd[p] = make_int2(s, __float_as_int(dinv[s]));
    }
}

// ---------------- TF32 tensor-core GEMM ----------------
struct GP {
    const float* A;
    const float* B;
    float* C;
    int lda, ldb, ldc, K, M;
};
struct GP2 { GP g[2]; };

struct GD {
    const float* x;
    const float* l;
    const float* h;
    const float* g;
    const float* lb;
    const float* gb;
    float* C;
    int ldx, K;
};
struct GD2 { GD d[2]; };

__device__ __forceinline__ float f2tf(float x) {
    uint32_t u;
    asm("cvt.rna.tf32.f32 %0, %1;" : "=r"(u) : "f"(x));
    return __uint_as_float(u);
}

__device__ __forceinline__ void mma_tf32(float* c,
                                         uint32_t a0, uint32_t a1, uint32_t a2, uint32_t a3,
                                         uint32_t b0, uint32_t b1) {
    asm volatile(
        "mma.sync.aligned.m16n8k8.row.col.f32.tf32.tf32.f32 "
        "{%0,%1,%2,%3}, {%4,%5,%6,%7}, {%8,%9}, {%0,%1,%2,%3};\n"
        : "+f"(c[0]), "+f"(c[1]), "+f"(c[2]), "+f"(c[3])
        : "r"(a0), "r"(a1), "r"(a2), "r"(a3), "r"(b0), "r"(b1));
}

#define SAS 136
#define SBS 72
#define SWS 136

// ===== wide GEMM: BM=128, BN=128, 256 thr = 4m x 2n warps, warp 32x64 =====
__global__ void __launch_bounds__(256)
k_gemmW(GP2 p) {
    GP g = p.g[blockIdx.z];
    const int bcol = blockIdx.x * 128;
    if (bcol >= g.M) return;
    __shared__ float sA[2][16][SAS];
    __shared__ float sB[2][16][SWS];
    const int tid = threadIdx.x;
    const int brow = blockIdx.y * 128;
    const int K = g.K, M = g.M;

    const int lane = tid & 31;
    const int wid  = tid >> 5;
    const int wm = (wid & 3) * 32;
    const int wn = (wid >> 2) * 64;
    const int grp = lane >> 2, thr = lane & 3;

    const int ar0 = tid >> 2, akq = (tid & 3) * 4;
    const int ar1 = ar0 + 64;
    const int br0 = tid >> 5, bc4 = (tid & 31) * 4;
    const int br1 = br0 + 8;

    float4 pA0, pA1, pB0, pB1;

#define LD_A(dst, row, k0)                                                     \
    do {                                                                       \
        dst = make_float4(0.f, 0.f, 0.f, 0.f);                                 \
        if (brow + (row) < NN) {                                               \
            const float* ap = g.A + (size_t)(brow + (row)) * g.lda + (k0) + akq;\
            if ((k0) + akq + 3 < K) dst = *(const float4*)ap;                  \
            else {                                                             \
                if ((k0) + akq + 0 < K) dst.x = ap[0];                         \
                if ((k0) + akq + 1 < K) dst.y = ap[1];                         \
                if ((k0) + akq + 2 < K) dst.z = ap[2];                         \
                if ((k0) + akq + 3 < K) dst.w = ap[3];                         \
            }                                                                  \
        }                                                                      \
    } while (0)

#define LD_B(dst, row, k0)                                                     \
    do {                                                                       \
        dst = make_float4(0.f, 0.f, 0.f, 0.f);                                 \
        if ((k0) + (row) < K) {                                                \
            const float* bp = g.B + (size_t)((k0) + (row)) * g.ldb + bcol + bc4;\
            if (bcol + bc4 + 3 < M) dst = *(const float4*)bp;                  \
            else {                                                             \
                if (bcol + bc4 + 0 < M) dst.x = bp[0];                         \
                if (bcol + bc4 + 1 < M) dst.y = bp[1];                         \
                if (bcol + bc4 + 2 < M) dst.z = bp[2];                         \
                if (bcol + bc4 + 3 < M) dst.w = bp[3];                         \
            }                                                                  \
        }                                                                      \
    } while (0)

#define LOAD_TILE(k0) do { LD_A(pA0, ar0, k0); LD_A(pA1, ar1, k0);             \
                           LD_B(pB0, br0, k0); LD_B(pB1, br1, k0); } while (0)

#define STORE_TILE(buf)                                                        \
    do {                                                                       \
        sA[buf][akq + 0][ar0] = f2tf(pA0.x);                                   \
        sA[buf][akq + 1][ar0] = f2tf(pA0.y);                                   \
        sA[buf][akq + 2][ar0] = f2tf(pA0.z);                                   \
        sA[buf][akq + 3][ar0] = f2tf(pA0.w);                                   \
        sA[buf][akq + 0][ar1] = f2tf(pA1.x);                                   \
        sA[buf][akq + 1][ar1] = f2tf(pA1.y);                                   \
        sA[buf][akq + 2][ar1] = f2tf(pA1.z);                                   \
        sA[buf][akq + 3][ar1] = f2tf(pA1.w);                                   \
        sB[buf][br0][bc4 + 0] = f2tf(pB0.x);                                   \
        sB[buf][br0][bc4 + 1] = f2tf(pB0.y);                                   \
        sB[buf][br0][bc4 + 2] = f2tf(pB0.z);                                   \
        sB[buf][br0][bc4 + 3] = f2tf(pB0.w);                                   \
        sB[buf][br1][bc4 + 0] = f2tf(pB1.x);                                   \
        sB[buf][br1][bc4 + 1] = f2tf(pB1.y);                                   \
        sB[buf][br1][bc4 + 2] = f2tf(pB1.z);                                   \
        sB[buf][br1][bc4 + 3] = f2tf(pB1.w);                                   \
    } while (0)

    float acc[2][8][4] = {};
    LOAD_TILE(0);
    STORE_TILE(0);
    __syncthreads();
    int buf = 0;

    for (int k0 = 0; k0 < K; k0 += 16) {
        int nk = k0 + 16;
        if (nk < K) LOAD_TILE(nk);
#pragma unroll
        for (int ks = 0; ks < 2; ks++) {
            int kb = ks * 8;
            uint32_t af[2][4], bf[8][2];
#pragma unroll
            for (int mt = 0; mt < 2; mt++) {
                int r = wm + mt * 16 + grp;
                af[mt][0] = __float_as_uint(sA[buf][kb + thr][r]);
                af[mt][1] = __float_as_uint(sA[buf][kb + thr][r + 8]);
                af[mt][2] = __float_as_uint(sA[buf][kb + 4 + thr][r]);
                af[mt][3] = __float_as_uint(sA[buf][kb + 4 + thr][r + 8]);
            }
#pragma unroll
            for (int nt = 0; nt < 8; nt++) {
                int c = wn + nt * 8 + grp;
                bf[nt][0] = __float_as_uint(sB[buf][kb + thr][c]);
                bf[nt][1] = __float_as_uint(sB[buf][kb + 4 + thr][c]);
            }
#pragma unroll
            for (int mt = 0; mt < 2; mt++)
#pragma unroll
                for (int nt = 0; nt < 8; nt++)
                    mma_tf32(acc[mt][nt], af[mt][0], af[mt][1], af[mt][2], af[mt][3],
                             bf[nt][0], bf[nt][1]);
        }
        if (nk < K) {
            STORE_TILE(buf ^ 1);
            __syncthreads();
            buf ^= 1;
        }
    }
#undef LOAD_TILE
#undef STORE_TILE
#undef LD_A
#undef LD_B

#pragma unroll
    for (int mt = 0; mt < 2; mt++) {
#pragma unroll
        for (int nt = 0; nt < 8; nt++) {
#pragma unroll
            for (int e = 0; e < 4; e++) {
                int r = brow + wm + mt * 16 + grp + (e >= 2 ? 8 : 0);
                int c = bcol + wn + nt * 8 + 2 * thr + (e & 1);
                if (r < NN && c < M)
                    g.C[(size_t)r * g.ldc + c] = acc[mt][nt][e];
            }
        }
    }
}

// ===== shared phase for narrow/dual kernels =====
__device__ __forceinline__ void gemm_phase64(
    const float* __restrict__ A, int lda, const float* __restrict__ B, int ldb,
    int K, int brow, int bcol, int Mlim, int tid, float (&acc)[2][4][4],
    float (*sA)[16][SAS], float (*sB)[16][SBS]) {

    const int lane = tid & 31;
    const int wid  = tid >> 5;
    const int wm = (wid & 3) * 32;
    const int wn = (wid >> 2) * 32;
    const int grp = lane >> 2, thr = lane & 3;

    const int ar0 = tid >> 2, akq = (tid & 3) * 4;
    const int ar1 = ar0 + 64;
    const int bkr = tid >> 4, bcq = (tid & 15) * 4;

    float4 pA0, pA1, pB;

#define LOAD_TILE64(k0)                                                        \
    do {                                                                       \
        pA0 = make_float4(0.f, 0.f, 0.f, 0.f);                                 \
        pA1 = make_float4(0.f, 0.f, 0.f, 0.f);                                 \
        pB  = make_float4(0.f, 0.f, 0.f, 0.f);                                 \
        if (brow + ar0 < NN) {                                                 \
            const float* ap = A + (size_t)(brow + ar0) * lda + (k0) + akq;     \
            if ((k0) + akq + 3 < K) pA0 = *(const float4*)ap;                  \
            else {                                                             \
                if ((k0) + akq + 0 < K) pA0.x = ap[0];                         \
                if ((k0) + akq + 1 < K) pA0.y = ap[1];                         \
                if ((k0) + akq + 2 < K) pA0.z = ap[2];                         \
                if ((k0) + akq + 3 < K) pA0.w = ap[3];                         \
            }                                                                  \
        }                                                                      \
        if (brow + ar1 < NN) {                                                 \
            const float* ap = A + (size_t)(brow + ar1) * lda + (k0) + akq;     \
            if ((k0) + akq + 3 < K) pA1 = *(const float4*)ap;                  \
            else {                                                             \
                if ((k0) + akq + 0 < K) pA1.x = ap[0];                         \
                if ((k0) + akq + 1 < K) pA1.y = ap[1];                         \
                if ((k0) + akq + 2 < K) pA1.z = ap[2];                         \
                if ((k0) + akq + 3 < K) pA1.w = ap[3];                         \
            }                                                                  \
        }                                                                      \
        if ((k0) + bkr < K) {                                                  \
            const float* bp = B + (size_t)((k0) + bkr) * ldb + bcol + bcq;     \
            if (bcol + bcq + 3 < Mlim) pB = *(const float4*)bp;                \
            else {                                                             \
                if (bcol + bcq + 0 < Mlim) pB.x = bp[0];                       \
                if (bcol + bcq + 1 < Mlim) pB.y = bp[1];                       \
                if (bcol + bcq + 2 < Mlim) pB.z = bp[2];                       \
                if (bcol + bcq + 3 < Mlim) pB.w = bp[3];                       \
            }                                                                  \
        }                                                                      \
    } while (0)

#define STORE_TILE64(buf)                                                      \
    do {                                                                       \
        sA[buf][akq + 0][ar0] = f2tf(pA0.x);                                   \
        sA[buf][akq + 1][ar0] = f2tf(pA0.y);                                   \
        sA[buf][akq + 2][ar0] = f2tf(pA0.z);                                   \
        sA[buf][akq + 3][ar0] = f2tf(pA0.w);                                   \
        sA[buf][akq + 0][ar1] = f2tf(pA1.x);                                   \
        sA[buf][akq + 1][ar1] = f2tf(pA1.y);                                   \
        sA[buf][akq + 2][ar1] = f2tf(pA1.z);                                   \
        sA[buf][akq + 3][ar1] = f2tf(pA1.w);                                   \
        sB[buf][bkr][bcq + 0] = f2tf(pB.x);                                    \
        sB[buf][bkr][bcq + 1] = f2tf(pB.y);                                    \
        sB[buf][bkr][bcq + 2] = f2tf(pB.z);                                    \
        sB[buf][bkr][bcq + 3] = f2tf(pB.w);                                    \
    } while (0)

    LOAD_TILE64(0);
    STORE_TILE64(0);
    __syncthreads();
    int buf = 0;

    for (int k0 = 0; k0 < K; k0 += 16) {
        int nk = k0 + 16;
        if (nk < K) LOAD_TILE64(nk);
#pragma unroll
        for (int ks = 0; ks < 2; ks++) {
            int kb = ks * 8;
            uint32_t af[2][4], bf[4][2];
#pragma unroll
            for (int mt = 0; mt < 2; mt++) {
                int r = wm + mt * 16 + grp;
                af[mt][0] = __float_as_uint(sA[buf][kb + thr][r]);
                af[mt][1] = __float_as_uint(sA[buf][kb + thr][r + 8]);
                af[mt][2] = __float_as_uint(sA[buf][kb + 4 + thr][r]);
                af[mt][3] = __float_as_uint(sA[buf][kb + 4 + thr][r + 8]);
            }
#pragma unroll
            for (int nt = 0; nt < 4; nt++) {
                int c = wn + nt * 8 + grp;
                bf[nt][0] = __float_as_uint(sB[buf][kb + thr][c]);
                bf[nt][1] = __float_as_uint(sB[buf][kb + 4 + thr][c]);
            }
#pragma unroll
            for (int mt = 0; mt < 2; mt++)
#pragma unroll
                for (int nt = 0; nt < 4; nt++)
                    mma_tf32(acc[mt][nt], af[mt][0], af[mt][1], af[mt][2], af[mt][3],
                             bf[nt][0], bf[nt][1]);
        }
        if (nk < K) {
            STORE_TILE64(buf ^ 1);
            __syncthreads();
            buf ^= 1;
        }
    }
    __syncthreads();
#undef LOAD_TILE64
#undef STORE_TILE64
}

// ===== narrow GEMM (plain): C = A @ B =====
__global__ void __launch_bounds__(256)
k_gemm(GP2 p) {
    GP g = p.g[blockIdx.z];
    const int bcol = blockIdx.x * 64;
    if (bcol >= g.M) return;
    __shared__ float sA[2][16][SAS];
    __shared__ float sB[2][16][SBS];
    const int tid = threadIdx.x;
    const int brow = blockIdx.y * 128;

    float acc[2][4][4] = {};
    gemm_phase64(g.A, g.lda, g.B, g.ldb, g.K, brow, bcol, g.M, tid, acc, sA, sB);

    const int lane = tid & 31;
    const int wid  = tid >> 5;
    const int wm = (wid & 3) * 32;
    const int wn = (wid >> 2) * 32;
    const int grp = lane >> 2, thr = lane & 3;

#pragma unroll
    for (int mt = 0; mt < 2; mt++)
#pragma unroll
        for (int nt = 0; nt < 4; nt++)
#pragma unroll
            for (int e = 0; e < 4; e++) {
                int r = brow + wm + mt * 16 + grp + (e >= 2 ? 8 : 0);
                int c = bcol + wn + nt * 8 + 2 * thr + (e & 1);
                if (r < NN && c < g.M)
                    g.C[(size_t)r * g.ldc + c] = acc[mt][nt][e];
            }
}

// ===== dual GEMM + combine =====
__global__ void __launch_bounds__(256)
k_gemmD(GD2 p, const float* __restrict__ id) {
    GD d = p.d[blockIdx.z];
    __shared__ float sA[2][16][SAS];
    __shared__ float sB[2][16][SBS];
    const int tid = threadIdx.x;
    const int brow = blockIdx.y * 128;

    float acc1[2][4][4] = {};
    float acc2[2][4][4] = {};
    gemm_phase64(d.x, d.ldx, d.l, DX, d.K, brow, 0, DX, tid, acc1, sA, sB);
    gemm_phase64(d.h, d.ldx, d.g, DX, d.K, brow, 0, DX, tid, acc2, sA, sB);

    const int lane = tid & 31;
    const int wid  = tid >> 5;
    const int wm = (wid & 3) * 32;
    const int wn = (wid >> 2) * 32;
    const int grp = lane >> 2, thr = lane & 3;

#pragma unroll
    for (int mt = 0; mt < 2; mt++)
#pragma unroll
        for (int nt = 0; nt < 4; nt++)
#pragma unroll
            for (int e = 0; e < 4; e++) {
                int r = brow + wm + mt * 16 + grp + (e >= 2 ? 8 : 0);
                int c = wn + nt * 8 + 2 * thr + (e & 1);
                if (r >= NN) continue;
                size_t lin = (size_t)r * 64 + c;
                float xh = acc1[mt][nt][e] + d.lb[c];
                xh = (xh > 0.f) ? xh : 0.01f * xh;
                xh += id[lin];
                float o = acc2[mt][nt][e] + d.gb[c] + xh;
                d.C[lin] = (o > 0.f) ? o : 0.01f * o;
            }
}

// ---------------- tanh + l2norm ----------------
__global__ void __launch_bounds__(256)
k_tanh2(float* __restrict__ xv, const float* __restrict__ bv,
        float* __restrict__ xt, const float* __restrict__ bt) {
    int w = (blockIdx.x * blockDim.x + threadIdx.x) >> 5;
    int lane = threadIdx.x & 31;
    if (w >= 2 * NN) return;
    float* row;
    const float* b;
    int dim;
    if (w < NN) { row = xv + (size_t)w * LV; b = bv; dim = LV; }
    else        { row = xt + (size_t)(w - NN) * LT; b = bt; dim = LT; }
    float v[8];
    float ss = 0.f;
#pragma unroll
    for (int j = 0; j < 8; j++) {
        v[j] = 0.f;
        int c = lane + 32 * j;
        if (c < dim) {
            float t = tanhf(row[c] + b[c]);
            v[j] = t;
            ss += t * t;
        }
    }
#pragma unroll
    for (int o = 16; o; o >>= 1) ss += __shfl_xor_sync(~0u, ss, o);
    float sc = 1.f / fmaxf(sqrtf(ss), 1e-12f);
#pragma unroll
    for (int j = 0; j < 8; j++) {
        int c = lane + 32 * j;
        if (c < dim) row[c] = v[j] * sc;
    }
}

// ---------------- vector helpers ----------------
template <int VEC>
__device__ __forceinline__ void ldrow(const float* __restrict__ p, float* v) {
    if (VEC == 8) {
        float4 a = *(const float4*)p;
        float4 b = *(const float4*)(p + 4);
        v[0] = a.x; v[1] = a.y; v[2] = a.z; v[3] = a.w;
        v[4] = b.x; v[5] = b.y; v[6] = b.z; v[7] = b.w;
    } else if (VEC == 4) {
        float4 a = *(const float4*)p;
        v[0] = a.x; v[1] = a.y; v[2] = a.z; v[3] = a.w;
    } else {
        float2 a = *(const float2*)p;
        v[0] = a.x; v[1] = a.y;
    }
}

template <int VEC>
__device__ __forceinline__ void strow(float* __restrict__ p, const float* v) {
    if (VEC == 8) {
        *(float4*)p       = make_float4(v[0], v[1], v[2], v[3]);
        *(float4*)(p + 4) = make_float4(v[4], v[5], v[6], v[7]);
    } else if (VEC == 4) {
        *(float4*)p = make_float4(v[0], v[1], v[2], v[3]);
    } else {
        *(float2*)p = make_float2(v[0], v[1]);
    }
}

// ---------------- GAT: single pass, NO max subtraction ----------------
// Softmax is shift-invariant; logits are O(1)-O(10) here so exp() is safe in
// fp32 without the segment-max shift. Zero-degree nodes degenerate identically
// (denom=0 -> attn=0 -> out = l2norm(bias)).
template <int VEC>
__device__ __forceinline__ void gat_node(const float* __restrict__ hc, int dim,
                                         const int2* __restrict__ esd, int b0, int b1,
                                         const float* __restrict__ bias,
                                         float* __restrict__ out, int n, int lane) {
    int c0 = lane * VEC;
    bool valid = c0 < dim;
    float hd[VEC];
#pragma unroll
    for (int j = 0; j < VEC; j++) hd[j] = 0.f;
    if (valid) ldrow<VEC>(hc + (size_t)n * dim + c0, hd);

    float denom = 0.f;
    float acc[VEC];
#pragma unroll
    for (int j = 0; j < VEC; j++) acc[j] = 0.f;

    int p = b0;
    for (; p + 3 < b1; p += 4) {
        int2 e[4];
        float v[4][VEC];
        float pd[4];
#pragma unroll
        for (int q = 0; q < 4; q++) e[q] = esd[p + q];
#pragma unroll
        for (int q = 0; q < 4; q++) {
#pragma unroll
            for (int j = 0; j < VEC; j++) v[q][j] = 0.f;
            if (valid) ldrow<VEC>(hc + (size_t)e[q].x * dim + c0, v[q]);
        }
        // 4 partial dots
#pragma unroll
        for (int q = 0; q < 4; q++) {
            float d = 0.f;
#pragma unroll
            for (int j = 0; j < VEC; j++) {
                float lr = (v[q][j] > 0.f) ? v[q][j] : 0.01f * v[q][j];
                d += hd[j] * lr;
            }
            pd[q] = d;
        }
        // 4 interleaved shfl reduction trees (independent -> ILP)
#pragma unroll
        for (int o = 16; o; o >>= 1) {
#pragma unroll
            for (int q = 0; q < 4; q++)
                pd[q] += __shfl_xor_sync(~0u, pd[q], o);
        }
        // cheap scalar updates (no branch, no rescale)
#pragma unroll
        for (int q = 0; q < 4; q++) {
            float d = pd[q];
            float t = d * __int_as_float(e[q].y);
            float gate = 1.f / (1.f + __expf(-t));
            float w = __expf(d * gate);
            denom += w;
#pragma unroll
            for (int j = 0; j < VEC; j++) acc[j] += w * v[q][j];
        }
    }
    for (; p < b1; p++) {
        int2 e = esd[p];
        float v[VEC];
#pragma unroll
        for (int j = 0; j < VEC; j++) v[j] = 0.f;
        if (valid) ldrow<VEC>(hc + (size_t)e.x * dim + c0, v);
        float d = 0.f;
#pragma unroll
        for (int j = 0; j < VEC; j++) {
            float lr = (v[j] > 0.f) ? v[j] : 0.01f * v[j];
            d += hd[j] * lr;
        }
#pragma unroll
        for (int o = 16; o; o >>= 1) d += __shfl_xor_sync(~0u, d, o);
        float t = d * __int_as_float(e.y);
        float gate = 1.f / (1.f + __expf(-t));
        float w = __expf(d * gate);
        denom += w;
#pragma unroll
        for (int j = 0; j < VEC; j++) acc[j] += w * v[j];
    }

    float inv = 1.f / (denom + 1e-16f);
    float val[VEC];
    float ss = 0.f;
#pragma unroll
    for (int j = 0; j < VEC; j++) {
        val[j] = 0.f;
        if (valid) {
            float v = acc[j] * inv + bias[c0 + j];
            val[j] = v;
            ss += v * v;
        }
    }
#pragma unroll
    for (int o = 16; o; o >>= 1) ss += __shfl_xor_sync(~0u, ss, o);
    float sc = 1.f / fmaxf(sqrtf(ss), 1e-12f);
    if (valid) {
        float res[VEC];
#pragma unroll
        for (int j = 0; j < VEC; j++) {
            float v = val[j] * sc;
            res[j] = (v > 0.f) ? v : 0.01f * v;
        }
        strow<VEC>(out + (size_t)n * dim + c0, res);
    }
}

__global__ void __launch_bounds__(128)
k_gat1(const float* __restrict__ hcv, const float* __restrict__ hct,
       const int2* __restrict__ esd, const int* __restrict__ off,
       const float* __restrict__ bv, const float* __restrict__ bt,
       float* __restrict__ ov, float* __restrict__ ot) {
    int w = (blockIdx.x * blockDim.x + threadIdx.x) >> 5;
    int lane = threadIdx.x & 31;
    if (w >= 2 * NN) return;
    if (w < NN) {
        gat_node<8>(hcv, LV, esd, off[w], off[w + 1], bv, ov, w, lane);
    } else {
        int n = w - NN;
        gat_node<4>(hct, LT, esd, off[n], off[n + 1], bt, ot, n, lane);
    }
}

__global__ void __launch_bounds__(128)
k_gat2(const float* __restrict__ hcv, const float* __restrict__ hct,
       const int2* __restrict__ esd, const int* __restrict__ off,
       const float* __restrict__ bv, const float* __restrict__ bt,
       float* __restrict__ ov, float* __restrict__ ot) {
    int w = (blockIdx.x * blockDim.x + threadIdx.x) >> 5;
    int lane = threadIdx.x & 31;
    if (w >= 2 * NN) return;
    if (w < NN) {
        gat_node<2>(hcv, DX, esd, off[w], off[w + 1], bv, ov, w, lane);
    } else {
        int n = w - NN;
        gat_node<2>(hct, DX, esd, off[n], off[n + 1], bt, ot, n, lane);
    }
}

// output: [representation | v_rep | t_rep]
__global__ void __launch_bounds__(256)
k_final(const float* __restrict__ vx1, const float* __restrict__ vx2,
        const float* __restrict__ tx1, const float* __restrict__ tx2,
        float* __restrict__ out, int out_size) {
    int i = blockIdx.x * blockDim.x + threadIdx.x;
    if (i >= NN * DX) return;
    int n = i >> 6, c = i & 63;
    float a1 = vx1[i], a2 = vx2[i], b1 = tx1[i], b2 = tx2[i];
    size_t base = (size_t)n * 128;
    out[base + c]      = (a1 + b1) * 0.5f;
    out[base + 64 + c] = (a2 + b2) * 0.5f;
    if (out_size >= 2 * NN * 128) {
        out[(size_t)NN * 128 + base + c]      = a1;
        out[(size_t)NN * 128 + base + 64 + c] = a2;
    }
    if (out_size >= 3 * NN * 128) {
        out[(size_t)2 * NN * 128 + base + c]      = b1;
        out[(size_t)2 * NN * 128 + base + 64 + c] = b2;
    }
}

// ---------------- host side ----------------
extern "C" void kernel_launch(void* const* d_in, const int* in_sizes, int n_in,
                              void* d_out, int out_size) {
    (void)in_sizes;
    (void)n_in;
    static float* F = nullptr;
    static int*   I = nullptr;
    if (!F) {
        cudaGetSymbolAddress((void**)&F, g_farena);
        cudaGetSymbolAddress((void**)&I, g_iarena);
    }

    float* x_v  = F;
    float* hc_v = F + 7680000;
    float* h_v  = F + 15360000;
    float* x_t  = F + 23040000;
    float* hc_t = F + 26040000;
    float* h_t  = F + 29040000;
    float* vx1  = F + 35880000;
    float* vx2  = F + 37800000;
    float* tx1  = F + 39720000;
    float* tx2  = F + 41640000;
    float* dinv = F + 43560000;

    int*  src  = I;
    int*  dst  = I + NE;
    int*  esrc = I + 2 * NE;
    int2* esd  = (int2*)(I + 3 * NE);
    int*  cnt  = I + 5 * NE;
    int*  degs = cnt + (NN + 1);
    int*  off  = degs + NN;
    int*  cur  = off + (NN + 1);
    int*  is64 = cur + NN;

    const float* feat  = (const float*)d_in[0];
    const void*  ei    = d_in[1];
    const float* idemb = (const float*)d_in[2];
    void* const* PV = d_in + 3;
    void* const* PT = d_in + 17;

#define PW(P, i) ((const float*)P[i])

    dim3 blk(256);
    int gy = (NN + 127) / 128;
    int warp2_grid = (2 * NN * 32 + 255) / 256;
    int gat_grid = (2 * NN * 32 + 127) / 128;

    k_init<<<(2 * NN + 256) / 256, 256>>>(ei, cnt, 2 * NN + 1, is64);
    k_convert_hist<<<(NE + 255) / 256, 256>>>(ei, src, dst, cnt, degs, is64);

    // S1: mlp GEMM (wide)
    {
        GP2 p = {{
            {feat, PW(PV, 0), x_v, FDIM, LV, LV, 128, LV},
            {feat + 128, PW(PT, 0), x_t, FDIM, LT, LT, 64, LT}}};
        k_gemmW<<<dim3(2, gy, 2), blk>>>(p);
    }
    // S2: tanh + l2norm
    k_tanh2<<<warp2_grid, 256>>>(x_v, PW(PV, 1), x_t, PW(PT, 1));
    // S3: c1 GEMM (wide)
    {
        GP2 p = {{
            {x_v, PW(PV, 2), hc_v, LV, LV, LV, LV, LV},
            {x_t, PW(PT, 2), hc_t, LT, LT, LT, LT, LT}}};
        k_gemmW<<<dim3(2, gy, 2), blk>>>(p);
    }

    // graph build tail
    k_scan<<<1, 1024>>>(cnt, off, cur, degs, dinv);
    k_fill<<<(NE + 255) / 256, 256>>>(src, dst, cur, esrc);
    k_sortseg<<<(NN + 255) / 256, 256>>>(off, esrc, dinv, esd);

    // S4: GAT layer 1
    k_gat1<<<gat_grid, 128>>>(hc_v, hc_t, esd, off, PW(PV, 3), PW(PT, 3), h_v, h_t);

    // S5: fused l1+g1 GEMMs + combine -> x1
    {
        GD2 p = {{
            {x_v, PW(PV, 4), h_v, PW(PV, 6), PW(PV, 5), PW(PV, 7), vx1, LV, LV},
            {x_t, PW(PT, 4), h_t, PW(PT, 6), PW(PT, 5), PW(PT, 7), tx1, LT, LT}}};
        k_gemmD<<<dim3(1, gy, 2), blk>>>(p, idemb);
    }
    // S6: c2 GEMM
    {
        GP2 p = {{
            {vx1, PW(PV, 8), hc_v, DX, DX, DX, DX, DX},
            {tx1, PW(PT, 8), hc_t, DX, DX, DX, DX, DX}}};
        k_gemm<<<dim3(1, gy, 2), blk>>>(p);
    }
    // S7: GAT layer 2
    k_gat2<<<gat_grid, 128>>>(hc_v, hc_t, esd, off, PW(PV, 9), PW(PT, 9), h_v, h_t);

    // S8: fused l2+g2 GEMMs + combine -> x2
    {
        GD2 p = {{
            {vx1, PW(PV, 10), h_v, PW(PV, 12), PW(PV, 11), PW(PV, 13), vx2, DX, DX},
            {tx1, PW(PT, 10), h_t, PW(PT, 12), PW(PT, 11), PW(PT, 13), tx2, DX, DX}}};
        k_gemmD<<<dim3(1, gy, 2), blk>>>(p, idemb);
    }

    k_final<<<(NN * DX + 255) / 256, 256>>>(vx1, vx2, tx1, tx2, (float*)d_out, out_size);
#undef PW
}

// round 13
// speedup vs baseline: 1.4309x; 1.0413x over previous
#include <cuda_runtime.h>
#include <math.h>
#include <stdint.h>

#define NN 30000
#define NE 480000
#define FDIM 192
#define DX 64
#define LV 256
#define LT 100

// ---------------- scratch arenas ----------------
__device__ float g_farena[44000000];
__device__ int   g_iarena[2700000];

// ---------------- graph build ----------------
__global__ void k_init(const void* ei, int* a, int n, int* is64) {
    int i = blockIdx.x * blockDim.x + threadIdx.x;
    if (i < n) a[i] = 0;
    if (blockIdx.x == 0 && threadIdx.x == 0) {
        const int* p = (const int*)ei;
        int zeros = 0;
#pragma unroll 8
        for (int j = 1; j < 256; j += 2) if (p[j] == 0) zeros++;
        *is64 = (zeros >= 120) ? 1 : 0;
    }
}

__global__ void k_convert_hist(const void* ei, int* src, int* dst,
                               int* cnt, int* degs, const int* is64) {
    int e = blockIdx.x * blockDim.x + threadIdx.x;
    if (e >= NE) return;
    int s, d;
    if (*is64) {
        const long long* p = (const long long*)ei;
        s = (int)p[e];
        d = (int)p[NE + e];
    } else {
        const int* p = (const int*)ei;
        s = p[e];
        d = p[NE + e];
    }
    src[e] = s;
    dst[e] = d;
    atomicAdd(&cnt[d], 1);
    atomicAdd(&degs[s], 1);
}

__global__ void __launch_bounds__(1024)
k_scan(const int* __restrict__ cnt, int* __restrict__ off, int* __restrict__ cur,
       const int* __restrict__ degs, float* __restrict__ dinv) {
    const int CH = 30;
    int t = threadIdx.x;
    int base = t * CH;
    int s = 0;
#pragma unroll 5
    for (int i = 0; i < CH; i++) {
        int idx = base + i;
        if (idx < NN) s += cnt[idx];
    }
    int lane = t & 31, wid = t >> 5;
    int v = s;
#pragma unroll
    for (int o = 1; o < 32; o <<= 1) {
        int u = __shfl_up_sync(~0u, v, o);
        if (lane >= o) v += u;
    }
    __shared__ int wt[32];
    if (lane == 31) wt[wid] = v;
    __syncthreads();
    if (wid == 0) {
        int w = wt[lane];
#pragma unroll
        for (int o = 1; o < 32; o <<= 1) {
            int u = __shfl_up_sync(~0u, w, o);
            if (lane >= o) w += u;
        }
        wt[lane] = w;
    }
    __syncthreads();
    int pre = v - s + (wid ? wt[wid - 1] : 0);
    int run = pre;
#pragma unroll 5
    for (int i = 0; i < CH; i++) {
        int idx = base + i;
        if (idx < NN) {
            off[idx] = run;
            cur[idx] = run;
            int dg = degs[idx];
            dinv[idx] = (dg > 0) ? rsqrtf((float)dg) : 0.f;
            run += cnt[idx];
        }
    }
    if (t == 1023) off[NN] = run;
}

__global__ void k_fill(const int* src, const int* dst, int* cur, int* esrc) {
    int e = blockIdx.x * blockDim.x + threadIdx.x;
    if (e >= NE) return;
    int p = atomicAdd(&cur[dst[e]], 1);
    esrc[p] = src[e];
}

__global__ void k_sortseg(const int* __restrict__ off, int* __restrict__ esrc,
                          const float* __restrict__ dinv, int2* __restrict__ esd) {
    int n = blockIdx.x * blockDim.x + threadIdx.x;
    if (n >= NN) return;
    int b = off[n], e = off[n + 1];
    for (int i = b + 1; i < e; i++) {
        int v = esrc[i];
        int j = i - 1;
        while (j >= b && esrc[j] > v) { esrc[j + 1] = esrc[j]; j--; }
        esrc[j + 1] = v;
    }
    for (int p = b; p < e; p++) {
        int s = esrc[p];
        esd[p] = make_int2(s, __float_as_int(dinv[s]));
    }
}

// ---------------- TF32 tensor-core GEMM ----------------
struct GP {
    const float* A;
    const float* B;
    float* C;
    int lda, ldb, ldc, K, M;
};
struct GP2 { GP g[2]; };

struct GD {
    const float* x;
    const float* l;
    const float* h;
    const float* g;
    const float* lb;
    const float* gb;
    float* C;
    int ldx, K;
};
struct GD2 { GD d[2]; };

__device__ __forceinline__ float f2tf(float x) {
    uint32_t u;
    asm("cvt.rna.tf32.f32 %0, %1;" : "=r"(u) : "f"(x));
    return __uint_as_float(u);
}

__device__ __forceinline__ void mma_tf32(float* c,
                                         uint32_t a0, uint32_t a1, uint32_t a2, uint32_t a3,
                                         uint32_t b0, uint32_t b1) {
    asm volatile(
        "mma.sync.aligned.m16n8k8.row.col.f32.tf32.tf32.f32 "
        "{%0,%1,%2,%3}, {%4,%5,%6,%7}, {%8,%9}, {%0,%1,%2,%3};\n"
        : "+f"(c[0]), "+f"(c[1]), "+f"(c[2]), "+f"(c[3])
        : "r"(a0), "r"(a1), "r"(a2), "r"(a3), "r"(b0), "r"(b1));
}

#define SAS 136
#define SBS 72
#define SWS 136

// ===== wide GEMM: BM=128, BN=128, 256 thr = 4m x 2n warps, warp 32x64 =====
__global__ void __launch_bounds__(256)
k_gemmW(GP2 p) {
    GP g = p.g[blockIdx.z];
    const int bcol = blockIdx.x * 128;
    if (bcol >= g.M) return;
    __shared__ float sA[2][16][SAS];
    __shared__ float sB[2][16][SWS];
    const int tid = threadIdx.x;
    const int brow = blockIdx.y * 128;
    const int K = g.K, M = g.M;

    const int lane = tid & 31;
    const int wid  = tid >> 5;
    const int wm = (wid & 3) * 32;
    const int wn = (wid >> 2) * 64;
    const int grp = lane >> 2, thr = lane & 3;

    const int ar0 = tid >> 2, akq = (tid & 3) * 4;
    const int ar1 = ar0 + 64;
    const int br0 = tid >> 5, bc4 = (tid & 31) * 4;
    const int br1 = br0 + 8;

    float4 pA0, pA1, pB0, pB1;

#define LD_A(dst, row, k0)                                                     \
    do {                                                                       \
        dst = make_float4(0.f, 0.f, 0.f, 0.f);                                 \
        if (brow + (row) < NN) {                                               \
            const float* ap = g.A + (size_t)(brow + (row)) * g.lda + (k0) + akq;\
            if ((k0) + akq + 3 < K) dst = *(const float4*)ap;                  \
            else {                                                             \
                if ((k0) + akq + 0 < K) dst.x = ap[0];                         \
                if ((k0) + akq + 1 < K) dst.y = ap[1];                         \
                if ((k0) + akq + 2 < K) dst.z = ap[2];                         \
                if ((k0) + akq + 3 < K) dst.w = ap[3];                         \
            }                                                                  \
        }                                                                      \
    } while (0)

#define LD_B(dst, row, k0)                                                     \
    do {                                                                       \
        dst = make_float4(0.f, 0.f, 0.f, 0.f);                                 \
        if ((k0) + (row) < K) {                                                \
            const float* bp = g.B + (size_t)((k0) + (row)) * g.ldb + bcol + bc4;\
            if (bcol + bc4 + 3 < M) dst = *(const float4*)bp;                  \
            else {                                                             \
                if (bcol + bc4 + 0 < M) dst.x = bp[0];                         \
                if (bcol + bc4 + 1 < M) dst.y = bp[1];                         \
                if (bcol + bc4 + 2 < M) dst.z = bp[2];                         \
                if (bcol + bc4 + 3 < M) dst.w = bp[3];                         \
            }                                                                  \
        }                                                                      \
    } while (0)

#define LOAD_TILE(k0) do { LD_A(pA0, ar0, k0); LD_A(pA1, ar1, k0);             \
                           LD_B(pB0, br0, k0); LD_B(pB1, br1, k0); } while (0)

#define STORE_TILE(buf)                                                        \
    do {                                                                       \
        sA[buf][akq + 0][ar0] = f2tf(pA0.x);                                   \
        sA[buf][akq + 1][ar0] = f2tf(pA0.y);                                   \
        sA[buf][akq + 2][ar0] = f2tf(pA0.z);                                   \
        sA[buf][akq + 3][ar0] = f2tf(pA0.w);                                   \
        sA[buf][akq + 0][ar1] = f2tf(pA1.x);                                   \
        sA[buf][akq + 1][ar1] = f2tf(pA1.y);                                   \
        sA[buf][akq + 2][ar1] = f2tf(pA1.z);                                   \
        sA[buf][akq + 3][ar1] = f2tf(pA1.w);                                   \
        sB[buf][br0][bc4 + 0] = f2tf(pB0.x);                                   \
        sB[buf][br0][bc4 + 1] = f2tf(pB0.y);                                   \
        sB[buf][br0][bc4 + 2] = f2tf(pB0.z);                                   \
        sB[buf][br0][bc4 + 3] = f2tf(pB0.w);                                   \
        sB[buf][br1][bc4 + 0] = f2tf(pB1.x);                                   \
        sB[buf][br1][bc4 + 1] = f2tf(pB1.y);                                   \
        sB[buf][br1][bc4 + 2] = f2tf(pB1.z);                                   \
        sB[buf][br1][bc4 + 3] = f2tf(pB1.w);                                   \
    } while (0)

    float acc[2][8][4] = {};
    LOAD_TILE(0);
    STORE_TILE(0);
    __syncthreads();
    int buf = 0;

    for (int k0 = 0; k0 < K; k0 += 16) {
        int nk = k0 + 16;
        if (nk < K) LOAD_TILE(nk);
#pragma unroll
        for (int ks = 0; ks < 2; ks++) {
            int kb = ks * 8;
            uint32_t af[2][4], bf[8][2];
#pragma unroll
            for (int mt = 0; mt < 2; mt++) {
                int r = wm + mt * 16 + grp;
                af[mt][0] = __float_as_uint(sA[buf][kb + thr][r]);
                af[mt][1] = __float_as_uint(sA[buf][kb + thr][r + 8]);
                af[mt][2] = __float_as_uint(sA[buf][kb + 4 + thr][r]);
                af[mt][3] = __float_as_uint(sA[buf][kb + 4 + thr][r + 8]);
            }
#pragma unroll
            for (int nt = 0; nt < 8; nt++) {
                int c = wn + nt * 8 + grp;
                bf[nt][0] = __float_as_uint(sB[buf][kb + thr][c]);
                bf[nt][1] = __float_as_uint(sB[buf][kb + 4 + thr][c]);
            }
#pragma unroll
            for (int mt = 0; mt < 2; mt++)
#pragma unroll
                for (int nt = 0; nt < 8; nt++)
                    mma_tf32(acc[mt][nt], af[mt][0], af[mt][1], af[mt][2], af[mt][3],
                             bf[nt][0], bf[nt][1]);
        }
        if (nk < K) {
            STORE_TILE(buf ^ 1);
            __syncthreads();
            buf ^= 1;
        }
    }
#undef LOAD_TILE
#undef STORE_TILE
#undef LD_A
#undef LD_B

#pragma unroll
    for (int mt = 0; mt < 2; mt++) {
#pragma unroll
        for (int nt = 0; nt < 8; nt++) {
#pragma unroll
            for (int e = 0; e < 4; e++) {
                int r = brow + wm + mt * 16 + grp + (e >= 2 ? 8 : 0);
                int c = bcol + wn + nt * 8 + 2 * thr + (e & 1);
                if (r < NN && c < M)
                    g.C[(size_t)r * g.ldc + c] = acc[mt][nt][e];
            }
        }
    }
}

// ===== shared phase for narrow/dual kernels =====
__device__ __forceinline__ void gemm_phase64(
    const float* __restrict__ A, int lda, const float* __restrict__ B, int ldb,
    int K, int brow, int bcol, int Mlim, int tid, float (&acc)[2][4][4],
    float (*sA)[16][SAS], float (*sB)[16][SBS]) {

    const int lane = tid & 31;
    const int wid  = tid >> 5;
    const int wm = (wid & 3) * 32;
    const int wn = (wid >> 2) * 32;
    const int grp = lane >> 2, thr = lane & 3;

    const int ar0 = tid >> 2, akq = (tid & 3) * 4;
    const int ar1 = ar0 + 64;
    const int bkr = tid >> 4, bcq = (tid & 15) * 4;

    float4 pA0, pA1, pB;

#define LOAD_TILE64(k0)                                                        \
    do {                                                                       \
        pA0 = make_float4(0.f, 0.f, 0.f, 0.f);                                 \
        pA1 = make_float4(0.f, 0.f, 0.f, 0.f);                                 \
        pB  = make_float4(0.f, 0.f, 0.f, 0.f);                                 \
        if (brow + ar0 < NN) {                                                 \
            const float* ap = A + (size_t)(brow + ar0) * lda + (k0) + akq;     \
            if ((k0) + akq + 3 < K) pA0 = *(const float4*)ap;                  \
            else {                                                             \
                if ((k0) + akq + 0 < K) pA0.x = ap[0];                         \
                if ((k0) + akq + 1 < K) pA0.y = ap[1];                         \
                if ((k0) + akq + 2 < K) pA0.z = ap[2];                         \
                if ((k0) + akq + 3 < K) pA0.w = ap[3];                         \
            }                                                                  \
        }                                                                      \
        if (brow + ar1 < NN) {                                                 \
            const float* ap = A + (size_t)(brow + ar1) * lda + (k0) + akq;     \
            if ((k0) + akq + 3 < K) pA1 = *(const float4*)ap;                  \
            else {                                                             \
                if ((k0) + akq + 0 < K) pA1.x = ap[0];                         \
                if ((k0) + akq + 1 < K) pA1.y = ap[1];                         \
                if ((k0) + akq + 2 < K) pA1.z = ap[2];                         \
                if ((k0) + akq + 3 < K) pA1.w = ap[3];                         \
            }                                                                  \
        }                                                                      \
        if ((k0) + bkr < K) {                                                  \
            const float* bp = B + (size_t)((k0) + bkr) * ldb + bcol + bcq;     \
            if (bcol + bcq + 3 < Mlim) pB = *(const float4*)bp;                \
            else {                                                             \
                if (bcol + bcq + 0 < Mlim) pB.x = bp[0];                       \
                if (bcol + bcq + 1 < Mlim) pB.y = bp[1];                       \
                if (bcol + bcq + 2 < Mlim) pB.z = bp[2];                       \
                if (bcol + bcq + 3 < Mlim) pB.w = bp[3];                       \
            }                                                                  \
        }                                                                      \
    } while (0)

#define STORE_TILE64(buf)                                                      \
    do {                                                                       \
        sA[buf][akq + 0][ar0] = f2tf(pA0.x);                                   \
        sA[buf][akq + 1][ar0] = f2tf(pA0.y);                                   \
        sA[buf][akq + 2][ar0] = f2tf(pA0.z);                                   \
        sA[buf][akq + 3][ar0] = f2tf(pA0.w);                                   \
        sA[buf][akq + 0][ar1] = f2tf(pA1.x);                                   \
        sA[buf][akq + 1][ar1] = f2tf(pA1.y);                                   \
        sA[buf][akq + 2][ar1] = f2tf(pA1.z);                                   \
        sA[buf][akq + 3][ar1] = f2tf(pA1.w);                                   \
        sB[buf][bkr][bcq + 0] = f2tf(pB.x);                                    \
        sB[buf][bkr][bcq + 1] = f2tf(pB.y);                                    \
        sB[buf][bkr][bcq + 2] = f2tf(pB.z);                                    \
        sB[buf][bkr][bcq + 3] = f2tf(pB.w);                                    \
    } while (0)

    LOAD_TILE64(0);
    STORE_TILE64(0);
    __syncthreads();
    int buf = 0;

    for (int k0 = 0; k0 < K; k0 += 16) {
        int nk = k0 + 16;
        if (nk < K) LOAD_TILE64(nk);
#pragma unroll
        for (int ks = 0; ks < 2; ks++) {
            int kb = ks * 8;
            uint32_t af[2][4], bf[4][2];
#pragma unroll
            for (int mt = 0; mt < 2; mt++) {
                int r = wm + mt * 16 + grp;
                af[mt][0] = __float_as_uint(sA[buf][kb + thr][r]);
                af[mt][1] = __float_as_uint(sA[buf][kb + thr][r + 8]);
                af[mt][2] = __float_as_uint(sA[buf][kb + 4 + thr][r]);
                af[mt][3] = __float_as_uint(sA[buf][kb + 4 + thr][r + 8]);
            }
#pragma unroll
            for (int nt = 0; nt < 4; nt++) {
                int c = wn + nt * 8 + grp;
                bf[nt][0] = __float_as_uint(sB[buf][kb + thr][c]);
                bf[nt][1] = __float_as_uint(sB[buf][kb + 4 + thr][c]);
            }
#pragma unroll
            for (int mt = 0; mt < 2; mt++)
#pragma unroll
                for (int nt = 0; nt < 4; nt++)
                    mma_tf32(acc[mt][nt], af[mt][0], af[mt][1], af[mt][2], af[mt][3],
                             bf[nt][0], bf[nt][1]);
        }
        if (nk < K) {
            STORE_TILE64(buf ^ 1);
            __syncthreads();
            buf ^= 1;
        }
    }
    __syncthreads();
#undef LOAD_TILE64
#undef STORE_TILE64
}

// ===== narrow GEMM (plain): C = A @ B =====
__global__ void __launch_bounds__(256)
k_gemm(GP2 p) {
    GP g = p.g[blockIdx.z];
    const int bcol = blockIdx.x * 64;
    if (bcol >= g.M) return;
    __shared__ float sA[2][16][SAS];
    __shared__ float sB[2][16][SBS];
    const int tid = threadIdx.x;
    const int brow = blockIdx.y * 128;

    float acc[2][4][4] = {};
    gemm_phase64(g.A, g.lda, g.B, g.ldb, g.K, brow, bcol, g.M, tid, acc, sA, sB);

    const int lane = tid & 31;
    const int wid  = tid >> 5;
    const int wm = (wid & 3) * 32;
    const int wn = (wid >> 2) * 32;
    const int grp = lane >> 2, thr = lane & 3;

#pragma unroll
    for (int mt = 0; mt < 2; mt++)
#pragma unroll
        for (int nt = 0; nt < 4; nt++)
#pragma unroll
            for (int e = 0; e < 4; e++) {
                int r = brow + wm + mt * 16 + grp + (e >= 2 ? 8 : 0);
                int c = bcol + wn + nt * 8 + 2 * thr + (e & 1);
                if (r < NN && c < g.M)
                    g.C[(size_t)r * g.ldc + c] = acc[mt][nt][e];
            }
}

// ===== dual GEMM + combine =====
__global__ void __launch_bounds__(256)
k_gemmD(GD2 p, const float* __restrict__ id) {
    GD d = p.d[blockIdx.z];
    __shared__ float sA[2][16][SAS];
    __shared__ float sB[2][16][SBS];
    const int tid = threadIdx.x;
    const int brow = blockIdx.y * 128;

    float acc1[2][4][4] = {};
    float acc2[2][4][4] = {};
    gemm_phase64(d.x, d.ldx, d.l, DX, d.K, brow, 0, DX, tid, acc1, sA, sB);
    gemm_phase64(d.h, d.ldx, d.g, DX, d.K, brow, 0, DX, tid, acc2, sA, sB);

    const int lane = tid & 31;
    const int wid  = tid >> 5;
    const int wm = (wid & 3) * 32;
    const int wn = (wid >> 2) * 32;
    const int grp = lane >> 2, thr = lane & 3;

#pragma unroll
    for (int mt = 0; mt < 2; mt++)
#pragma unroll
        for (int nt = 0; nt < 4; nt++)
#pragma unroll
            for (int e = 0; e < 4; e++) {
                int r = brow + wm + mt * 16 + grp + (e >= 2 ? 8 : 0);
                int c = wn + nt * 8 + 2 * thr + (e & 1);
                if (r >= NN) continue;
                size_t lin = (size_t)r * 64 + c;
                float xh = acc1[mt][nt][e] + d.lb[c];
                xh = (xh > 0.f) ? xh : 0.01f * xh;
                xh += id[lin];
                float o = acc2[mt][nt][e] + d.gb[c] + xh;
                d.C[lin] = (o > 0.f) ? o : 0.01f * o;
            }
}

// ---------------- tanh + l2norm ----------------
__global__ void __launch_bounds__(256)
k_tanh2(float* __restrict__ xv, const float* __restrict__ bv,
        float* __restrict__ xt, const float* __restrict__ bt) {
    int w = (blockIdx.x * blockDim.x + threadIdx.x) >> 5;
    int lane = threadIdx.x & 31;
    if (w >= 2 * NN) return;
    float* row;
    const float* b;
    int dim;
    if (w < NN) { row = xv + (size_t)w * LV; b = bv; dim = LV; }
    else        { row = xt + (size_t)(w - NN) * LT; b = bt; dim = LT; }
    float v[8];
    float ss = 0.f;
#pragma unroll
    for (int j = 0; j < 8; j++) {
        v[j] = 0.f;
        int c = lane + 32 * j;
        if (c < dim) {
            float t = tanhf(row[c] + b[c]);
            v[j] = t;
            ss += t * t;
        }
    }
#pragma unroll
    for (int o = 16; o; o >>= 1) ss += __shfl_xor_sync(~0u, ss, o);
    float sc = 1.f / fmaxf(sqrtf(ss), 1e-12f);
#pragma unroll
    for (int j = 0; j < 8; j++) {
        int c = lane + 32 * j;
        if (c < dim) row[c] = v[j] * sc;
    }
}

// ---------------- vector helpers ----------------
template <int VEC>
__device__ __forceinline__ void ldrow(const float* __restrict__ p, float* v) {
    if (VEC == 8) {
        float4 a = *(const float4*)p;
        float4 b = *(const float4*)(p + 4);
        v[0] = a.x; v[1] = a.y; v[2] = a.z; v[3] = a.w;
        v[4] = b.x; v[5] = b.y; v[6] = b.z; v[7] = b.w;
    } else if (VEC == 4) {
        float4 a = *(const float4*)p;
        v[0] = a.x; v[1] = a.y; v[2] = a.z; v[3] = a.w;
    } else {
        float2 a = *(const float2*)p;
        v[0] = a.x; v[1] = a.y;
    }
}

template <int VEC>
__device__ __forceinline__ void strow(float* __restrict__ p, const float* v) {
    if (VEC == 8) {
        *(float4*)p       = make_float4(v[0], v[1], v[2], v[3]);
        *(float4*)(p + 4) = make_float4(v[4], v[5], v[6], v[7]);
    } else if (VEC == 4) {
        *(float4*)p = make_float4(v[0], v[1], v[2], v[3]);
    } else {
        *(float2*)p = make_float2(v[0], v[1]);
    }
}

// ---------------- GAT: single pass, no max subtraction ----------------
template <int VEC>
__device__ __forceinline__ void gat_node(const float* __restrict__ hc, int dim,
                                         const int2* __restrict__ esd, int b0, int b1,
                                         const float* __restrict__ bias,
                                         float* __restrict__ out, int n, int lane) {
    int c0 = lane * VEC;
    bool valid = c0 < dim;
    float hd[VEC];
#pragma unroll
    for (int j = 0; j < VEC; j++) hd[j] = 0.f;
    if (valid) ldrow<VEC>(hc + (size_t)n * dim + c0, hd);

    float denom = 0.f;
    float acc[VEC];
#pragma unroll
    for (int j = 0; j < VEC; j++) acc[j] = 0.f;

    int p = b0;
    for (; p + 3 < b1; p += 4) {
        int2 e[4];
        float v[4][VEC];
        float pd[4];
#pragma unroll
        for (int q = 0; q < 4; q++) e[q] = esd[p + q];
#pragma unroll
        for (int q = 0; q < 4; q++) {
#pragma unroll
            for (int j = 0; j < VEC; j++) v[q][j] = 0.f;
            if (valid) ldrow<VEC>(hc + (size_t)e[q].x * dim + c0, v[q]);
        }
#pragma unroll
        for (int q = 0; q < 4; q++) {
            float d = 0.f;
#pragma unroll
            for (int j = 0; j < VEC; j++) {
                float lr = (v[q][j] > 0.f) ? v[q][j] : 0.01f * v[q][j];
                d += hd[j] * lr;
            }
            pd[q] = d;
        }
#pragma unroll
        for (int o = 16; o; o >>= 1) {
#pragma unroll
            for (int q = 0; q < 4; q++)
                pd[q] += __shfl_xor_sync(~0u, pd[q], o);
        }
#pragma unroll
        for (int q = 0; q < 4; q++) {
            float d = pd[q];
            float t = d * __int_as_float(e[q].y);
            float gate = 1.f / (1.f + __expf(-t));
            float w = __expf(d * gate);
            denom += w;
#pragma unroll
            for (int j = 0; j < VEC; j++) acc[j] += w * v[q][j];
        }
    }
    for (; p < b1; p++) {
        int2 e = esd[p];
        float v[VEC];
#pragma unroll
        for (int j = 0; j < VEC; j++) v[j] = 0.f;
        if (valid) ldrow<VEC>(hc + (size_t)e.x * dim + c0, v);
        float d = 0.f;
#pragma unroll
        for (int j = 0; j < VEC; j++) {
            float lr = (v[j] > 0.f) ? v[j] : 0.01f * v[j];
            d += hd[j] * lr;
        }
#pragma unroll
        for (int o = 16; o; o >>= 1) d += __shfl_xor_sync(~0u, d, o);
        float t = d * __int_as_float(e.y);
        float gate = 1.f / (1.f + __expf(-t));
        float w = __expf(d * gate);
        denom += w;
#pragma unroll
        for (int j = 0; j < VEC; j++) acc[j] += w * v[j];
    }

    float inv = 1.f / (denom + 1e-16f);
    float val[VEC];
    float ss = 0.f;
#pragma unroll
    for (int j = 0; j < VEC; j++) {
        val[j] = 0.f;
        if (valid) {
            float v = acc[j] * inv + bias[c0 + j];
            val[j] = v;
            ss += v * v;
        }
    }
#pragma unroll
    for (int o = 16; o; o >>= 1) ss += __shfl_xor_sync(~0u, ss, o);
    float sc = 1.f / fmaxf(sqrtf(ss), 1e-12f);
    if (valid) {
        float res[VEC];
#pragma unroll
        for (int j = 0; j < VEC; j++) {
            float v = val[j] * sc;
            res[j] = (v > 0.f) ? v : 0.01f * v;
        }
        strow<VEC>(out + (size_t)n * dim + c0, res);
    }
}

__global__ void __launch_bounds__(128)
k_gat1(const float* __restrict__ hcv, const float* __restrict__ hct,
       const int2* __restrict__ esd, const int* __restrict__ off,
       const float* __restrict__ bv, const float* __restrict__ bt,
       float* __restrict__ ov, float* __restrict__ ot) {
    int w = (blockIdx.x * blockDim.x + threadIdx.x) >> 5;
    int lane = threadIdx.x & 31;
    if (w >= 2 * NN) return;
    if (w < NN) {
        gat_node<8>(hcv, LV, esd, off[w], off[w + 1], bv, ov, w, lane);
    } else {
        int n = w - NN;
        gat_node<4>(hct, LT, esd, off[n], off[n + 1], bt, ot, n, lane);
    }
}

__global__ void __launch_bounds__(128)
k_gat2(const float* __restrict__ hcv, const float* __restrict__ hct,
       const int2* __restrict__ esd, const int* __restrict__ off,
       const float* __restrict__ bv, const float* __restrict__ bt,
       float* __restrict__ ov, float* __restrict__ ot) {
    int w = (blockIdx.x * blockDim.x + threadIdx.x) >> 5;
    int lane = threadIdx.x & 31;
    if (w >= 2 * NN) return;
    if (w < NN) {
        gat_node<2>(hcv, DX, esd, off[w], off[w + 1], bv, ov, w, lane);
    } else {
        int n = w - NN;
        gat_node<2>(hct, DX, esd, off[n], off[n + 1], bt, ot, n, lane);
    }
}

// output: [representation | v_rep | t_rep]
__global__ void __launch_bounds__(256)
k_final(const float* __restrict__ vx1, const float* __restrict__ vx2,
        const float* __restrict__ tx1, const float* __restrict__ tx2,
        float* __restrict__ out, int out_size) {
    int i = blockIdx.x * blockDim.x + threadIdx.x;
    if (i >= NN * DX) return;
    int n = i >> 6, c = i & 63;
    float a1 = vx1[i], a2 = vx2[i], b1 = tx1[i], b2 = tx2[i];
    size_t base = (size_t)n * 128;
    out[base + c]      = (a1 + b1) * 0.5f;
    out[base + 64 + c] = (a2 + b2) * 0.5f;
    if (out_size >= 2 * NN * 128) {
        out[(size_t)NN * 128 + base + c]      = a1;
        out[(size_t)NN * 128 + base + 64 + c] = a2;
    }
    if (out_size >= 3 * NN * 128) {
        out[(size_t)2 * NN * 128 + base + c]      = b1;
        out[(size_t)2 * NN * 128 + base + 64 + c] = b2;
    }
}

// ---------------- host side ----------------
extern "C" void kernel_launch(void* const* d_in, const int* in_sizes, int n_in,
                              void* d_out, int out_size) {
    (void)in_sizes;
    (void)n_in;
    static float* F = nullptr;
    static int*   I = nullptr;
    static cudaStream_t sG = nullptr, sC = nullptr;
    static cudaEvent_t e0 = nullptr, eG = nullptr, eC = nullptr;
    if (!F) {
        cudaGetSymbolAddress((void**)&F, g_farena);
        cudaGetSymbolAddress((void**)&I, g_iarena);
        cudaStreamCreate(&sG);
        cudaStreamCreate(&sC);
        cudaEventCreateWithFlags(&e0, cudaEventDisableTiming);
        cudaEventCreateWithFlags(&eG, cudaEventDisableTiming);
        cudaEventCreateWithFlags(&eC, cudaEventDisableTiming);
    }

    float* x_v  = F;
    float* hc_v = F + 7680000;
    float* h_v  = F + 15360000;
    float* x_t  = F + 23040000;
    float* hc_t = F + 26040000;
    float* h_t  = F + 29040000;
    float* vx1  = F + 35880000;
    float* vx2  = F + 37800000;
    float* tx1  = F + 39720000;
    float* tx2  = F + 41640000;
    float* dinv = F + 43560000;

    int*  src  = I;
    int*  dst  = I + NE;
    int*  esrc = I + 2 * NE;
    int2* esd  = (int2*)(I + 3 * NE);
    int*  cnt  = I + 5 * NE;
    int*  degs = cnt + (NN + 1);
    int*  off  = degs + NN;
    int*  cur  = off + (NN + 1);
    int*  is64 = cur + NN;

    const float* feat  = (const float*)d_in[0];
    const void*  ei    = d_in[1];
    const float* idemb = (const float*)d_in[2];
    void* const* PV = d_in + 3;
    void* const* PT = d_in + 17;

#define PW(P, i) ((const float*)P[i])

    dim3 blk(256);
    int gy = (NN + 127) / 128;
    int warp2_grid = (2 * NN * 32 + 255) / 256;
    int gat_grid = (2 * NN * 32 + 127) / 128;

    // fork both worker streams off the (captured) legacy stream
    cudaEventRecord(e0, 0);
    cudaStreamWaitEvent(sG, e0, 0);
    cudaStreamWaitEvent(sC, e0, 0);

    // --- graph-build chain on sG ---
    k_init<<<(2 * NN + 256) / 256, 256, 0, sG>>>(ei, cnt, 2 * NN + 1, is64);
    k_convert_hist<<<(NE + 255) / 256, 256, 0, sG>>>(ei, src, dst, cnt, degs, is64);
    k_scan<<<1, 1024, 0, sG>>>(cnt, off, cur, degs, dinv);
    k_fill<<<(NE + 255) / 256, 256, 0, sG>>>(src, dst, cur, esrc);
    k_sortseg<<<(NN + 255) / 256, 256, 0, sG>>>(off, esrc, dinv, esd);
    cudaEventRecord(eG, sG);

    // --- compute chain on sC (overlaps with graph build) ---
    // S1: mlp GEMM (wide)
    {
        GP2 p = {{
            {feat, PW(PV, 0), x_v, FDIM, LV, LV, 128, LV},
            {feat + 128, PW(PT, 0), x_t, FDIM, LT, LT, 64, LT}}};
        k_gemmW<<<dim3(2, gy, 2), blk, 0, sC>>>(p);
    }
    k_tanh2<<<warp2_grid, 256, 0, sC>>>(x_v, PW(PV, 1), x_t, PW(PT, 1));
    // S3: c1 GEMM (wide)
    {
        GP2 p = {{
            {x_v, PW(PV, 2), hc_v, LV, LV, LV, LV, LV},
            {x_t, PW(PT, 2), hc_t, LT, LT, LT, LT, LT}}};
        k_gemmW<<<dim3(2, gy, 2), blk, 0, sC>>>(p);
    }

    // join: GAT needs both chains
    cudaStreamWaitEvent(sC, eG, 0);

    // S4: GAT layer 1
    k_gat1<<<gat_grid, 128, 0, sC>>>(hc_v, hc_t, esd, off, PW(PV, 3), PW(PT, 3), h_v, h_t);

    // S5: fused l1+g1 GEMMs + combine -> x1
    {
        GD2 p = {{
            {x_v, PW(PV, 4), h_v, PW(PV, 6), PW(PV, 5), PW(PV, 7), vx1, LV, LV},
            {x_t, PW(PT, 4), h_t, PW(PT, 6), PW(PT, 5), PW(PT, 7), tx1, LT, LT}}};
        k_gemmD<<<dim3(1, gy, 2), blk, 0, sC>>>(p, idemb);
    }
    // S6: c2 GEMM
    {
        GP2 p = {{
            {vx1, PW(PV, 8), hc_v, DX, DX, DX, DX, DX},
            {tx1, PW(PT, 8), hc_t, DX, DX, DX, DX, DX}}};
        k_gemm<<<dim3(1, gy, 2), blk, 0, sC>>>(p);
    }
    // S7: GAT layer 2
    k_gat2<<<gat_grid, 128, 0, sC>>>(hc_v, hc_t, esd, off, PW(PV, 9), PW(PT, 9), h_v, h_t);

    // S8: fused l2+g2 GEMMs + combine -> x2
    {
        GD2 p = {{
            {vx1, PW(PV, 10), h_v, PW(PV, 12), PW(PV, 11), PW(PV, 13), vx2, DX, DX},
            {tx1, PW(PT, 10), h_t, PW(PT, 12), PW(PT, 11), PW(PT, 13), tx2, DX, DX}}};
        k_gemmD<<<dim3(1, gy, 2), blk, 0, sC>>>(p, idemb);
    }

    k_final<<<(NN * DX + 255) / 256, 256, 0, sC>>>(vx1, vx2, tx1, tx2, (float*)d_out, out_size);
    cudaEventRecord(eC, sC);

    // join back to the legacy stream the harness owns
    cudaStreamWaitEvent(0, eC, 0);
#undef PW
}

// round 14
// speedup vs baseline: 1.6098x; 1.1251x over previous
#include <cuda_runtime.h>
#include <math.h>
#include <stdint.h>

#define NN 30000
#define NE 480000
#define FDIM 192
#define DX 64
#define LV 256
#define LT 100

// ---------------- scratch arenas ----------------
__device__ float g_farena[44000000];
__device__ int   g_iarena[2700000];

// ---------------- graph build ----------------
__global__ void k_init(const void* ei, int* a, int n, int* is64) {
    int i = blockIdx.x * blockDim.x + threadIdx.x;
    if (i < n) a[i] = 0;
    if (blockIdx.x == 0 && threadIdx.x == 0) {
        const int* p = (const int*)ei;
        int zeros = 0;
#pragma unroll 8
        for (int j = 1; j < 256; j += 2) if (p[j] == 0) zeros++;
        *is64 = (zeros >= 120) ? 1 : 0;
    }
}

__global__ void k_convert_hist(const void* ei, int* src, int* dst,
                               int* cnt, int* degs, const int* is64) {
    int e = blockIdx.x * blockDim.x + threadIdx.x;
    if (e >= NE) return;
    int s, d;
    if (*is64) {
        const long long* p = (const long long*)ei;
        s = (int)p[e];
        d = (int)p[NE + e];
    } else {
        const int* p = (const int*)ei;
        s = p[e];
        d = p[NE + e];
    }
    src[e] = s;
    dst[e] = d;
    atomicAdd(&cnt[d], 1);
    atomicAdd(&degs[s], 1);
}

__global__ void __launch_bounds__(1024)
k_scan(const int* __restrict__ cnt, int* __restrict__ off, int* __restrict__ cur,
       const int* __restrict__ degs, float* __restrict__ dinv) {
    const int CH = 30;
    int t = threadIdx.x;
    int base = t * CH;
    int s = 0;
#pragma unroll 5
    for (int i = 0; i < CH; i++) {
        int idx = base + i;
        if (idx < NN) s += cnt[idx];
    }
    int lane = t & 31, wid = t >> 5;
    int v = s;
#pragma unroll
    for (int o = 1; o < 32; o <<= 1) {
        int u = __shfl_up_sync(~0u, v, o);
        if (lane >= o) v += u;
    }
    __shared__ int wt[32];
    if (lane == 31) wt[wid] = v;
    __syncthreads();
    if (wid == 0) {
        int w = wt[lane];
#pragma unroll
        for (int o = 1; o < 32; o <<= 1) {
            int u = __shfl_up_sync(~0u, w, o);
            if (lane >= o) w += u;
        }
        wt[lane] = w;
    }
    __syncthreads();
    int pre = v - s + (wid ? wt[wid - 1] : 0);
    int run = pre;
#pragma unroll 5
    for (int i = 0; i < CH; i++) {
        int idx = base + i;
        if (idx < NN) {
            off[idx] = run;
            cur[idx] = run;
            int dg = degs[idx];
            dinv[idx] = (dg > 0) ? rsqrtf((float)dg) : 0.f;
            run += cnt[idx];
        }
    }
    if (t == 1023) off[NN] = run;
}

__global__ void k_fill(const int* src, const int* dst, int* cur, int* esrc) {
    int e = blockIdx.x * blockDim.x + threadIdx.x;
    if (e >= NE) return;
    int p = atomicAdd(&cur[dst[e]], 1);
    esrc[p] = src[e];
}

// warp-parallel deterministic segment sort: rank by (value, lane/pos) and emit
// (src, dinv[src]) records. Same ascending-value order as insertion sort.
__global__ void __launch_bounds__(128)
k_sortwarp(const int* __restrict__ off, const int* __restrict__ esrc,
           const float* __restrict__ dinv, int2* __restrict__ esd) {
    int w = (blockIdx.x * blockDim.x + threadIdx.x) >> 5;
    int lane = threadIdx.x & 31;
    if (w >= NN) return;
    int b0 = off[w], b1 = off[w + 1];
    int deg = b1 - b0;
    if (deg <= 0) return;
    if (deg <= 32) {
        int val = (lane < deg) ? esrc[b0 + lane] : 0x7fffffff;
        int rank = 0;
        for (int j = 0; j < deg; j++) {
            int o = __shfl_sync(~0u, val, j);
            rank += (o < val) || (o == val && j < lane);
        }
        if (lane < deg)
            esd[b0 + rank] = make_int2(val, __float_as_int(dinv[val]));
    } else {
        for (int i = lane; i < deg; i += 32) {
            int val = esrc[b0 + i];
            int rank = 0;
            for (int j = 0; j < deg; j++) {
                int o = esrc[b0 + j];
                rank += (o < val) || (o == val && j < i);
            }
            esd[b0 + rank] = make_int2(val, __float_as_int(dinv[val]));
        }
    }
}

// ---------------- TF32 tensor-core GEMM ----------------
struct GP {
    const float* A;
    const float* B;
    float* C;
    int lda, ldb, ldc, K, M;
};
struct GP2 { GP g[2]; };

struct GD {
    const float* x;
    const float* l;
    const float* h;
    const float* g;
    const float* lb;
    const float* gb;
    float* C;
    int ldx, K;
};
struct GD2 { GD d[2]; };

__device__ __forceinline__ float f2tf(float x) {
    uint32_t u;
    asm("cvt.rna.tf32.f32 %0, %1;" : "=r"(u) : "f"(x));
    return __uint_as_float(u);
}

__device__ __forceinline__ void mma_tf32(float* c,
                                         uint32_t a0, uint32_t a1, uint32_t a2, uint32_t a3,
                                         uint32_t b0, uint32_t b1) {
    asm volatile(
        "mma.sync.aligned.m16n8k8.row.col.f32.tf32.tf32.f32 "
        "{%0,%1,%2,%3}, {%4,%5,%6,%7}, {%8,%9}, {%0,%1,%2,%3};\n"
        : "+f"(c[0]), "+f"(c[1]), "+f"(c[2]), "+f"(c[3])
        : "r"(a0), "r"(a1), "r"(a2), "r"(a3), "r"(b0), "r"(b1));
}

#define SAS 136
#define SBS 72
#define SWS 136

// ===== wide GEMM: BM=128, BN=128, 256 thr = 4m x 2n warps, warp 32x64 =====
__global__ void __launch_bounds__(256)
k_gemmW(GP2 p) {
    GP g = p.g[blockIdx.z];
    const int bcol = blockIdx.x * 128;
    if (bcol >= g.M) return;
    __shared__ float sA[2][16][SAS];
    __shared__ float sB[2][16][SWS];
    const int tid = threadIdx.x;
    const int brow = blockIdx.y * 128;
    const int K = g.K, M = g.M;

    const int lane = tid & 31;
    const int wid  = tid >> 5;
    const int wm = (wid & 3) * 32;
    const int wn = (wid >> 2) * 64;
    const int grp = lane >> 2, thr = lane & 3;

    const int ar0 = tid >> 2, akq = (tid & 3) * 4;
    const int ar1 = ar0 + 64;
    const int br0 = tid >> 5, bc4 = (tid & 31) * 4;
    const int br1 = br0 + 8;

    float4 pA0, pA1, pB0, pB1;

#define LD_A(dst, row, k0)                                                     \
    do {                                                                       \
        dst = make_float4(0.f, 0.f, 0.f, 0.f);                                 \
        if (brow + (row) < NN) {                                               \
            const float* ap = g.A + (size_t)(brow + (row)) * g.lda + (k0) + akq;\
            if ((k0) + akq + 3 < K) dst = *(const float4*)ap;                  \
            else {                                                             \
                if ((k0) + akq + 0 < K) dst.x = ap[0];                         \
                if ((k0) + akq + 1 < K) dst.y = ap[1];                         \
                if ((k0) + akq + 2 < K) dst.z = ap[2];                         \
                if ((k0) + akq + 3 < K) dst.w = ap[3];                         \
            }                                                                  \
        }                                                                      \
    } while (0)

#define LD_B(dst, row, k0)                                                     \
    do {                                                                       \
        dst = make_float4(0.f, 0.f, 0.f, 0.f);                                 \
        if ((k0) + (row) < K) {                                                \
            const float* bp = g.B + (size_t)((k0) + (row)) * g.ldb + bcol + bc4;\
            if (bcol + bc4 + 3 < M) dst = *(const float4*)bp;                  \
            else {                                                             \
                if (bcol + bc4 + 0 < M) dst.x = bp[0];                         \
                if (bcol + bc4 + 1 < M) dst.y = bp[1];                         \
                if (bcol + bc4 + 2 < M) dst.z = bp[2];                         \
                if (bcol + bc4 + 3 < M) dst.w = bp[3];                         \
            }                                                                  \
        }                                                                      \
    } while (0)

#define LOAD_TILE(k0) do { LD_A(pA0, ar0, k0); LD_A(pA1, ar1, k0);             \
                           LD_B(pB0, br0, k0); LD_B(pB1, br1, k0); } while (0)

#define STORE_TILE(buf)                                                        \
    do {                                                                       \
        sA[buf][akq + 0][ar0] = f2tf(pA0.x);                                   \
        sA[buf][akq + 1][ar0] = f2tf(pA0.y);                                   \
        sA[buf][akq + 2][ar0] = f2tf(pA0.z);                                   \
        sA[buf][akq + 3][ar0] = f2tf(pA0.w);                                   \
        sA[buf][akq + 0][ar1] = f2tf(pA1.x);                                   \
        sA[buf][akq + 1][ar1] = f2tf(pA1.y);                                   \
        sA[buf][akq + 2][ar1] = f2tf(pA1.z);                                   \
        sA[buf][akq + 3][ar1] = f2tf(pA1.w);                                   \
        sB[buf][br0][bc4 + 0] = f2tf(pB0.x);                                   \
        sB[buf][br0][bc4 + 1] = f2tf(pB0.y);                                   \
        sB[buf][br0][bc4 + 2] = f2tf(pB0.z);                                   \
        sB[buf][br0][bc4 + 3] = f2tf(pB0.w);                                   \
        sB[buf][br1][bc4 + 0] = f2tf(pB1.x);                                   \
        sB[buf][br1][bc4 + 1] = f2tf(pB1.y);                                   \
        sB[buf][br1][bc4 + 2] = f2tf(pB1.z);                                   \
        sB[buf][br1][bc4 + 3] = f2tf(pB1.w);                                   \
    } while (0)

    float acc[2][8][4] = {};
    LOAD_TILE(0);
    STORE_TILE(0);
    __syncthreads();
    int buf = 0;

    for (int k0 = 0; k0 < K; k0 += 16) {
        int nk = k0 + 16;
        if (nk < K) LOAD_TILE(nk);
#pragma unroll
        for (int ks = 0; ks < 2; ks++) {
            int kb = ks * 8;
            uint32_t af[2][4], bf[8][2];
#pragma unroll
            for (int mt = 0; mt < 2; mt++) {
                int r = wm + mt * 16 + grp;
                af[mt][0] = __float_as_uint(sA[buf][kb + thr][r]);
                af[mt][1] = __float_as_uint(sA[buf][kb + thr][r + 8]);
                af[mt][2] = __float_as_uint(sA[buf][kb + 4 + thr][r]);
                af[mt][3] = __float_as_uint(sA[buf][kb + 4 + thr][r + 8]);
            }
#pragma unroll
            for (int nt = 0; nt < 8; nt++) {
                int c = wn + nt * 8 + grp;
                bf[nt][0] = __float_as_uint(sB[buf][kb + thr][c]);
                bf[nt][1] = __float_as_uint(sB[buf][kb + 4 + thr][c]);
            }
#pragma unroll
            for (int mt = 0; mt < 2; mt++)
#pragma unroll
                for (int nt = 0; nt < 8; nt++)
                    mma_tf32(acc[mt][nt], af[mt][0], af[mt][1], af[mt][2], af[mt][3],
                             bf[nt][0], bf[nt][1]);
        }
        if (nk < K) {
            STORE_TILE(buf ^ 1);
            __syncthreads();
            buf ^= 1;
        }
    }
#undef LOAD_TILE
#undef STORE_TILE
#undef LD_A
#undef LD_B

#pragma unroll
    for (int mt = 0; mt < 2; mt++) {
#pragma unroll
        for (int nt = 0; nt < 8; nt++) {
#pragma unroll
            for (int e = 0; e < 4; e++) {
                int r = brow + wm + mt * 16 + grp + (e >= 2 ? 8 : 0);
                int c = bcol + wn + nt * 8 + 2 * thr + (e & 1);
                if (r < NN && c < M)
                    g.C[(size_t)r * g.ldc + c] = acc[mt][nt][e];
            }
        }
    }
}

// ===== shared phase for narrow/dual kernels =====
__device__ __forceinline__ void gemm_phase64(
    const float* __restrict__ A, int lda, const float* __restrict__ B, int ldb,
    int K, int brow, int bcol, int Mlim, int tid, float (&acc)[2][4][4],
    float (*sA)[16][SAS], float (*sB)[16][SBS]) {

    const int lane = tid & 31;
    const int wid  = tid >> 5;
    const int wm = (wid & 3) * 32;
    const int wn = (wid >> 2) * 32;
    const int grp = lane >> 2, thr = lane & 3;

    const int ar0 = tid >> 2, akq = (tid & 3) * 4;
    const int ar1 = ar0 + 64;
    const int bkr = tid >> 4, bcq = (tid & 15) * 4;

    float4 pA0, pA1, pB;

#define LOAD_TILE64(k0)                                                        \
    do {                                                                       \
        pA0 = make_float4(0.f, 0.f, 0.f, 0.f);                                 \
        pA1 = make_float4(0.f, 0.f, 0.f, 0.f);                                 \
        pB  = make_float4(0.f, 0.f, 0.f, 0.f);                                 \
        if (brow + ar0 < NN) {                                                 \
            const float* ap = A + (size_t)(brow + ar0) * lda + (k0) + akq;     \
            if ((k0) + akq + 3 < K) pA0 = *(const float4*)ap;                  \
            else {                                                             \
                if ((k0) + akq + 0 < K) pA0.x = ap[0];                         \
                if ((k0) + akq + 1 < K) pA0.y = ap[1];                         \
                if ((k0) + akq + 2 < K) pA0.z = ap[2];                         \
                if ((k0) + akq + 3 < K) pA0.w = ap[3];                         \
            }                                                                  \
        }                                                                      \
        if (brow + ar1 < NN) {                                                 \
            const float* ap = A + (size_t)(brow + ar1) * lda + (k0) + akq;     \
            if ((k0) + akq + 3 < K) pA1 = *(const float4*)ap;                  \
            else {                                                             \
                if ((k0) + akq + 0 < K) pA1.x = ap[0];                         \
                if ((k0) + akq + 1 < K) pA1.y = ap[1];                         \
                if ((k0) + akq + 2 < K) pA1.z = ap[2];                         \
                if ((k0) + akq + 3 < K) pA1.w = ap[3];                         \
            }                                                                  \
        }                                                                      \
        if ((k0) + bkr < K) {                                                  \
            const float* bp = B + (size_t)((k0) + bkr) * ldb + bcol + bcq;     \
            if (bcol + bcq + 3 < Mlim) pB = *(const float4*)bp;                \
            else {                                                             \
                if (bcol + bcq + 0 < Mlim) pB.x = bp[0];                       \
                if (bcol + bcq + 1 < Mlim) pB.y = bp[1];                       \
                if (bcol + bcq + 2 < Mlim) pB.z = bp[2];                       \
                if (bcol + bcq + 3 < Mlim) pB.w = bp[3];                       \
            }                                                                  \
        }                                                                      \
    } while (0)

#define STORE_TILE64(buf)                                                      \
    do {                                                                       \
        sA[buf][akq + 0][ar0] = f2tf(pA0.x);                                   \
        sA[buf][akq + 1][ar0] = f2tf(pA0.y);                                   \
        sA[buf][akq + 2][ar0] = f2tf(pA0.z);                                   \
        sA[buf][akq + 3][ar0] = f2tf(pA0.w);                                   \
        sA[buf][akq + 0][ar1] = f2tf(pA1.x);                                   \
        sA[buf][akq + 1][ar1] = f2tf(pA1.y);                                   \
        sA[buf][akq + 2][ar1] = f2tf(pA1.z);                                   \
        sA[buf][akq + 3][ar1] = f2tf(pA1.w);                                   \
        sB[buf][bkr][bcq + 0] = f2tf(pB.x);                                    \
        sB[buf][bkr][bcq + 1] = f2tf(pB.y);                                    \
        sB[buf][bkr][bcq + 2] = f2tf(pB.z);                                    \
        sB[buf][bkr][bcq + 3] = f2tf(pB.w);                                    \
    } while (0)

    LOAD_TILE64(0);
    STORE_TILE64(0);
    __syncthreads();
    int buf = 0;

    for (int k0 = 0; k0 < K; k0 += 16) {
        int nk = k0 + 16;
        if (nk < K) LOAD_TILE64(nk);
#pragma unroll
        for (int ks = 0; ks < 2; ks++) {
            int kb = ks * 8;
            uint32_t af[2][4], bf[4][2];
#pragma unroll
            for (int mt = 0; mt < 2; mt++) {
                int r = wm + mt * 16 + grp;
                af[mt][0] = __float_as_uint(sA[buf][kb + thr][r]);
                af[mt][1] = __float_as_uint(sA[buf][kb + thr][r + 8]);
                af[mt][2] = __float_as_uint(sA[buf][kb + 4 + thr][r]);
                af[mt][3] = __float_as_uint(sA[buf][kb + 4 + thr][r + 8]);
            }
#pragma unroll
            for (int nt = 0; nt < 4; nt++) {
                int c = wn + nt * 8 + grp;
                bf[nt][0] = __float_as_uint(sB[buf][kb + thr][c]);
                bf[nt][1] = __float_as_uint(sB[buf][kb + 4 + thr][c]);
            }
#pragma unroll
            for (int mt = 0; mt < 2; mt++)
#pragma unroll
                for (int nt = 0; nt < 4; nt++)
                    mma_tf32(acc[mt][nt], af[mt][0], af[mt][1], af[mt][2], af[mt][3],
                             bf[nt][0], bf[nt][1]);
        }
        if (nk < K) {
            STORE_TILE64(buf ^ 1);
            __syncthreads();
            buf ^= 1;
        }
    }
    __syncthreads();
#undef LOAD_TILE64
#undef STORE_TILE64
}

// ===== narrow GEMM (plain): C = A @ B =====
__global__ void __launch_bounds__(256)
k_gemm(GP2 p) {
    GP g = p.g[blockIdx.z];
    const int bcol = blockIdx.x * 64;
    if (bcol >= g.M) return;
    __shared__ float sA[2][16][SAS];
    __shared__ float sB[2][16][SBS];
    const int tid = threadIdx.x;
    const int brow = blockIdx.y * 128;

    float acc[2][4][4] = {};
    gemm_phase64(g.A, g.lda, g.B, g.ldb, g.K, brow, bcol, g.M, tid, acc, sA, sB);

    const int lane = tid & 31;
    const int wid  = tid >> 5;
    const int wm = (wid & 3) * 32;
    const int wn = (wid >> 2) * 32;
    const int grp = lane >> 2, thr = lane & 3;

#pragma unroll
    for (int mt = 0; mt < 2; mt++)
#pragma unroll
        for (int nt = 0; nt < 4; nt++)
#pragma unroll
            for (int e = 0; e < 4; e++) {
                int r = brow + wm + mt * 16 + grp + (e >= 2 ? 8 : 0);
                int c = bcol + wn + nt * 8 + 2 * thr + (e & 1);
                if (r < NN && c < g.M)
                    g.C[(size_t)r * g.ldc + c] = acc[mt][nt][e];
            }
}

// ===== dual GEMM + combine =====
__global__ void __launch_bounds__(256)
k_gemmD(GD2 p, const float* __restrict__ id) {
    GD d = p.d[blockIdx.z];
    __shared__ float sA[2][16][SAS];
    __shared__ float sB[2][16][SBS];
    const int tid = threadIdx.x;
    const int brow = blockIdx.y * 128;

    float acc1[2][4][4] = {};
    float acc2[2][4][4] = {};
    gemm_phase64(d.x, d.ldx, d.l, DX, d.K, brow, 0, DX, tid, acc1, sA, sB);
    gemm_phase64(d.h, d.ldx, d.g, DX, d.K, brow, 0, DX, tid, acc2, sA, sB);

    const int lane = tid & 31;
    const int wid  = tid >> 5;
    const int wm = (wid & 3) * 32;
    const int wn = (wid >> 2) * 32;
    const int grp = lane >> 2, thr = lane & 3;

#pragma unroll
    for (int mt = 0; mt < 2; mt++)
#pragma unroll
        for (int nt = 0; nt < 4; nt++)
#pragma unroll
            for (int e = 0; e < 4; e++) {
                int r = brow + wm + mt * 16 + grp + (e >= 2 ? 8 : 0);
                int c = wn + nt * 8 + 2 * thr + (e & 1);
                if (r >= NN) continue;
                size_t lin = (size_t)r * 64 + c;
                float xh = acc1[mt][nt][e] + d.lb[c];
                xh = (xh > 0.f) ? xh : 0.01f * xh;
                xh += id[lin];
                float o = acc2[mt][nt][e] + d.gb[c] + xh;
                d.C[lin] = (o > 0.f) ? o : 0.01f * o;
            }
}

// ---------------- tanh + l2norm ----------------
__global__ void __launch_bounds__(256)
k_tanh2(float* __restrict__ xv, const float* __restrict__ bv,
        float* __restrict__ xt, const float* __restrict__ bt) {
    int w = (blockIdx.x * blockDim.x + threadIdx.x) >> 5;
    int lane = threadIdx.x & 31;
    if (w >= 2 * NN) return;
    float* row;
    const float* b;
    int dim;
    if (w < NN) { row = xv + (size_t)w * LV; b = bv; dim = LV; }
    else        { row = xt + (size_t)(w - NN) * LT; b = bt; dim = LT; }
    float v[8];
    float ss = 0.f;
#pragma unroll
    for (int j = 0; j < 8; j++) {
        v[j] = 0.f;
        int c = lane + 32 * j;
        if (c < dim) {
            float t = tanhf(row[c] + b[c]);
            v[j] = t;
            ss += t * t;
        }
    }
#pragma unroll
    for (int o = 16; o; o >>= 1) ss += __shfl_xor_sync(~0u, ss, o);
    float sc = 1.f / fmaxf(sqrtf(ss), 1e-12f);
#pragma unroll
    for (int j = 0; j < 8; j++) {
        int c = lane + 32 * j;
        if (c < dim) row[c] = v[j] * sc;
    }
}

// ---------------- vector helpers ----------------
template <int VEC>
__device__ __forceinline__ void ldrow(const float* __restrict__ p, float* v) {
    if (VEC == 8) {
        float4 a = *(const float4*)p;
        float4 b = *(const float4*)(p + 4);
        v[0] = a.x; v[1] = a.y; v[2] = a.z; v[3] = a.w;
        v[4] = b.x; v[5] = b.y; v[6] = b.z; v[7] = b.w;
    } else if (VEC == 4) {
        float4 a = *(const float4*)p;
        v[0] = a.x; v[1] = a.y; v[2] = a.z; v[3] = a.w;
    } else {
        float2 a = *(const float2*)p;
        v[0] = a.x; v[1] = a.y;
    }
}

template <int VEC>
__device__ __forceinline__ void strow(float* __restrict__ p, const float* v) {
    if (VEC == 8) {
        *(float4*)p       = make_float4(v[0], v[1], v[2], v[3]);
        *(float4*)(p + 4) = make_float4(v[4], v[5], v[6], v[7]);
    } else if (VEC == 4) {
        *(float4*)p = make_float4(v[0], v[1], v[2], v[3]);
    } else {
        *(float2*)p = make_float2(v[0], v[1]);
    }
}

// ---------------- GAT: single pass, no max subtraction ----------------
template <int VEC>
__device__ __forceinline__ void gat_node(const float* __restrict__ hc, int dim,
                                         const int2* __restrict__ esd, int b0, int b1,
                                         const float* __restrict__ bias,
                                         float* __restrict__ out, int n, int lane) {
    int c0 = lane * VEC;
    bool valid = c0 < dim;
    float hd[VEC];
#pragma unroll
    for (int j = 0; j < VEC; j++) hd[j] = 0.f;
    if (valid) ldrow<VEC>(hc + (size_t)n * dim + c0, hd);

    float denom = 0.f;
    float acc[VEC];
#pragma unroll
    for (int j = 0; j < VEC; j++) acc[j] = 0.f;

    int p = b0;
    for (; p + 3 < b1; p += 4) {
        int2 e[4];
        float v[4][VEC];
        float pd[4];
#pragma unroll
        for (int q = 0; q < 4; q++) e[q] = esd[p + q];
#pragma unroll
        for (int q = 0; q < 4; q++) {
#pragma unroll
            for (int j = 0; j < VEC; j++) v[q][j] = 0.f;
            if (valid) ldrow<VEC>(hc + (size_t)e[q].x * dim + c0, v[q]);
        }
#pragma unroll
        for (int q = 0; q < 4; q++) {
            float d = 0.f;
#pragma unroll
            for (int j = 0; j < VEC; j++) {
                float lr = (v[q][j] > 0.f) ? v[q][j] : 0.01f * v[q][j];
                d += hd[j] * lr;
            }
            pd[q] = d;
        }
#pragma unroll
        for (int o = 16; o; o >>= 1) {
#pragma unroll
            for (int q = 0; q < 4; q++)
                pd[q] += __shfl_xor_sync(~0u, pd[q], o);
        }
#pragma unroll
        for (int q = 0; q < 4; q++) {
            float d = pd[q];
            float t = d * __int_as_float(e[q].y);
            float gate = 1.f / (1.f + __expf(-t));
            float w = __expf(d * gate);
            denom += w;
#pragma unroll
            for (int j = 0; j < VEC; j++) acc[j] += w * v[q][j];
        }
    }
    for (; p < b1; p++) {
        int2 e = esd[p];
        float v[VEC];
#pragma unroll
        for (int j = 0; j < VEC; j++) v[j] = 0.f;
        if (valid) ldrow<VEC>(hc + (size_t)e.x * dim + c0, v);
        float d = 0.f;
#pragma unroll
        for (int j = 0; j < VEC; j++) {
            float lr = (v[j] > 0.f) ? v[j] : 0.01f * v[j];
            d += hd[j] * lr;
        }
#pragma unroll
        for (int o = 16; o; o >>= 1) d += __shfl_xor_sync(~0u, d, o);
        float t = d * __int_as_float(e.y);
        float gate = 1.f / (1.f + __expf(-t));
        float w = __expf(d * gate);
        denom += w;
#pragma unroll
        for (int j = 0; j < VEC; j++) acc[j] += w * v[j];
    }

    float inv = 1.f / (denom + 1e-16f);
    float val[VEC];
    float ss = 0.f;
#pragma unroll
    for (int j = 0; j < VEC; j++) {
        val[j] = 0.f;
        if (valid) {
            float v = acc[j] * inv + bias[c0 + j];
            val[j] = v;
            ss += v * v;
        }
    }
#pragma unroll
    for (int o = 16; o; o >>= 1) ss += __shfl_xor_sync(~0u, ss, o);
    float sc = 1.f / fmaxf(sqrtf(ss), 1e-12f);
    if (valid) {
        float res[VEC];
#pragma unroll
        for (int j = 0; j < VEC; j++) {
            float v = val[j] * sc;
            res[j] = (v > 0.f) ? v : 0.01f * v;
        }
        strow<VEC>(out + (size_t)n * dim + c0, res);
    }
}

__global__ void __launch_bounds__(128)
k_gat1(const float* __restrict__ hcv, const float* __restrict__ hct,
       const int2* __restrict__ esd, const int* __restrict__ off,
       const float* __restrict__ bv, const float* __restrict__ bt,
       float* __restrict__ ov, float* __restrict__ ot) {
    int w = (blockIdx.x * blockDim.x + threadIdx.x) >> 5;
    int lane = threadIdx.x & 31;
    if (w >= 2 * NN) return;
    if (w < NN) {
        gat_node<8>(hcv, LV, esd, off[w], off[w + 1], bv, ov, w, lane);
    } else {
        int n = w - NN;
        gat_node<4>(hct, LT, esd, off[n], off[n + 1], bt, ot, n, lane);
    }
}

__global__ void __launch_bounds__(128)
k_gat2(const float* __restrict__ hcv, const float* __restrict__ hct,
       const int2* __restrict__ esd, const int* __restrict__ off,
       const float* __restrict__ bv, const float* __restrict__ bt,
       float* __restrict__ ov, float* __restrict__ ot) {
    int w = (blockIdx.x * blockDim.x + threadIdx.x) >> 5;
    int lane = threadIdx.x & 31;
    if (w >= 2 * NN) return;
    if (w < NN) {
        gat_node<2>(hcv, DX, esd, off[w], off[w + 1], bv, ov, w, lane);
    } else {
        int n = w - NN;
        gat_node<2>(hct, DX, esd, off[n], off[n + 1], bt, ot, n, lane);
    }
}

// output: [representation | v_rep | t_rep]
__global__ void __launch_bounds__(256)
k_final(const float* __restrict__ vx1, const float* __restrict__ vx2,
        const float* __restrict__ tx1, const float* __restrict__ tx2,
        float* __restrict__ out, int out_size) {
    int i = blockIdx.x * blockDim.x + threadIdx.x;
    if (i >= NN * DX) return;
    int n = i >> 6, c = i & 63;
    float a1 = vx1[i], a2 = vx2[i], b1 = tx1[i], b2 = tx2[i];
    size_t base = (size_t)n * 128;
    out[base + c]      = (a1 + b1) * 0.5f;
    out[base + 64 + c] = (a2 + b2) * 0.5f;
    if (out_size >= 2 * NN * 128) {
        out[(size_t)NN * 128 + base + c]      = a1;
        out[(size_t)NN * 128 + base + 64 + c] = a2;
    }
    if (out_size >= 3 * NN * 128) {
        out[(size_t)2 * NN * 128 + base + c]      = b1;
        out[(size_t)2 * NN * 128 + base + 64 + c] = b2;
    }
}

// ---------------- host side ----------------
extern "C" void kernel_launch(void* const* d_in, const int* in_sizes, int n_in,
                              void* d_out, int out_size) {
    (void)in_sizes;
    (void)n_in;
    static float* F = nullptr;
    static int*   I = nullptr;
    static cudaStream_t sG = nullptr, sC = nullptr;
    static cudaEvent_t e0 = nullptr, eG = nullptr, eC = nullptr;
    if (!F) {
        cudaGetSymbolAddress((void**)&F, g_farena);
        cudaGetSymbolAddress((void**)&I, g_iarena);
        cudaStreamCreate(&sG);
        cudaStreamCreate(&sC);
        cudaEventCreateWithFlags(&e0, cudaEventDisableTiming);
        cudaEventCreateWithFlags(&eG, cudaEventDisableTiming);
        cudaEventCreateWithFlags(&eC, cudaEventDisableTiming);
    }

    float* x_v  = F;
    float* hc_v = F + 7680000;
    float* h_v  = F + 15360000;
    float* x_t  = F + 23040000;
    float* hc_t = F + 26040000;
    float* h_t  = F + 29040000;
    float* vx1  = F + 35880000;
    float* vx2  = F + 37800000;
    float* tx1  = F + 39720000;
    float* tx2  = F + 41640000;
    float* dinv = F + 43560000;

    int*  src  = I;
    int*  dst  = I + NE;
    int*  esrc = I + 2 * NE;
    int2* esd  = (int2*)(I + 3 * NE);
    int*  cnt  = I + 5 * NE;
    int*  degs = cnt + (NN + 1);
    int*  off  = degs + NN;
    int*  cur  = off + (NN + 1);
    int*  is64 = cur + NN;

    const float* feat  = (const float*)d_in[0];
    const void*  ei    = d_in[1];
    const float* idemb = (const float*)d_in[2];
    void* const* PV = d_in + 3;
    void* const* PT = d_in + 17;

#define PW(P, i) ((const float*)P[i])

    dim3 blk(256);
    int gy = (NN + 127) / 128;
    int warp2_grid = (2 * NN * 32 + 255) / 256;
    int gat_grid = (2 * NN * 32 + 127) / 128;
    int sort_grid = (NN * 32 + 127) / 128;

    // fork both worker streams off the (captured) legacy stream
    cudaEventRecord(e0, 0);
    cudaStreamWaitEvent(sG, e0, 0);
    cudaStreamWaitEvent(sC, e0, 0);

    // --- graph-build chain on sG ---
    k_init<<<(2 * NN + 256) / 256, 256, 0, sG>>>(ei, cnt, 2 * NN + 1, is64);
    k_convert_hist<<<(NE + 255) / 256, 256, 0, sG>>>(ei, src, dst, cnt, degs, is64);
    k_scan<<<1, 1024, 0, sG>>>(cnt, off, cur, degs, dinv);
    k_fill<<<(NE + 255) / 256, 256, 0, sG>>>(src, dst, cur, esrc);
    k_sortwarp<<<sort_grid, 128, 0, sG>>>(off, esrc, dinv, esd);
    cudaEventRecord(eG, sG);

    // --- compute chain on sC (overlaps with graph build) ---
    {
        GP2 p = {{
            {feat, PW(PV, 0), x_v, FDIM, LV, LV, 128, LV},
            {feat + 128, PW(PT, 0), x_t, FDIM, LT, LT, 64, LT}}};
        k_gemmW<<<dim3(2, gy, 2), blk, 0, sC>>>(p);
    }
    k_tanh2<<<warp2_grid, 256, 0, sC>>>(x_v, PW(PV, 1), x_t, PW(PT, 1));
    {
        GP2 p = {{
            {x_v, PW(PV, 2), hc_v, LV, LV, LV, LV, LV},
            {x_t, PW(PT, 2), hc_t, LT, LT, LT, LT, LT}}};
        k_gemmW<<<dim3(2, gy, 2), blk, 0, sC>>>(p);
    }

    // join: GAT needs both chains
    cudaStreamWaitEvent(sC, eG, 0);

    // S4: GAT layer 1
    k_gat1<<<gat_grid, 128, 0, sC>>>(hc_v, hc_t, esd, off, PW(PV, 3), PW(PT, 3), h_v, h_t);

    // S5: fused l1+g1 GEMMs + combine -> x1
    {
        GD2 p = {{
            {x_v, PW(PV, 4), h_v, PW(PV, 6), PW(PV, 5), PW(PV, 7), vx1, LV, LV},
            {x_t, PW(PT, 4), h_t, PW(PT, 6), PW(PT, 5), PW(PT, 7), tx1, LT, LT}}};
        k_gemmD<<<dim3(1, gy, 2), blk, 0, sC>>>(p, idemb);
    }
    // S6: c2 GEMM
    {
        GP2 p = {{
            {vx1, PW(PV, 8), hc_v, DX, DX, DX, DX, DX},
            {tx1, PW(PT, 8), hc_t, DX, DX, DX, DX, DX}}};
        k_gemm<<<dim3(1, gy, 2), blk, 0, sC>>>(p);
    }
    // S7: GAT layer 2
    k_gat2<<<gat_grid, 128, 0, sC>>>(hc_v, hc_t, esd, off, PW(PV, 9), PW(PT, 9), h_v, h_t);

    // S8: fused l2+g2 GEMMs + combine -> x2
    {
        GD2 p = {{
            {vx1, PW(PV, 10), h_v, PW(PV, 12), PW(PV, 11), PW(PV, 13), vx2, DX, DX},
            {tx1, PW(PT, 10), h_t, PW(PT, 12), PW(PT, 11), PW(PT, 13), tx2, DX, DX}}};
        k_gemmD<<<dim3(1, gy, 2), blk, 0, sC>>>(p, idemb);
    }

    k_final<<<(NN * DX + 255) / 256, 256, 0, sC>>>(vx1, vx2, tx1, tx2, (float*)d_out, out_size);
    cudaEventRecord(eC, sC);

    // join back to the legacy stream the harness owns
    cudaStreamWaitEvent(0, eC, 0);
#undef PW
}